// round 1
// baseline (speedup 1.0000x reference)
#include <cuda_runtime.h>
#include <math.h>

#define TOKENS 16384
#define DMODEL 768
#define NHEAD  12
#define HDIM   64
#define DMLP   3072
#define SEQ    1024
#define BATCH  16

// ---------------- scratch (device globals; no cudaMalloc allowed) ----------------
__device__ float g_ln [12582912];   // [TOKENS][DMODEL] (reused for LN1 and LN2 out)
__device__ float g_q  [12582912];
__device__ float g_k  [12582912];
__device__ float g_v  [12582912];
__device__ float g_x1 [12582912];   // x + attn_out (residual 1)
__device__ float g_act[50331648];   // [TOKENS][DMLP]

// ---------------- LayerNorm: one block per token, 256 threads ----------------
__global__ void ln_kernel(const float* __restrict__ x, const float* __restrict__ g,
                          const float* __restrict__ b, float* __restrict__ out)
{
    int tok = blockIdx.x;
    int t = threadIdx.x;
    const float* xr = x + (size_t)tok * DMODEL;
    float v0 = xr[t], v1 = xr[t + 256], v2 = xr[t + 512];
    float s = v0 + v1 + v2;
    __shared__ float red[8];
#pragma unroll
    for (int o = 16; o > 0; o >>= 1) s += __shfl_xor_sync(0xffffffffu, s, o);
    if ((t & 31) == 0) red[t >> 5] = s;
    __syncthreads();
    float tot = 0.f;
#pragma unroll
    for (int i = 0; i < 8; i++) tot += red[i];
    float mu = tot * (1.0f / DMODEL);
    float d0 = v0 - mu, d1 = v1 - mu, d2 = v2 - mu;
    float sq = d0 * d0 + d1 * d1 + d2 * d2;
#pragma unroll
    for (int o = 16; o > 0; o >>= 1) sq += __shfl_xor_sync(0xffffffffu, sq, o);
    __syncthreads();
    if ((t & 31) == 0) red[t >> 5] = sq;
    __syncthreads();
    float vs = 0.f;
#pragma unroll
    for (int i = 0; i < 8; i++) vs += red[i];
    float rs = rsqrtf(vs * (1.0f / DMODEL) + 1e-5f);
    float* orow = out + (size_t)tok * DMODEL;
    orow[t]       = d0 * rs * g[t]       + b[t];
    orow[t + 256] = d1 * rs * g[t + 256] + b[t + 256];
    orow[t + 512] = d2 * rs * g[t + 512] + b[t + 512];
}

// ---------------- Block-diagonal per-head QKV projection ----------------
// grid: (TOKENS/64, NHEAD), block 256. Each block: 64 tokens x one head,
// computes q,k,v (3x 64x64 GEMM) reusing the X tile in smem.
__global__ void __launch_bounds__(256) qkv_kernel(
    const float* __restrict__ ln,
    const float* __restrict__ Wq, const float* __restrict__ bq,
    const float* __restrict__ Wk, const float* __restrict__ bk,
    const float* __restrict__ Wv, const float* __restrict__ bv,
    float* __restrict__ q, float* __restrict__ k, float* __restrict__ v)
{
    __shared__ float Xs[64 * 65];   // [d][token], padded
    __shared__ float Ws[64 * 65];   // [d][o], padded
    int h  = blockIdx.y;
    int t0 = blockIdx.x * 64;
    int t  = threadIdx.x;
    int tx = t & 15, ty = t >> 4;

    // load X tile (64 tokens x 64 dims of this head's slice), store transposed
#pragma unroll
    for (int it = 0; it < 4; it++) {
        int idx = it * 1024 + t * 4;
        int r = idx >> 6, c = idx & 63;
        float4 x4 = *(const float4*)(ln + (size_t)(t0 + r) * DMODEL + h * HDIM + c);
        Xs[(c + 0) * 65 + r] = x4.x;
        Xs[(c + 1) * 65 + r] = x4.y;
        Xs[(c + 2) * 65 + r] = x4.z;
        Xs[(c + 3) * 65 + r] = x4.w;
    }

    const float* Wm[3] = { Wq + h * 4096, Wk + h * 4096, Wv + h * 4096 };
    const float* bm[3] = { bq + h * 64,  bk + h * 64,  bv + h * 64 };
    float*       om[3] = { q, k, v };

    for (int m = 0; m < 3; m++) {
        __syncthreads();   // protect Ws (prev iter readers) / ensure Xs visible (iter 0)
#pragma unroll
        for (int it = 0; it < 4; it++) {
            int idx = it * 1024 + t * 4;
            int r = idx >> 6, c = idx & 63;          // r = o, c = d
            float4 w4 = *(const float4*)(Wm[m] + r * 64 + c);
            Ws[(c + 0) * 65 + r] = w4.x;
            Ws[(c + 1) * 65 + r] = w4.y;
            Ws[(c + 2) * 65 + r] = w4.z;
            Ws[(c + 3) * 65 + r] = w4.w;
        }
        __syncthreads();

        float acc[4][4] = {};
#pragma unroll
        for (int d = 0; d < 64; d++) {
            float xa[4], wb[4];
#pragma unroll
            for (int i = 0; i < 4; i++) xa[i] = Xs[d * 65 + ty * 4 + i];
#pragma unroll
            for (int j = 0; j < 4; j++) wb[j] = Ws[d * 65 + tx + 16 * j];
#pragma unroll
            for (int i = 0; i < 4; i++)
#pragma unroll
                for (int j = 0; j < 4; j++) acc[i][j] += xa[i] * wb[j];
        }
        float* outp = om[m];
#pragma unroll
        for (int i = 0; i < 4; i++) {
            int tok = t0 + ty * 4 + i;
#pragma unroll
            for (int j = 0; j < 4; j++) {
                int o = tx + 16 * j;
                outp[(size_t)tok * DMODEL + h * HDIM + o] = acc[i][j] + bm[m][o];
            }
        }
    }
}

// ---------------- Fused attention (two-pass, scores in smem) + residual ----------------
// grid: (SEQ/16, NHEAD, BATCH), block 256, dynamic smem ~86KB.
// Each warp owns 2 query rows end-to-end (scores, softmax, AV) -> no inter-warp
// hazards on the score buffer; only K/V tile reloads need syncs.
__global__ void __launch_bounds__(256) attn_kernel(
    const float* __restrict__ q, const float* __restrict__ k,
    const float* __restrict__ v, const float* __restrict__ x,
    float* __restrict__ out)
{
    extern __shared__ float sm[];
    float* attn = sm;                  // [16][1024]
    float* Ks   = sm + 16 * 1024;      // [64][65]  (reused for V tiles)
    float* Qs   = Ks + 64 * 65;        // [16][64]

    int b  = blockIdx.z, h = blockIdx.y;
    int q0 = blockIdx.x * 16;
    int t  = threadIdx.x;
    size_t base = ((size_t)b * SEQ) * DMODEL + h * HDIM;

    {   // load Q tile
        int r = t >> 4, c = (t & 15) << 2;
        float4 q4 = *(const float4*)(q + base + (size_t)(q0 + r) * DMODEL + c);
        *(float4*)&Qs[r * 64 + c] = q4;
    }
    int w = t >> 5, lane = t & 31;
    int qi = w * 2;
    const float scale = 0.125f;   // 1/sqrt(64)

    // ---- pass A: scores ----
    for (int kt = 0; kt < 16; kt++) {
        __syncthreads();
#pragma unroll
        for (int it = 0; it < 4; it++) {
            int idx = it * 1024 + t * 4;
            int r = idx >> 6, c = idx & 63;
            float4 k4 = *(const float4*)(k + base + (size_t)(kt * 64 + r) * DMODEL + c);
            Ks[r * 65 + c + 0] = k4.x; Ks[r * 65 + c + 1] = k4.y;
            Ks[r * 65 + c + 2] = k4.z; Ks[r * 65 + c + 3] = k4.w;
        }
        __syncthreads();
        float s00 = 0, s01 = 0, s10 = 0, s11 = 0;
#pragma unroll
        for (int d = 0; d < 64; d++) {
            float q0v = Qs[qi * 64 + d];
            float q1v = Qs[(qi + 1) * 64 + d];
            float k0v = Ks[lane * 65 + d];          // conflict-free: bank = lane+d
            float k1v = Ks[(lane + 32) * 65 + d];
            s00 += q0v * k0v; s01 += q0v * k1v;
            s10 += q1v * k0v; s11 += q1v * k1v;
        }
        int kc = kt * 64;
        attn[qi * 1024 + kc + lane]            = s00 * scale;
        attn[qi * 1024 + kc + lane + 32]       = s01 * scale;
        attn[(qi + 1) * 1024 + kc + lane]      = s10 * scale;
        attn[(qi + 1) * 1024 + kc + lane + 32] = s11 * scale;
    }

    // ---- softmax (warp-private rows, no block sync needed) ----
#pragma unroll
    for (int rr = 0; rr < 2; rr++) {
        float* row = attn + (size_t)(qi + rr) * 1024;
        float mx = -1e30f;
        for (int i = lane; i < 1024; i += 32) mx = fmaxf(mx, row[i]);
#pragma unroll
        for (int o = 16; o > 0; o >>= 1) mx = fmaxf(mx, __shfl_xor_sync(0xffffffffu, mx, o));
        float sum = 0.f;
        for (int i = lane; i < 1024; i += 32) { float e = __expf(row[i] - mx); row[i] = e; sum += e; }
#pragma unroll
        for (int o = 16; o > 0; o >>= 1) sum += __shfl_xor_sync(0xffffffffu, sum, o);
        float inv = 1.0f / sum;
        for (int i = lane; i < 1024; i += 32) row[i] *= inv;
    }

    // ---- pass B: O = attn @ V, fused residual add ----
    float o00 = 0, o01 = 0, o10 = 0, o11 = 0;
    for (int kt = 0; kt < 16; kt++) {
        __syncthreads();
#pragma unroll
        for (int it = 0; it < 4; it++) {
            int idx = it * 1024 + t * 4;
            int r = idx >> 6, c = idx & 63;
            float4 v4 = *(const float4*)(v + base + (size_t)(kt * 64 + r) * DMODEL + c);
            Ks[r * 65 + c + 0] = v4.x; Ks[r * 65 + c + 1] = v4.y;
            Ks[r * 65 + c + 2] = v4.z; Ks[r * 65 + c + 3] = v4.w;
        }
        __syncthreads();
#pragma unroll
        for (int kk = 0; kk < 64; kk++) {
            float a0 = attn[qi * 1024 + kt * 64 + kk];        // broadcast
            float a1 = attn[(qi + 1) * 1024 + kt * 64 + kk];
            float v0 = Ks[kk * 65 + lane];                    // conflict-free
            float v1 = Ks[kk * 65 + lane + 32];
            o00 += a0 * v0; o01 += a0 * v1;
            o10 += a1 * v0; o11 += a1 * v1;
        }
    }
    size_t r0 = base + (size_t)(q0 + qi) * DMODEL;
    size_t r1 = base + (size_t)(q0 + qi + 1) * DMODEL;
    out[r0 + lane]      = o00 + x[r0 + lane];
    out[r0 + lane + 32] = o01 + x[r0 + lane + 32];
    out[r1 + lane]      = o10 + x[r1 + lane];
    out[r1 + lane + 32] = o11 + x[r1 + lane + 32];
}

// ---------------- Tiled SGEMM: C[M,N] = A[M,K] @ B[N,K]^T + bias (+GELU / +residual) ----
// BM=BN=128, BK=8, 256 threads, 8x8 per thread.
#define MODE_GELU  1
#define MODE_RESID 2

__global__ void __launch_bounds__(256) sgemm_kernel(
    const float* __restrict__ A, const float* __restrict__ B,
    const float* __restrict__ bias, const float* __restrict__ resid,
    float* __restrict__ C, int M, int N, int K, int mode)
{
    __shared__ float As[8][128];
    __shared__ float Bs[8][128];
    int t  = threadIdx.x;
    int m0 = blockIdx.y * 128;
    int n0 = blockIdx.x * 128;
    int tx = t & 15, ty = t >> 4;

    float acc[8][8] = {};

    int lrow = t >> 1;            // 0..127
    int lk   = (t & 1) * 4;       // 0 or 4
    const float* Aptr = A + (size_t)(m0 + lrow) * K + lk;
    const float* Bptr = B + (size_t)(n0 + lrow) * K + lk;

    for (int k0 = 0; k0 < K; k0 += 8) {
        float4 a4 = *(const float4*)(Aptr + k0);
        float4 b4 = *(const float4*)(Bptr + k0);
        As[lk + 0][lrow] = a4.x; As[lk + 1][lrow] = a4.y;
        As[lk + 2][lrow] = a4.z; As[lk + 3][lrow] = a4.w;
        Bs[lk + 0][lrow] = b4.x; Bs[lk + 1][lrow] = b4.y;
        Bs[lk + 2][lrow] = b4.z; Bs[lk + 3][lrow] = b4.w;
        __syncthreads();
#pragma unroll
        for (int kk = 0; kk < 8; kk++) {
            float ra[8], rb[8];
            *(float4*)&ra[0] = *(const float4*)&As[kk][ty * 8];
            *(float4*)&ra[4] = *(const float4*)&As[kk][ty * 8 + 4];
            *(float4*)&rb[0] = *(const float4*)&Bs[kk][tx * 8];
            *(float4*)&rb[4] = *(const float4*)&Bs[kk][tx * 8 + 4];
#pragma unroll
            for (int i = 0; i < 8; i++)
#pragma unroll
                for (int j = 0; j < 8; j++) acc[i][j] += ra[i] * rb[j];
        }
        __syncthreads();
    }

    int mrow = m0 + ty * 8;
    int ncol = n0 + tx * 8;
#pragma unroll
    for (int i = 0; i < 8; i++) {
        size_t off = (size_t)(mrow + i) * N + ncol;
#pragma unroll
        for (int j = 0; j < 8; j += 4) {
            float4 r;
            r.x = acc[i][j + 0] + bias[ncol + j + 0];
            r.y = acc[i][j + 1] + bias[ncol + j + 1];
            r.z = acc[i][j + 2] + bias[ncol + j + 2];
            r.w = acc[i][j + 3] + bias[ncol + j + 3];
            if (mode == MODE_GELU) {
                r.x = 0.5f * r.x * (1.0f + erff(r.x * 0.70710678118654752f));
                r.y = 0.5f * r.y * (1.0f + erff(r.y * 0.70710678118654752f));
                r.z = 0.5f * r.z * (1.0f + erff(r.z * 0.70710678118654752f));
                r.w = 0.5f * r.w * (1.0f + erff(r.w * 0.70710678118654752f));
            } else if (mode == MODE_RESID) {
                const float* rp = resid + off + j;
                r.x += rp[0]; r.y += rp[1]; r.z += rp[2]; r.w += rp[3];
            }
            *(float4*)(C + off + j) = r;
        }
    }
}

// ---------------- launch ----------------
extern "C" void kernel_launch(void* const* d_in, const int* in_sizes, int n_in,
                              void* d_out, int out_size)
{
    const float* x    = (const float*)d_in[0];
    const float* ln1g = (const float*)d_in[1];
    const float* ln1b = (const float*)d_in[2];
    const float* Wq   = (const float*)d_in[3];
    const float* bq   = (const float*)d_in[4];
    const float* Wk   = (const float*)d_in[5];
    const float* bk   = (const float*)d_in[6];
    const float* Wv   = (const float*)d_in[7];
    const float* bv   = (const float*)d_in[8];
    const float* ln2g = (const float*)d_in[9];
    const float* ln2b = (const float*)d_in[10];
    const float* W1   = (const float*)d_in[11];
    const float* b1   = (const float*)d_in[12];
    const float* W2   = (const float*)d_in[13];
    const float* b2   = (const float*)d_in[14];
    float* out = (float*)d_out;

    float *ln, *qb, *kb, *vb, *x1, *act;
    cudaGetSymbolAddress((void**)&ln,  g_ln);
    cudaGetSymbolAddress((void**)&qb,  g_q);
    cudaGetSymbolAddress((void**)&kb,  g_k);
    cudaGetSymbolAddress((void**)&vb,  g_v);
    cudaGetSymbolAddress((void**)&x1,  g_x1);
    cudaGetSymbolAddress((void**)&act, g_act);

    const int ATTN_SMEM = (16 * 1024 + 64 * 65 + 16 * 64) * (int)sizeof(float); // 86272 B
    cudaFuncSetAttribute((const void*)attn_kernel,
                         cudaFuncAttributeMaxDynamicSharedMemorySize, ATTN_SMEM);

    // 1) LN1
    ln_kernel<<<TOKENS, 256>>>(x, ln1g, ln1b, ln);
    // 2) per-head QKV projections
    qkv_kernel<<<dim3(TOKENS / 64, NHEAD), 256>>>(ln, Wq, bq, Wk, bk, Wv, bv, qb, kb, vb);
    // 3) attention + residual (writes x1 = x + mha)
    attn_kernel<<<dim3(SEQ / 16, NHEAD, BATCH), 256, ATTN_SMEM>>>(qb, kb, vb, x, x1);
    // 4) LN2
    ln_kernel<<<TOKENS, 256>>>(x1, ln2g, ln2b, ln);
    // 5) MLP up + exact GELU
    sgemm_kernel<<<dim3(DMLP / 128, TOKENS / 128), 256>>>(
        ln, W1, b1, nullptr, act, TOKENS, DMLP, DMODEL, MODE_GELU);
    // 6) MLP down + bias + residual -> d_out
    sgemm_kernel<<<dim3(DMODEL / 128, TOKENS / 128), 256>>>(
        act, W2, b2, x1, out, TOKENS, DMODEL, DMLP, MODE_RESID);
}

// round 3
// speedup vs baseline: 1.5059x; 1.5059x over previous
#include <cuda_runtime.h>
#include <cuda_bf16.h>
#include <math.h>
#include <stdint.h>

#define TOKENS 16384
#define DMODEL 768
#define NHEAD  12
#define HDIM   64
#define DMLP   3072
#define SEQ    1024
#define BATCH  16

// ---------------- scratch (device globals; no cudaMalloc allowed) ----------------
__device__ float    g_ln  [TOKENS * DMODEL];      // LN1 out fp32 (for qkv)
__device__ uint32_t g_lnp [TOKENS * DMODEL];      // LN2 out packed bf16(hi,lo)
__device__ float    g_q   [TOKENS * DMODEL];
__device__ float    g_k   [TOKENS * DMODEL];
__device__ float    g_v   [TOKENS * DMODEL];
__device__ float    g_x1  [TOKENS * DMODEL];      // x + attn
__device__ uint32_t g_actp[TOKENS * DMLP];        // GELU out packed bf16(hi,lo)
__device__ uint32_t g_w1s [DMLP * DMODEL];        // W1 packed (hi,lo)
__device__ uint32_t g_w1w [DMLP * DMODEL];        // W1 packed (lo,hi)
__device__ uint32_t g_w2s [DMODEL * DMLP];
__device__ uint32_t g_w2w [DMODEL * DMLP];

// ---------------- PTX helpers (portable: sm_80-class instructions only) ----------------
__device__ __forceinline__ void cp16(uint32_t s, const void* g) {
    asm volatile("cp.async.cg.shared.global [%0], [%1], 16;" :: "r"(s), "l"(g));
}
__device__ __forceinline__ void cp_commit() { asm volatile("cp.async.commit_group;" ::: "memory"); }
__device__ __forceinline__ void cp_wait1()  { asm volatile("cp.async.wait_group 1;" ::: "memory"); }
__device__ __forceinline__ void cp_wait0()  { asm volatile("cp.async.wait_group 0;" ::: "memory"); }

__device__ __forceinline__ void ldsm4(uint32_t* r, uint32_t addr) {
    asm volatile("ldmatrix.sync.aligned.m8n8.x4.shared.b16 {%0,%1,%2,%3}, [%4];"
                 : "=r"(r[0]), "=r"(r[1]), "=r"(r[2]), "=r"(r[3]) : "r"(addr));
}
__device__ __forceinline__ void mma_bf16(float* d, const uint32_t* a, const uint32_t* b) {
    asm volatile(
        "mma.sync.aligned.m16n8k16.row.col.f32.bf16.bf16.f32 "
        "{%0,%1,%2,%3}, {%4,%5,%6,%7}, {%8,%9}, {%0,%1,%2,%3};"
        : "+f"(d[0]), "+f"(d[1]), "+f"(d[2]), "+f"(d[3])
        : "r"(a[0]), "r"(a[1]), "r"(a[2]), "r"(a[3]), "r"(b[0]), "r"(b[1]));
}

// bf16 split pack: low half = hi, high half = lo
__device__ __forceinline__ uint32_t pack_split(float x) {
    __nv_bfloat16 h = __float2bfloat16(x);
    float hf = __bfloat162float(h);
    __nv_bfloat16 l = __float2bfloat16(x - hf);
    uint32_t hu = (uint32_t)__bfloat16_as_ushort(h);
    uint32_t lu = (uint32_t)__bfloat16_as_ushort(l);
    return hu | (lu << 16);
}

// ---------------- LayerNorm (fp32 out) ----------------
__global__ void ln_kernel(const float* __restrict__ x, const float* __restrict__ g,
                          const float* __restrict__ b, float* __restrict__ out)
{
    int tok = blockIdx.x;
    int t = threadIdx.x;
    const float* xr = x + (size_t)tok * DMODEL;
    float v0 = xr[t], v1 = xr[t + 256], v2 = xr[t + 512];
    float s = v0 + v1 + v2;
    __shared__ float red[8];
#pragma unroll
    for (int o = 16; o > 0; o >>= 1) s += __shfl_xor_sync(0xffffffffu, s, o);
    if ((t & 31) == 0) red[t >> 5] = s;
    __syncthreads();
    float tot = 0.f;
#pragma unroll
    for (int i = 0; i < 8; i++) tot += red[i];
    float mu = tot * (1.0f / DMODEL);
    float d0 = v0 - mu, d1 = v1 - mu, d2 = v2 - mu;
    float sq = d0 * d0 + d1 * d1 + d2 * d2;
#pragma unroll
    for (int o = 16; o > 0; o >>= 1) sq += __shfl_xor_sync(0xffffffffu, sq, o);
    __syncthreads();
    if ((t & 31) == 0) red[t >> 5] = sq;
    __syncthreads();
    float vs = 0.f;
#pragma unroll
    for (int i = 0; i < 8; i++) vs += red[i];
    float rs = rsqrtf(vs * (1.0f / DMODEL) + 1e-5f);
    float* orow = out + (size_t)tok * DMODEL;
    orow[t]       = d0 * rs * g[t]       + b[t];
    orow[t + 256] = d1 * rs * g[t + 256] + b[t + 256];
    orow[t + 512] = d2 * rs * g[t + 512] + b[t + 512];
}

// ---------------- LayerNorm (packed bf16 split out) ----------------
__global__ void ln_packed_kernel(const float* __restrict__ x, const float* __restrict__ g,
                                 const float* __restrict__ b, uint32_t* __restrict__ out)
{
    int tok = blockIdx.x;
    int t = threadIdx.x;
    const float* xr = x + (size_t)tok * DMODEL;
    float v0 = xr[t], v1 = xr[t + 256], v2 = xr[t + 512];
    float s = v0 + v1 + v2;
    __shared__ float red[8];
#pragma unroll
    for (int o = 16; o > 0; o >>= 1) s += __shfl_xor_sync(0xffffffffu, s, o);
    if ((t & 31) == 0) red[t >> 5] = s;
    __syncthreads();
    float tot = 0.f;
#pragma unroll
    for (int i = 0; i < 8; i++) tot += red[i];
    float mu = tot * (1.0f / DMODEL);
    float d0 = v0 - mu, d1 = v1 - mu, d2 = v2 - mu;
    float sq = d0 * d0 + d1 * d1 + d2 * d2;
#pragma unroll
    for (int o = 16; o > 0; o >>= 1) sq += __shfl_xor_sync(0xffffffffu, sq, o);
    __syncthreads();
    if ((t & 31) == 0) red[t >> 5] = sq;
    __syncthreads();
    float vs = 0.f;
#pragma unroll
    for (int i = 0; i < 8; i++) vs += red[i];
    float rs = rsqrtf(vs * (1.0f / DMODEL) + 1e-5f);
    uint32_t* orow = out + (size_t)tok * DMODEL;
    orow[t]       = pack_split(d0 * rs * g[t]       + b[t]);
    orow[t + 256] = pack_split(d1 * rs * g[t + 256] + b[t + 256]);
    orow[t + 512] = pack_split(d2 * rs * g[t + 512] + b[t + 512]);
}

// ---------------- weight conversion: fp32 -> packed (hi,lo) and (lo,hi) ----------------
__global__ void convert_w_kernel(const float* __restrict__ W,
                                 uint32_t* __restrict__ same, uint32_t* __restrict__ swp, int n)
{
    int i = blockIdx.x * 256 + threadIdx.x;
    if (i < n) {
        float x = W[i];
        __nv_bfloat16 h = __float2bfloat16(x);
        float hf = __bfloat162float(h);
        __nv_bfloat16 l = __float2bfloat16(x - hf);
        uint32_t hu = (uint32_t)__bfloat16_as_ushort(h);
        uint32_t lu = (uint32_t)__bfloat16_as_ushort(l);
        same[i] = hu | (lu << 16);
        swp[i]  = lu | (hu << 16);
    }
}

// ---------------- Block-diagonal per-head QKV projection ----------------
__global__ void __launch_bounds__(256) qkv_kernel(
    const float* __restrict__ ln,
    const float* __restrict__ Wq, const float* __restrict__ bq,
    const float* __restrict__ Wk, const float* __restrict__ bk,
    const float* __restrict__ Wv, const float* __restrict__ bv,
    float* __restrict__ q, float* __restrict__ k, float* __restrict__ v)
{
    __shared__ float Xs[64 * 65];
    __shared__ float Ws[64 * 65];
    int h  = blockIdx.y;
    int t0 = blockIdx.x * 64;
    int t  = threadIdx.x;
    int tx = t & 15, ty = t >> 4;

#pragma unroll
    for (int it = 0; it < 4; it++) {
        int idx = it * 1024 + t * 4;
        int r = idx >> 6, c = idx & 63;
        float4 x4 = *(const float4*)(ln + (size_t)(t0 + r) * DMODEL + h * HDIM + c);
        Xs[(c + 0) * 65 + r] = x4.x;
        Xs[(c + 1) * 65 + r] = x4.y;
        Xs[(c + 2) * 65 + r] = x4.z;
        Xs[(c + 3) * 65 + r] = x4.w;
    }

    const float* Wm[3] = { Wq + h * 4096, Wk + h * 4096, Wv + h * 4096 };
    const float* bm[3] = { bq + h * 64,  bk + h * 64,  bv + h * 64 };
    float*       om[3] = { q, k, v };

    for (int m = 0; m < 3; m++) {
        __syncthreads();
#pragma unroll
        for (int it = 0; it < 4; it++) {
            int idx = it * 1024 + t * 4;
            int r = idx >> 6, c = idx & 63;
            float4 w4 = *(const float4*)(Wm[m] + r * 64 + c);
            Ws[(c + 0) * 65 + r] = w4.x;
            Ws[(c + 1) * 65 + r] = w4.y;
            Ws[(c + 2) * 65 + r] = w4.z;
            Ws[(c + 3) * 65 + r] = w4.w;
        }
        __syncthreads();

        float acc[4][4] = {};
#pragma unroll
        for (int d = 0; d < 64; d++) {
            float xa[4], wb[4];
#pragma unroll
            for (int i = 0; i < 4; i++) xa[i] = Xs[d * 65 + ty * 4 + i];
#pragma unroll
            for (int j = 0; j < 4; j++) wb[j] = Ws[d * 65 + tx + 16 * j];
#pragma unroll
            for (int i = 0; i < 4; i++)
#pragma unroll
                for (int j = 0; j < 4; j++) acc[i][j] += xa[i] * wb[j];
        }
        float* outp = om[m];
#pragma unroll
        for (int i = 0; i < 4; i++) {
            int tok = t0 + ty * 4 + i;
#pragma unroll
            for (int j = 0; j < 4; j++) {
                int o = tx + 16 * j;
                outp[(size_t)tok * DMODEL + h * HDIM + o] = acc[i][j] + bm[m][o];
            }
        }
    }
}

// ---------------- Fused attention (two-pass, scores in smem) + residual ----------------
__global__ void __launch_bounds__(256) attn_kernel(
    const float* __restrict__ q, const float* __restrict__ k,
    const float* __restrict__ v, const float* __restrict__ x,
    float* __restrict__ out)
{
    extern __shared__ float sm[];
    float* attn = sm;
    float* Ks   = sm + 16 * 1024;
    float* Qs   = Ks + 64 * 65;

    int b  = blockIdx.z, h = blockIdx.y;
    int q0 = blockIdx.x * 16;
    int t  = threadIdx.x;
    size_t base = ((size_t)b * SEQ) * DMODEL + h * HDIM;

    {
        int r = t >> 4, c = (t & 15) << 2;
        float4 q4 = *(const float4*)(q + base + (size_t)(q0 + r) * DMODEL + c);
        *(float4*)&Qs[r * 64 + c] = q4;
    }
    int w = t >> 5, lane = t & 31;
    int qi = w * 2;
    const float scale = 0.125f;

    for (int kt = 0; kt < 16; kt++) {
        __syncthreads();
#pragma unroll
        for (int it = 0; it < 4; it++) {
            int idx = it * 1024 + t * 4;
            int r = idx >> 6, c = idx & 63;
            float4 k4 = *(const float4*)(k + base + (size_t)(kt * 64 + r) * DMODEL + c);
            Ks[r * 65 + c + 0] = k4.x; Ks[r * 65 + c + 1] = k4.y;
            Ks[r * 65 + c + 2] = k4.z; Ks[r * 65 + c + 3] = k4.w;
        }
        __syncthreads();
        float s00 = 0, s01 = 0, s10 = 0, s11 = 0;
#pragma unroll
        for (int d = 0; d < 64; d++) {
            float q0v = Qs[qi * 64 + d];
            float q1v = Qs[(qi + 1) * 64 + d];
            float k0v = Ks[lane * 65 + d];
            float k1v = Ks[(lane + 32) * 65 + d];
            s00 += q0v * k0v; s01 += q0v * k1v;
            s10 += q1v * k0v; s11 += q1v * k1v;
        }
        int kc = kt * 64;
        attn[qi * 1024 + kc + lane]            = s00 * scale;
        attn[qi * 1024 + kc + lane + 32]       = s01 * scale;
        attn[(qi + 1) * 1024 + kc + lane]      = s10 * scale;
        attn[(qi + 1) * 1024 + kc + lane + 32] = s11 * scale;
    }

#pragma unroll
    for (int rr = 0; rr < 2; rr++) {
        float* row = attn + (size_t)(qi + rr) * 1024;
        float mx = -1e30f;
        for (int i = lane; i < 1024; i += 32) mx = fmaxf(mx, row[i]);
#pragma unroll
        for (int o = 16; o > 0; o >>= 1) mx = fmaxf(mx, __shfl_xor_sync(0xffffffffu, mx, o));
        float sum = 0.f;
        for (int i = lane; i < 1024; i += 32) { float e = __expf(row[i] - mx); row[i] = e; sum += e; }
#pragma unroll
        for (int o = 16; o > 0; o >>= 1) sum += __shfl_xor_sync(0xffffffffu, sum, o);
        float inv = 1.0f / sum;
        for (int i = lane; i < 1024; i += 32) row[i] *= inv;
    }

    float o00 = 0, o01 = 0, o10 = 0, o11 = 0;
    for (int kt = 0; kt < 16; kt++) {
        __syncthreads();
#pragma unroll
        for (int it = 0; it < 4; it++) {
            int idx = it * 1024 + t * 4;
            int r = idx >> 6, c = idx & 63;
            float4 v4 = *(const float4*)(v + base + (size_t)(kt * 64 + r) * DMODEL + c);
            Ks[r * 65 + c + 0] = v4.x; Ks[r * 65 + c + 1] = v4.y;
            Ks[r * 65 + c + 2] = v4.z; Ks[r * 65 + c + 3] = v4.w;
        }
        __syncthreads();
#pragma unroll
        for (int kk = 0; kk < 64; kk++) {
            float a0 = attn[qi * 1024 + kt * 64 + kk];
            float a1 = attn[(qi + 1) * 1024 + kt * 64 + kk];
            float v0 = Ks[kk * 65 + lane];
            float v1 = Ks[kk * 65 + lane + 32];
            o00 += a0 * v0; o01 += a0 * v1;
            o10 += a1 * v0; o11 += a1 * v1;
        }
    }
    size_t r0 = base + (size_t)(q0 + qi) * DMODEL;
    size_t r1 = base + (size_t)(q0 + qi + 1) * DMODEL;
    out[r0 + lane]      = o00 + x[r0 + lane];
    out[r0 + lane + 32] = o01 + x[r0 + lane + 32];
    out[r1 + lane]      = o10 + x[r1 + lane];
    out[r1 + lane + 32] = o11 + x[r1 + lane + 32];
}

// ---------------- HMMA split-bf16 GEMM ----------------
// C[M,N] = A[M,K] @ B[N,K]^T (+bias), MODE 1: GELU + pack u32 out; MODE 2: +resid fp32 out.
// A packed (hi,lo) per element -> 2K bf16 halves along K.
// Pass over halves with Bs=(hi,lo) gives Ah*Bh+Al*Bl; with Bw=(lo,hi) gives Ah*Bl+Al*Bh.
// Both accumulate into one fp32 accumulator => exact (Ah+Al)(Bh+Bl).
// CTA tile 128x128, BK = 64 halves (32 fp32 elems), 8 warps (64x32 each).
// Smem rows: 128B, 8x16B chunks, XOR swizzle chunk^= (row&7) => conflict-free ldmatrix.
#define TILE_B  16384
#define STAGE_B 49152

__device__ __forceinline__ uint32_t sw(uint32_t b, int row, int ch) {
    return b + (uint32_t)(row * 128) + (uint32_t)((ch ^ (row & 7)) << 4);
}

__device__ __forceinline__ void load_tile3(uint32_t sb,
    const uint32_t* __restrict__ Ap, const uint32_t* __restrict__ Bs,
    const uint32_t* __restrict__ Bw, int m0, int n0, int Ku32, int ic, int t)
{
#pragma unroll
    for (int i = 0; i < 4; i++) {
        int idx = t + 256 * i;
        int row = idx >> 3, ch = idx & 7;
        cp16(sw(sb, row, ch),              Ap + (size_t)(m0 + row) * Ku32 + ic * 32 + ch * 4);
        cp16(sw(sb + TILE_B, row, ch),     Bs + (size_t)(n0 + row) * Ku32 + ic * 32 + ch * 4);
        cp16(sw(sb + 2 * TILE_B, row, ch), Bw + (size_t)(n0 + row) * Ku32 + ic * 32 + ch * 4);
    }
}

template<int MODE>
__global__ void __launch_bounds__(256, 1)
gemm_hmma_kernel(const uint32_t* __restrict__ Ap,
                 const uint32_t* __restrict__ Bs, const uint32_t* __restrict__ Bw,
                 const float* __restrict__ bias, const float* __restrict__ resid,
                 void* __restrict__ outp, int N, int Ku32)
{
    extern __shared__ char dsm[];
    uint32_t smem_u32 = (uint32_t)__cvta_generic_to_shared(dsm);
    uint32_t base = (smem_u32 + 127) & ~127u;

    const int t = threadIdx.x;
    const int lane = t & 31, wid = t >> 5;
    const int m0 = blockIdx.y * 128, n0 = blockIdx.x * 128;
    const int warp_m = (wid >> 2) * 64, warp_n = (wid & 3) * 32;

    float acc[4][4][4] = {};
    const int NC = Ku32 >> 5;   // 32 u32 (=64 halves) per iter

    load_tile3(base, Ap, Bs, Bw, m0, n0, Ku32, 0, t);
    cp_commit();

    for (int ic = 0; ic < NC; ic++) {
        uint32_t cb = base + (uint32_t)(ic & 1) * STAGE_B;
        if (ic + 1 < NC) {
            load_tile3(base + (uint32_t)((ic + 1) & 1) * STAGE_B,
                       Ap, Bs, Bw, m0, n0, Ku32, ic + 1, t);
            cp_commit();
            cp_wait1();
        } else {
            cp_wait0();
        }
        __syncthreads();

        uint32_t Ab = cb, B0 = cb + TILE_B, B1 = cb + 2 * TILE_B;
#pragma unroll
        for (int kp = 0; kp < 2; kp++) {
            uint32_t af[4][2][4];
#pragma unroll
            for (int mt = 0; mt < 4; mt++)
#pragma unroll
                for (int ks = 0; ks < 2; ks++) {
                    int row = warp_m + mt * 16 + (lane & 15);
                    int ch  = (kp * 2 + ks) * 2 + (lane >> 4);
                    ldsm4(af[mt][ks], sw(Ab, row, ch));
                }
            uint32_t bf[4][2][4];
#pragma unroll
            for (int nt = 0; nt < 4; nt++) {
                int row = warp_n + nt * 8 + (lane & 7);
                int ch  = kp * 4 + ((lane >> 3) & 3);
                ldsm4(bf[nt][0], sw(B0, row, ch));
                ldsm4(bf[nt][1], sw(B1, row, ch));
            }
#pragma unroll
            for (int ks = 0; ks < 2; ks++)
#pragma unroll
                for (int mt = 0; mt < 4; mt++)
#pragma unroll
                    for (int nt = 0; nt < 4; nt++) {
                        mma_bf16(acc[mt][nt], af[mt][ks], &bf[nt][0][ks * 2]);
                        mma_bf16(acc[mt][nt], af[mt][ks], &bf[nt][1][ks * 2]);
                    }
        }
        __syncthreads();
    }

    // epilogue: thread owns (row = t/4 [+8], cols 2*(t%4)+{0,1}) per 16x8 frag
    int rbase = m0 + warp_m + (lane >> 2);
    int cbase = n0 + warp_n + (lane & 3) * 2;
#pragma unroll
    for (int mt = 0; mt < 4; mt++)
#pragma unroll
        for (int nt = 0; nt < 4; nt++)
#pragma unroll
            for (int hh = 0; hh < 2; hh++) {
                int row = rbase + mt * 16 + hh * 8;
                int col = cbase + nt * 8;
                float v0 = acc[mt][nt][hh * 2 + 0] + bias[col];
                float v1 = acc[mt][nt][hh * 2 + 1] + bias[col + 1];
                size_t off = (size_t)row * N + col;
                if (MODE == 1) {
                    v0 = 0.5f * v0 * (1.0f + erff(v0 * 0.70710678118654752f));
                    v1 = 0.5f * v1 * (1.0f + erff(v1 * 0.70710678118654752f));
                    uint2 pk = { pack_split(v0), pack_split(v1) };
                    *(uint2*)((uint32_t*)outp + off) = pk;
                } else {
                    const float2 rr = *(const float2*)(resid + off);
                    float2 ov = { v0 + rr.x, v1 + rr.y };
                    *(float2*)((float*)outp + off) = ov;
                }
            }
}

// ---------------- launch ----------------
extern "C" void kernel_launch(void* const* d_in, const int* in_sizes, int n_in,
                              void* d_out, int out_size)
{
    const float* x    = (const float*)d_in[0];
    const float* ln1g = (const float*)d_in[1];
    const float* ln1b = (const float*)d_in[2];
    const float* Wq   = (const float*)d_in[3];
    const float* bq   = (const float*)d_in[4];
    const float* Wk   = (const float*)d_in[5];
    const float* bk   = (const float*)d_in[6];
    const float* Wv   = (const float*)d_in[7];
    const float* bv   = (const float*)d_in[8];
    const float* ln2g = (const float*)d_in[9];
    const float* ln2b = (const float*)d_in[10];
    const float* W1   = (const float*)d_in[11];
    const float* b1   = (const float*)d_in[12];
    const float* W2   = (const float*)d_in[13];
    const float* b2   = (const float*)d_in[14];
    float* out = (float*)d_out;

    float *ln, *qb, *kb, *vb, *x1;
    uint32_t *lnp, *actp, *w1s, *w1w, *w2s, *w2w;
    cudaGetSymbolAddress((void**)&ln,   g_ln);
    cudaGetSymbolAddress((void**)&lnp,  g_lnp);
    cudaGetSymbolAddress((void**)&qb,   g_q);
    cudaGetSymbolAddress((void**)&kb,   g_k);
    cudaGetSymbolAddress((void**)&vb,   g_v);
    cudaGetSymbolAddress((void**)&x1,   g_x1);
    cudaGetSymbolAddress((void**)&actp, g_actp);
    cudaGetSymbolAddress((void**)&w1s,  g_w1s);
    cudaGetSymbolAddress((void**)&w1w,  g_w1w);
    cudaGetSymbolAddress((void**)&w2s,  g_w2s);
    cudaGetSymbolAddress((void**)&w2w,  g_w2w);

    const int ATTN_SMEM = (16 * 1024 + 64 * 65 + 16 * 64) * (int)sizeof(float);
    cudaFuncSetAttribute((const void*)attn_kernel,
                         cudaFuncAttributeMaxDynamicSharedMemorySize, ATTN_SMEM);
    const int GEMM_SMEM = 2 * STAGE_B + 256;   // 98560
    cudaFuncSetAttribute(gemm_hmma_kernel<1>,
                         cudaFuncAttributeMaxDynamicSharedMemorySize, GEMM_SMEM);
    cudaFuncSetAttribute(gemm_hmma_kernel<2>,
                         cudaFuncAttributeMaxDynamicSharedMemorySize, GEMM_SMEM);

    // weight conversion (every call; cheap)
    convert_w_kernel<<<(DMLP * DMODEL + 255) / 256, 256>>>(W1, w1s, w1w, DMLP * DMODEL);
    convert_w_kernel<<<(DMODEL * DMLP + 255) / 256, 256>>>(W2, w2s, w2w, DMODEL * DMLP);

    // 1) LN1 (fp32 out for qkv)
    ln_kernel<<<TOKENS, 256>>>(x, ln1g, ln1b, ln);
    // 2) per-head QKV
    qkv_kernel<<<dim3(TOKENS / 64, NHEAD), 256>>>(ln, Wq, bq, Wk, bk, Wv, bv, qb, kb, vb);
    // 3) attention + residual -> x1
    attn_kernel<<<dim3(SEQ / 16, NHEAD, BATCH), 256, ATTN_SMEM>>>(qb, kb, vb, x, x1);
    // 4) LN2 (packed split-bf16 out)
    ln_packed_kernel<<<TOKENS, 256>>>(x1, ln2g, ln2b, lnp);
    // 5) MLP up + GELU (HMMA) -> packed act
    gemm_hmma_kernel<1><<<dim3(DMLP / 128, TOKENS / 128), 256, GEMM_SMEM>>>(
        lnp, w1s, w1w, b1, nullptr, (void*)actp, DMLP, DMODEL / 1);
    // 6) MLP down + bias + residual (HMMA) -> d_out
    gemm_hmma_kernel<2><<<dim3(DMODEL / 128, TOKENS / 128), 256, GEMM_SMEM>>>(
        actp, w2s, w2w, b2, x1, (void*)out, DMODEL, DMLP);
}

// round 5
// speedup vs baseline: 3.0132x; 2.0009x over previous
#include <cuda_runtime.h>
#include <cuda_bf16.h>
#include <cuda_fp16.h>
#include <math.h>
#include <stdint.h>

#define TOKENS 16384
#define DMODEL 768
#define NHEAD  12
#define HDIM   64
#define DMLP   3072
#define SEQ    1024
#define BATCH  16

// ---------------- scratch (device globals; no cudaMalloc allowed) ----------------
__device__ float    g_ln  [TOKENS * DMODEL];      // LN1 out fp32 (for qkv)
__device__ uint32_t g_lnp [TOKENS * DMODEL];      // LN2 out packed bf16(hi,lo)
__device__ uint32_t g_qp  [TOKENS * DMODEL];      // q packed (hi,lo), pre-scaled by 0.125 [tok][h*64+o]
__device__ uint32_t g_ks  [TOKENS * DMODEL];      // k packed (hi,lo)                     [tok][h*64+o]
__device__ uint32_t g_kw  [TOKENS * DMODEL];      // k packed (lo,hi)                     [tok][h*64+o]
__device__ __half   g_vt  [TOKENS * DMODEL];      // V^T f16: [(b*12+h)*64+d][1024]
__device__ float    g_x1  [TOKENS * DMODEL];      // x + attn
__device__ uint32_t g_actp[TOKENS * DMLP];        // GELU out packed bf16(hi,lo)
__device__ uint32_t g_w1s [DMLP * DMODEL];
__device__ uint32_t g_w1w [DMLP * DMODEL];
__device__ uint32_t g_w2s [DMODEL * DMLP];
__device__ uint32_t g_w2w [DMODEL * DMLP];

// ---------------- PTX helpers (portable sm_80-class only) ----------------
__device__ __forceinline__ void cp16(uint32_t s, const void* g) {
    asm volatile("cp.async.cg.shared.global [%0], [%1], 16;" :: "r"(s), "l"(g));
}
__device__ __forceinline__ void cp_commit() { asm volatile("cp.async.commit_group;" ::: "memory"); }
__device__ __forceinline__ void cp_wait1()  { asm volatile("cp.async.wait_group 1;" ::: "memory"); }
__device__ __forceinline__ void cp_wait0()  { asm volatile("cp.async.wait_group 0;" ::: "memory"); }

__device__ __forceinline__ void ldsm4(uint32_t* r, uint32_t addr) {
    asm volatile("ldmatrix.sync.aligned.m8n8.x4.shared.b16 {%0,%1,%2,%3}, [%4];"
                 : "=r"(r[0]), "=r"(r[1]), "=r"(r[2]), "=r"(r[3]) : "r"(addr));
}
__device__ __forceinline__ void mma_bf16(float* d, const uint32_t* a, const uint32_t* b) {
    asm volatile(
        "mma.sync.aligned.m16n8k16.row.col.f32.bf16.bf16.f32 "
        "{%0,%1,%2,%3}, {%4,%5,%6,%7}, {%8,%9}, {%0,%1,%2,%3};"
        : "+f"(d[0]), "+f"(d[1]), "+f"(d[2]), "+f"(d[3])
        : "r"(a[0]), "r"(a[1]), "r"(a[2]), "r"(a[3]), "r"(b[0]), "r"(b[1]));
}
__device__ __forceinline__ void mma_f16(float* d, const uint32_t* a, const uint32_t* b) {
    asm volatile(
        "mma.sync.aligned.m16n8k16.row.col.f32.f16.f16.f32 "
        "{%0,%1,%2,%3}, {%4,%5,%6,%7}, {%8,%9}, {%0,%1,%2,%3};"
        : "+f"(d[0]), "+f"(d[1]), "+f"(d[2]), "+f"(d[3])
        : "r"(a[0]), "r"(a[1]), "r"(a[2]), "r"(a[3]), "r"(b[0]), "r"(b[1]));
}
__device__ __forceinline__ uint32_t f16x2(float hi, float lo) {
    uint32_t u;
    asm("cvt.rn.f16x2.f32 %0, %1, %2;" : "=r"(u) : "f"(hi), "f"(lo));
    return u;
}

// bf16 split pack: low half = hi, high half = lo
__device__ __forceinline__ uint32_t pack_split(float x) {
    __nv_bfloat16 h = __float2bfloat16(x);
    float hf = __bfloat162float(h);
    __nv_bfloat16 l = __float2bfloat16(x - hf);
    uint32_t hu = (uint32_t)__bfloat16_as_ushort(h);
    uint32_t lu = (uint32_t)__bfloat16_as_ushort(l);
    return hu | (lu << 16);
}
__device__ __forceinline__ void pack_split2(float x, uint32_t& s, uint32_t& w) {
    __nv_bfloat16 h = __float2bfloat16(x);
    float hf = __bfloat162float(h);
    __nv_bfloat16 l = __float2bfloat16(x - hf);
    uint32_t hu = (uint32_t)__bfloat16_as_ushort(h);
    uint32_t lu = (uint32_t)__bfloat16_as_ushort(l);
    s = hu | (lu << 16);
    w = lu | (hu << 16);
}

// ---------------- LayerNorm (fp32 out) ----------------
__global__ void ln_kernel(const float* __restrict__ x, const float* __restrict__ g,
                          const float* __restrict__ b, float* __restrict__ out)
{
    int tok = blockIdx.x;
    int t = threadIdx.x;
    const float* xr = x + (size_t)tok * DMODEL;
    float v0 = xr[t], v1 = xr[t + 256], v2 = xr[t + 512];
    float s = v0 + v1 + v2;
    __shared__ float red[8];
#pragma unroll
    for (int o = 16; o > 0; o >>= 1) s += __shfl_xor_sync(0xffffffffu, s, o);
    if ((t & 31) == 0) red[t >> 5] = s;
    __syncthreads();
    float tot = 0.f;
#pragma unroll
    for (int i = 0; i < 8; i++) tot += red[i];
    float mu = tot * (1.0f / DMODEL);
    float d0 = v0 - mu, d1 = v1 - mu, d2 = v2 - mu;
    float sq = d0 * d0 + d1 * d1 + d2 * d2;
#pragma unroll
    for (int o = 16; o > 0; o >>= 1) sq += __shfl_xor_sync(0xffffffffu, sq, o);
    __syncthreads();
    if ((t & 31) == 0) red[t >> 5] = sq;
    __syncthreads();
    float vs = 0.f;
#pragma unroll
    for (int i = 0; i < 8; i++) vs += red[i];
    float rs = rsqrtf(vs * (1.0f / DMODEL) + 1e-5f);
    float* orow = out + (size_t)tok * DMODEL;
    orow[t]       = d0 * rs * g[t]       + b[t];
    orow[t + 256] = d1 * rs * g[t + 256] + b[t + 256];
    orow[t + 512] = d2 * rs * g[t + 512] + b[t + 512];
}

// ---------------- LayerNorm (packed bf16 split out) ----------------
__global__ void ln_packed_kernel(const float* __restrict__ x, const float* __restrict__ g,
                                 const float* __restrict__ b, uint32_t* __restrict__ out)
{
    int tok = blockIdx.x;
    int t = threadIdx.x;
    const float* xr = x + (size_t)tok * DMODEL;
    float v0 = xr[t], v1 = xr[t + 256], v2 = xr[t + 512];
    float s = v0 + v1 + v2;
    __shared__ float red[8];
#pragma unroll
    for (int o = 16; o > 0; o >>= 1) s += __shfl_xor_sync(0xffffffffu, s, o);
    if ((t & 31) == 0) red[t >> 5] = s;
    __syncthreads();
    float tot = 0.f;
#pragma unroll
    for (int i = 0; i < 8; i++) tot += red[i];
    float mu = tot * (1.0f / DMODEL);
    float d0 = v0 - mu, d1 = v1 - mu, d2 = v2 - mu;
    float sq = d0 * d0 + d1 * d1 + d2 * d2;
#pragma unroll
    for (int o = 16; o > 0; o >>= 1) sq += __shfl_xor_sync(0xffffffffu, sq, o);
    __syncthreads();
    if ((t & 31) == 0) red[t >> 5] = sq;
    __syncthreads();
    float vs = 0.f;
#pragma unroll
    for (int i = 0; i < 8; i++) vs += red[i];
    float rs = rsqrtf(vs * (1.0f / DMODEL) + 1e-5f);
    uint32_t* orow = out + (size_t)tok * DMODEL;
    orow[t]       = pack_split(d0 * rs * g[t]       + b[t]);
    orow[t + 256] = pack_split(d1 * rs * g[t + 256] + b[t + 256]);
    orow[t + 512] = pack_split(d2 * rs * g[t + 512] + b[t + 512]);
}

// ---------------- weight conversion ----------------
__global__ void convert_w_kernel(const float* __restrict__ W,
                                 uint32_t* __restrict__ same, uint32_t* __restrict__ swp, int n)
{
    int i = blockIdx.x * 256 + threadIdx.x;
    if (i < n) {
        uint32_t s, w;
        pack_split2(W[i], s, w);
        same[i] = s;
        swp[i]  = w;
    }
}

// ---------------- Block-diagonal per-head QKV -> packed q/k + V^T f16 ----------------
__global__ void __launch_bounds__(256) qkv_kernel(
    const float* __restrict__ ln,
    const float* __restrict__ Wq, const float* __restrict__ bq,
    const float* __restrict__ Wk, const float* __restrict__ bk,
    const float* __restrict__ Wv, const float* __restrict__ bv,
    uint32_t* __restrict__ qp, uint32_t* __restrict__ ksp,
    uint32_t* __restrict__ kwp, __half* __restrict__ vt)
{
    __shared__ float Xs[64 * 65];
    __shared__ float Ws[64 * 65];
    int hh = blockIdx.y;
    int t0 = blockIdx.x * 64;
    int t  = threadIdx.x;
    int tx = t & 15, ty = t >> 4;

#pragma unroll
    for (int it = 0; it < 4; it++) {
        int idx = it * 1024 + t * 4;
        int r = idx >> 6, c = idx & 63;
        float4 x4 = *(const float4*)(ln + (size_t)(t0 + r) * DMODEL + hh * HDIM + c);
        Xs[(c + 0) * 65 + r] = x4.x;
        Xs[(c + 1) * 65 + r] = x4.y;
        Xs[(c + 2) * 65 + r] = x4.z;
        Xs[(c + 3) * 65 + r] = x4.w;
    }

    const float* Wm[3] = { Wq + hh * 4096, Wk + hh * 4096, Wv + hh * 4096 };
    const float* bm[3] = { bq + hh * 64,  bk + hh * 64,  bv + hh * 64 };

    for (int m = 0; m < 3; m++) {
        __syncthreads();
#pragma unroll
        for (int it = 0; it < 4; it++) {
            int idx = it * 1024 + t * 4;
            int r = idx >> 6, c = idx & 63;
            float4 w4 = *(const float4*)(Wm[m] + r * 64 + c);
            Ws[(c + 0) * 65 + r] = w4.x;
            Ws[(c + 1) * 65 + r] = w4.y;
            Ws[(c + 2) * 65 + r] = w4.z;
            Ws[(c + 3) * 65 + r] = w4.w;
        }
        __syncthreads();

        float acc[4][4] = {};
#pragma unroll
        for (int d = 0; d < 64; d++) {
            float xa[4], wb[4];
#pragma unroll
            for (int i = 0; i < 4; i++) xa[i] = Xs[d * 65 + ty * 4 + i];
#pragma unroll
            for (int j = 0; j < 4; j++) wb[j] = Ws[d * 65 + tx + 16 * j];
#pragma unroll
            for (int i = 0; i < 4; i++)
#pragma unroll
                for (int j = 0; j < 4; j++) acc[i][j] += xa[i] * wb[j];
        }
#pragma unroll
        for (int i = 0; i < 4; i++) {
            int tok = t0 + ty * 4 + i;
#pragma unroll
            for (int j = 0; j < 4; j++) {
                int o = tx + 16 * j;
                float val = acc[i][j] + bm[m][o];
                size_t off = (size_t)tok * DMODEL + hh * HDIM + o;   // [tok][h*64+o]
                if (m == 0) {
                    qp[off] = pack_split(0.125f * val);
                } else if (m == 1) {
                    uint32_t s, w;
                    pack_split2(val, s, w);
                    ksp[off] = s;
                    kwp[off] = w;
                } else {
                    int bb = tok >> 10, pos = tok & 1023;
                    vt[((size_t)((bb * 12 + hh) * 64 + o)) * 1024 + pos] = __float2half(val);
                }
            }
        }
    }
}

// ---------------- HMMA flash attention + residual ----------------
// CTA: (b,h) x 128 queries; stream 16 key-tiles of 64.
// Scores: split-bf16 exact MMA (Q pre-scaled). No max (|s| <~ 2). P,V f16 MMA.
// Smem: Q 32KB + 2 x (Ks 16K + Kw 16K + Vt 8K) = 112KB.
#define AT_BUF 40960

__global__ void __launch_bounds__(256, 1) attn_mma_kernel(
    const uint32_t* __restrict__ qp, const uint32_t* __restrict__ ksp,
    const uint32_t* __restrict__ kwp, const __half* __restrict__ vt,
    const float* __restrict__ x, float* __restrict__ out)
{
    extern __shared__ char dsm[];
    uint32_t sb = (uint32_t)__cvta_generic_to_shared(dsm);

    const int b = blockIdx.z, hh = blockIdx.y;
    const int q0 = blockIdx.x * 128;
    const int t = threadIdx.x, lane = t & 31, w = t >> 5;
    const int wq = w * 16;
    const int bh = b * 12 + hh;
    const int ho = hh * HDIM;                       // head column offset
    const size_t tok0 = (size_t)b * 1024 + q0;

    const uint32_t Qb = sb;
    const uint32_t Bb = sb + 32768;

    // Q tile: 128 rows x 64 u32 (256B rows, 16 chunks, swizzled)
#pragma unroll
    for (int i = 0; i < 8; i++) {
        int idx = t + 256 * i;
        int r = idx >> 4, c = idx & 15;
        cp16(Qb + r * 256 + (uint32_t)((c ^ (r & 7)) << 4),
             qp + (tok0 + r) * DMODEL + ho + c * 4);
    }
    // key-tile 0
    {
        int kg0 = b * 1024;
#pragma unroll
        for (int i = 0; i < 4; i++) {
            int idx = t + 256 * i;
            int r = idx >> 4, c = idx & 15;
            uint32_t so = (uint32_t)(r * 256 + ((c ^ (r & 7)) << 4));
            cp16(Bb + so,         ksp + (size_t)(kg0 + r) * DMODEL + ho + c * 4);
            cp16(Bb + 16384 + so, kwp + (size_t)(kg0 + r) * DMODEL + ho + c * 4);
        }
#pragma unroll
        for (int i = 0; i < 2; i++) {
            int idx = t + 256 * i;
            int r = idx >> 3, c = idx & 7;
            cp16(Bb + 32768 + (uint32_t)(r * 128 + ((c ^ (r & 7)) << 4)),
                 vt + ((size_t)(bh * 64 + r)) * 1024 + c * 8);
        }
    }
    cp_commit();

    float oacc[8][4] = {};
    float rs0 = 0.f, rs1 = 0.f;
    uint32_t af[8][4];

    for (int kt = 0; kt < 16; kt++) {
        if (kt + 1 < 16) {
            uint32_t nb = Bb + (uint32_t)((kt + 1) & 1) * AT_BUF;
            int kg = b * 1024 + (kt + 1) * 64;
#pragma unroll
            for (int i = 0; i < 4; i++) {
                int idx = t + 256 * i;
                int r = idx >> 4, c = idx & 15;
                uint32_t so = (uint32_t)(r * 256 + ((c ^ (r & 7)) << 4));
                cp16(nb + so,         ksp + (size_t)(kg + r) * DMODEL + ho + c * 4);
                cp16(nb + 16384 + so, kwp + (size_t)(kg + r) * DMODEL + ho + c * 4);
            }
#pragma unroll
            for (int i = 0; i < 2; i++) {
                int idx = t + 256 * i;
                int r = idx >> 3, c = idx & 7;
                cp16(nb + 32768 + (uint32_t)(r * 128 + ((c ^ (r & 7)) << 4)),
                     vt + ((size_t)(bh * 64 + r)) * 1024 + (kt + 1) * 64 + c * 8);
            }
            cp_commit();
            cp_wait1();
        } else {
            cp_wait0();
        }
        __syncthreads();

        uint32_t cb = Bb + (uint32_t)(kt & 1) * AT_BUF;

        if (kt == 0) {
            // hoisted Q A-fragments (Q smem ready after first wait)
#pragma unroll
            for (int ks = 0; ks < 8; ks++) {
                int r = wq + (lane & 15);
                int c = 2 * ks + (lane >> 4);
                ldsm4(af[ks], Qb + r * 256 + (uint32_t)((c ^ (r & 7)) << 4));
            }
        }

        // ---- scores: split-bf16, two passes ----
        float sacc[8][4] = {};
#pragma unroll
        for (int pass = 0; pass < 2; pass++) {
            uint32_t kb = cb + (uint32_t)pass * 16384;
#pragma unroll
            for (int kp = 0; kp < 4; kp++) {
                uint32_t bf[8][4];
#pragma unroll
                for (int j = 0; j < 8; j++) {
                    int r = j * 8 + (lane & 7);
                    int c = kp * 4 + ((lane >> 3) & 3);
                    ldsm4(bf[j], kb + r * 256 + (uint32_t)((c ^ (r & 7)) << 4));
                }
#pragma unroll
                for (int s = 0; s < 2; s++)
#pragma unroll
                    for (int j = 0; j < 8; j++)
                        mma_bf16(sacc[j], af[kp * 2 + s], &bf[j][s * 2]);
            }
        }

        // ---- exp (no max) + pack P to f16 A-fragments ----
        uint32_t pa[4][4];
#pragma unroll
        for (int j = 0; j < 8; j++) {
            float e0 = __expf(sacc[j][0]);
            float e1 = __expf(sacc[j][1]);
            float e2 = __expf(sacc[j][2]);
            float e3 = __expf(sacc[j][3]);
            rs0 += e0 + e1;
            rs1 += e2 + e3;
            pa[j >> 1][(j & 1) * 2 + 0] = f16x2(e1, e0);
            pa[j >> 1][(j & 1) * 2 + 1] = f16x2(e3, e2);
        }

        // ---- O += P @ V (f16) ----
        uint32_t vb0 = cb + 32768;
#pragma unroll
        for (int kp = 0; kp < 2; kp++) {
            uint32_t vb[8][4];
#pragma unroll
            for (int j = 0; j < 8; j++) {
                int r = j * 8 + (lane & 7);
                int c = kp * 4 + ((lane >> 3) & 3);
                ldsm4(vb[j], vb0 + r * 128 + (uint32_t)((c ^ (r & 7)) << 4));
            }
#pragma unroll
            for (int s = 0; s < 2; s++)
#pragma unroll
                for (int j = 0; j < 8; j++)
                    mma_f16(oacc[j], pa[kp * 2 + s], &vb[j][s * 2]);
        }
        __syncthreads();
    }

    // full row sums within quad
    rs0 += __shfl_xor_sync(0xffffffffu, rs0, 1);
    rs0 += __shfl_xor_sync(0xffffffffu, rs0, 2);
    rs1 += __shfl_xor_sync(0xffffffffu, rs1, 1);
    rs1 += __shfl_xor_sync(0xffffffffu, rs1, 2);
    float inv0 = 1.0f / rs0, inv1 = 1.0f / rs1;

    size_t row0 = tok0 + wq + (lane >> 2);
    size_t row1 = row0 + 8;
#pragma unroll
    for (int j = 0; j < 8; j++) {
        int col = ho + j * 8 + 2 * (lane & 3);
        size_t o0 = row0 * DMODEL + col;
        size_t o1 = row1 * DMODEL + col;
        float2 x0 = *(const float2*)(x + o0);
        float2 x1v = *(const float2*)(x + o1);
        float2 r0 = { oacc[j][0] * inv0 + x0.x,  oacc[j][1] * inv0 + x0.y };
        float2 r1 = { oacc[j][2] * inv1 + x1v.x, oacc[j][3] * inv1 + x1v.y };
        *(float2*)(out + o0) = r0;
        *(float2*)(out + o1) = r1;
    }
}

// ---------------- HMMA split-bf16 GEMM (unchanged from R3) ----------------
#define TILE_B  16384
#define STAGE_B 49152

__device__ __forceinline__ uint32_t sw(uint32_t b, int row, int ch) {
    return b + (uint32_t)(row * 128) + (uint32_t)((ch ^ (row & 7)) << 4);
}

__device__ __forceinline__ void load_tile3(uint32_t sb,
    const uint32_t* __restrict__ Ap, const uint32_t* __restrict__ Bs,
    const uint32_t* __restrict__ Bw, int m0, int n0, int Ku32, int ic, int t)
{
#pragma unroll
    for (int i = 0; i < 4; i++) {
        int idx = t + 256 * i;
        int row = idx >> 3, ch = idx & 7;
        cp16(sw(sb, row, ch),              Ap + (size_t)(m0 + row) * Ku32 + ic * 32 + ch * 4);
        cp16(sw(sb + TILE_B, row, ch),     Bs + (size_t)(n0 + row) * Ku32 + ic * 32 + ch * 4);
        cp16(sw(sb + 2 * TILE_B, row, ch), Bw + (size_t)(n0 + row) * Ku32 + ic * 32 + ch * 4);
    }
}

template<int MODE>
__global__ void __launch_bounds__(256, 1)
gemm_hmma_kernel(const uint32_t* __restrict__ Ap,
                 const uint32_t* __restrict__ Bs, const uint32_t* __restrict__ Bw,
                 const float* __restrict__ bias, const float* __restrict__ resid,
                 void* __restrict__ outp, int N, int Ku32)
{
    extern __shared__ char dsm[];
    uint32_t smem_u32 = (uint32_t)__cvta_generic_to_shared(dsm);
    uint32_t base = (smem_u32 + 127) & ~127u;

    const int t = threadIdx.x;
    const int lane = t & 31, wid = t >> 5;
    const int m0 = blockIdx.y * 128, n0 = blockIdx.x * 128;
    const int warp_m = (wid >> 2) * 64, warp_n = (wid & 3) * 32;

    float acc[4][4][4] = {};
    const int NC = Ku32 >> 5;

    load_tile3(base, Ap, Bs, Bw, m0, n0, Ku32, 0, t);
    cp_commit();

    for (int ic = 0; ic < NC; ic++) {
        uint32_t cb = base + (uint32_t)(ic & 1) * STAGE_B;
        if (ic + 1 < NC) {
            load_tile3(base + (uint32_t)((ic + 1) & 1) * STAGE_B,
                       Ap, Bs, Bw, m0, n0, Ku32, ic + 1, t);
            cp_commit();
            cp_wait1();
        } else {
            cp_wait0();
        }
        __syncthreads();

        uint32_t Ab = cb, B0 = cb + TILE_B, B1 = cb + 2 * TILE_B;
#pragma unroll
        for (int kp = 0; kp < 2; kp++) {
            uint32_t afr[4][2][4];
#pragma unroll
            for (int mt = 0; mt < 4; mt++)
#pragma unroll
                for (int ks = 0; ks < 2; ks++) {
                    int row = warp_m + mt * 16 + (lane & 15);
                    int ch  = (kp * 2 + ks) * 2 + (lane >> 4);
                    ldsm4(afr[mt][ks], sw(Ab, row, ch));
                }
            uint32_t bfr[4][2][4];
#pragma unroll
            for (int nt = 0; nt < 4; nt++) {
                int row = warp_n + nt * 8 + (lane & 7);
                int ch  = kp * 4 + ((lane >> 3) & 3);
                ldsm4(bfr[nt][0], sw(B0, row, ch));
                ldsm4(bfr[nt][1], sw(B1, row, ch));
            }
#pragma unroll
            for (int ks = 0; ks < 2; ks++)
#pragma unroll
                for (int mt = 0; mt < 4; mt++)
#pragma unroll
                    for (int nt = 0; nt < 4; nt++) {
                        mma_bf16(acc[mt][nt], afr[mt][ks], &bfr[nt][0][ks * 2]);
                        mma_bf16(acc[mt][nt], afr[mt][ks], &bfr[nt][1][ks * 2]);
                    }
        }
        __syncthreads();
    }

    int rbase = m0 + warp_m + (lane >> 2);
    int cbase = n0 + warp_n + (lane & 3) * 2;
#pragma unroll
    for (int mt = 0; mt < 4; mt++)
#pragma unroll
        for (int nt = 0; nt < 4; nt++)
#pragma unroll
            for (int hhh = 0; hhh < 2; hhh++) {
                int row = rbase + mt * 16 + hhh * 8;
                int col = cbase + nt * 8;
                float v0 = acc[mt][nt][hhh * 2 + 0] + bias[col];
                float v1 = acc[mt][nt][hhh * 2 + 1] + bias[col + 1];
                size_t off = (size_t)row * N + col;
                if (MODE == 1) {
                    v0 = 0.5f * v0 * (1.0f + erff(v0 * 0.70710678118654752f));
                    v1 = 0.5f * v1 * (1.0f + erff(v1 * 0.70710678118654752f));
                    uint2 pk = { pack_split(v0), pack_split(v1) };
                    *(uint2*)((uint32_t*)outp + off) = pk;
                } else {
                    const float2 rr = *(const float2*)(resid + off);
                    float2 ov = { v0 + rr.x, v1 + rr.y };
                    *(float2*)((float*)outp + off) = ov;
                }
            }
}

// ---------------- launch ----------------
extern "C" void kernel_launch(void* const* d_in, const int* in_sizes, int n_in,
                              void* d_out, int out_size)
{
    const float* x    = (const float*)d_in[0];
    const float* ln1g = (const float*)d_in[1];
    const float* ln1b = (const float*)d_in[2];
    const float* Wq   = (const float*)d_in[3];
    const float* bq   = (const float*)d_in[4];
    const float* Wk   = (const float*)d_in[5];
    const float* bk   = (const float*)d_in[6];
    const float* Wv   = (const float*)d_in[7];
    const float* bv   = (const float*)d_in[8];
    const float* ln2g = (const float*)d_in[9];
    const float* ln2b = (const float*)d_in[10];
    const float* W1   = (const float*)d_in[11];
    const float* b1   = (const float*)d_in[12];
    const float* W2   = (const float*)d_in[13];
    const float* b2   = (const float*)d_in[14];
    float* out = (float*)d_out;

    float *ln, *x1;
    uint32_t *lnp, *qp, *ksp, *kwp, *actp, *w1s, *w1w, *w2s, *w2w;
    __half* vt;
    cudaGetSymbolAddress((void**)&ln,   g_ln);
    cudaGetSymbolAddress((void**)&lnp,  g_lnp);
    cudaGetSymbolAddress((void**)&qp,   g_qp);
    cudaGetSymbolAddress((void**)&ksp,  g_ks);
    cudaGetSymbolAddress((void**)&kwp,  g_kw);
    cudaGetSymbolAddress((void**)&vt,   g_vt);
    cudaGetSymbolAddress((void**)&x1,   g_x1);
    cudaGetSymbolAddress((void**)&actp, g_actp);
    cudaGetSymbolAddress((void**)&w1s,  g_w1s);
    cudaGetSymbolAddress((void**)&w1w,  g_w1w);
    cudaGetSymbolAddress((void**)&w2s,  g_w2s);
    cudaGetSymbolAddress((void**)&w2w,  g_w2w);

    const int ATTN_SMEM = 32768 + 2 * AT_BUF;   // 114688
    cudaFuncSetAttribute((const void*)attn_mma_kernel,
                         cudaFuncAttributeMaxDynamicSharedMemorySize, ATTN_SMEM);
    const int GEMM_SMEM = 2 * STAGE_B + 256;
    cudaFuncSetAttribute(gemm_hmma_kernel<1>,
                         cudaFuncAttributeMaxDynamicSharedMemorySize, GEMM_SMEM);
    cudaFuncSetAttribute(gemm_hmma_kernel<2>,
                         cudaFuncAttributeMaxDynamicSharedMemorySize, GEMM_SMEM);

    convert_w_kernel<<<(DMLP * DMODEL + 255) / 256, 256>>>(W1, w1s, w1w, DMLP * DMODEL);
    convert_w_kernel<<<(DMODEL * DMLP + 255) / 256, 256>>>(W2, w2s, w2w, DMODEL * DMLP);

    // 1) LN1
    ln_kernel<<<TOKENS, 256>>>(x, ln1g, ln1b, ln);
    // 2) QKV -> packed q/k + V^T f16
    qkv_kernel<<<dim3(TOKENS / 64, NHEAD), 256>>>(ln, Wq, bq, Wk, bk, Wv, bv, qp, ksp, kwp, vt);
    // 3) HMMA attention + residual -> x1
    attn_mma_kernel<<<dim3(SEQ / 128, NHEAD, BATCH), 256, ATTN_SMEM>>>(qp, ksp, kwp, vt, x, x1);
    // 4) LN2 (packed)
    ln_packed_kernel<<<TOKENS, 256>>>(x1, ln2g, ln2b, lnp);
    // 5) MLP up + GELU
    gemm_hmma_kernel<1><<<dim3(DMLP / 128, TOKENS / 128), 256, GEMM_SMEM>>>(
        lnp, w1s, w1w, b1, nullptr, (void*)actp, DMLP, DMODEL);
    // 6) MLP down + bias + residual -> out
    gemm_hmma_kernel<2><<<dim3(DMODEL / 128, TOKENS / 128), 256, GEMM_SMEM>>>(
        actp, w2s, w2w, b2, x1, (void*)out, DMODEL, DMLP);
}

// round 6
// speedup vs baseline: 3.6079x; 1.1974x over previous
#include <cuda_runtime.h>
#include <cuda_bf16.h>
#include <cuda_fp16.h>
#include <math.h>
#include <stdint.h>

#define TOKENS 16384
#define DMODEL 768
#define NHEAD  12
#define HDIM   64
#define DMLP   3072
#define SEQ    1024
#define BATCH  16

// ---------------- scratch (device globals; no cudaMalloc allowed) ----------------
__device__ float    g_ln  [TOKENS * DMODEL];      // LN1 out fp32 (for qkv)
__device__ uint16_t g_lnh [TOKENS * DMODEL];      // LN2 out bf16 hi plane
__device__ uint16_t g_lnl [TOKENS * DMODEL];      // LN2 out bf16 lo plane
__device__ uint32_t g_qp  [TOKENS * DMODEL];      // q packed (hi,lo), pre-scaled by 0.125 [tok][h*64+o]
__device__ uint32_t g_ks  [TOKENS * DMODEL];      // k packed (hi,lo)
__device__ uint32_t g_kw  [TOKENS * DMODEL];      // k packed (lo,hi)
__device__ __half   g_vt  [TOKENS * DMODEL];      // V^T f16: [(b*12+h)*64+d][1024]
__device__ float    g_x1  [TOKENS * DMODEL];      // x + attn
__device__ uint16_t g_acth[TOKENS * DMLP];        // GELU out bf16 hi plane
__device__ uint16_t g_actl[TOKENS * DMLP];        // GELU out bf16 lo plane
__device__ uint16_t g_w1h [DMLP * DMODEL];
__device__ uint16_t g_w1l [DMLP * DMODEL];
__device__ uint16_t g_w2h [DMODEL * DMLP];
__device__ uint16_t g_w2l [DMODEL * DMLP];

// ---------------- PTX helpers (portable sm_80-class only) ----------------
__device__ __forceinline__ void cp16(uint32_t s, const void* g) {
    asm volatile("cp.async.cg.shared.global [%0], [%1], 16;" :: "r"(s), "l"(g));
}
__device__ __forceinline__ void cp_commit() { asm volatile("cp.async.commit_group;" ::: "memory"); }
__device__ __forceinline__ void cp_wait1()  { asm volatile("cp.async.wait_group 1;" ::: "memory"); }
__device__ __forceinline__ void cp_wait0()  { asm volatile("cp.async.wait_group 0;" ::: "memory"); }

__device__ __forceinline__ void ldsm4(uint32_t* r, uint32_t addr) {
    asm volatile("ldmatrix.sync.aligned.m8n8.x4.shared.b16 {%0,%1,%2,%3}, [%4];"
                 : "=r"(r[0]), "=r"(r[1]), "=r"(r[2]), "=r"(r[3]) : "r"(addr));
}
__device__ __forceinline__ void mma_bf16(float* d, const uint32_t* a, const uint32_t* b) {
    asm volatile(
        "mma.sync.aligned.m16n8k16.row.col.f32.bf16.bf16.f32 "
        "{%0,%1,%2,%3}, {%4,%5,%6,%7}, {%8,%9}, {%0,%1,%2,%3};"
        : "+f"(d[0]), "+f"(d[1]), "+f"(d[2]), "+f"(d[3])
        : "r"(a[0]), "r"(a[1]), "r"(a[2]), "r"(a[3]), "r"(b[0]), "r"(b[1]));
}
__device__ __forceinline__ void mma_f16(float* d, const uint32_t* a, const uint32_t* b) {
    asm volatile(
        "mma.sync.aligned.m16n8k16.row.col.f32.f16.f16.f32 "
        "{%0,%1,%2,%3}, {%4,%5,%6,%7}, {%8,%9}, {%0,%1,%2,%3};"
        : "+f"(d[0]), "+f"(d[1]), "+f"(d[2]), "+f"(d[3])
        : "r"(a[0]), "r"(a[1]), "r"(a[2]), "r"(a[3]), "r"(b[0]), "r"(b[1]));
}
__device__ __forceinline__ uint32_t f16x2(float hi, float lo) {
    uint32_t u;
    asm("cvt.rn.f16x2.f32 %0, %1, %2;" : "=r"(u) : "f"(hi), "f"(lo));
    return u;
}

// bf16 split helpers
__device__ __forceinline__ uint32_t pack_split(float x) {
    __nv_bfloat16 h = __float2bfloat16(x);
    float hf = __bfloat162float(h);
    __nv_bfloat16 l = __float2bfloat16(x - hf);
    uint32_t hu = (uint32_t)__bfloat16_as_ushort(h);
    uint32_t lu = (uint32_t)__bfloat16_as_ushort(l);
    return hu | (lu << 16);
}
__device__ __forceinline__ void pack_split2(float x, uint32_t& s, uint32_t& w) {
    __nv_bfloat16 h = __float2bfloat16(x);
    float hf = __bfloat162float(h);
    __nv_bfloat16 l = __float2bfloat16(x - hf);
    uint32_t hu = (uint32_t)__bfloat16_as_ushort(h);
    uint32_t lu = (uint32_t)__bfloat16_as_ushort(l);
    s = hu | (lu << 16);
    w = lu | (hu << 16);
}
__device__ __forceinline__ void split_hl(float x, uint16_t& h, uint16_t& l) {
    __nv_bfloat16 hb = __float2bfloat16(x);
    float hf = __bfloat162float(hb);
    __nv_bfloat16 lb = __float2bfloat16(x - hf);
    h = __bfloat16_as_ushort(hb);
    l = __bfloat16_as_ushort(lb);
}

// ---------------- LayerNorm (fp32 out) ----------------
__global__ void ln_kernel(const float* __restrict__ x, const float* __restrict__ g,
                          const float* __restrict__ b, float* __restrict__ out)
{
    int tok = blockIdx.x;
    int t = threadIdx.x;
    const float* xr = x + (size_t)tok * DMODEL;
    float v0 = xr[t], v1 = xr[t + 256], v2 = xr[t + 512];
    float s = v0 + v1 + v2;
    __shared__ float red[8];
#pragma unroll
    for (int o = 16; o > 0; o >>= 1) s += __shfl_xor_sync(0xffffffffu, s, o);
    if ((t & 31) == 0) red[t >> 5] = s;
    __syncthreads();
    float tot = 0.f;
#pragma unroll
    for (int i = 0; i < 8; i++) tot += red[i];
    float mu = tot * (1.0f / DMODEL);
    float d0 = v0 - mu, d1 = v1 - mu, d2 = v2 - mu;
    float sq = d0 * d0 + d1 * d1 + d2 * d2;
#pragma unroll
    for (int o = 16; o > 0; o >>= 1) sq += __shfl_xor_sync(0xffffffffu, sq, o);
    __syncthreads();
    if ((t & 31) == 0) red[t >> 5] = sq;
    __syncthreads();
    float vs = 0.f;
#pragma unroll
    for (int i = 0; i < 8; i++) vs += red[i];
    float rs = rsqrtf(vs * (1.0f / DMODEL) + 1e-5f);
    float* orow = out + (size_t)tok * DMODEL;
    orow[t]       = d0 * rs * g[t]       + b[t];
    orow[t + 256] = d1 * rs * g[t + 256] + b[t + 256];
    orow[t + 512] = d2 * rs * g[t + 512] + b[t + 512];
}

// ---------------- LayerNorm (split hi/lo bf16 planes out) ----------------
__global__ void ln_split_kernel(const float* __restrict__ x, const float* __restrict__ g,
                                const float* __restrict__ b,
                                uint16_t* __restrict__ oh, uint16_t* __restrict__ ol)
{
    int tok = blockIdx.x;
    int t = threadIdx.x;
    const float* xr = x + (size_t)tok * DMODEL;
    float v0 = xr[t], v1 = xr[t + 256], v2 = xr[t + 512];
    float s = v0 + v1 + v2;
    __shared__ float red[8];
#pragma unroll
    for (int o = 16; o > 0; o >>= 1) s += __shfl_xor_sync(0xffffffffu, s, o);
    if ((t & 31) == 0) red[t >> 5] = s;
    __syncthreads();
    float tot = 0.f;
#pragma unroll
    for (int i = 0; i < 8; i++) tot += red[i];
    float mu = tot * (1.0f / DMODEL);
    float d0 = v0 - mu, d1 = v1 - mu, d2 = v2 - mu;
    float sq = d0 * d0 + d1 * d1 + d2 * d2;
#pragma unroll
    for (int o = 16; o > 0; o >>= 1) sq += __shfl_xor_sync(0xffffffffu, sq, o);
    __syncthreads();
    if ((t & 31) == 0) red[t >> 5] = sq;
    __syncthreads();
    float vs = 0.f;
#pragma unroll
    for (int i = 0; i < 8; i++) vs += red[i];
    float rs = rsqrtf(vs * (1.0f / DMODEL) + 1e-5f);
    size_t base = (size_t)tok * DMODEL;
    float vals[3] = { d0 * rs * g[t] + b[t],
                      d1 * rs * g[t + 256] + b[t + 256],
                      d2 * rs * g[t + 512] + b[t + 512] };
#pragma unroll
    for (int i = 0; i < 3; i++) {
        uint16_t h, l;
        split_hl(vals[i], h, l);
        oh[base + t + 256 * i] = h;
        ol[base + t + 256 * i] = l;
    }
}

// ---------------- weight conversion: fp32 -> hi/lo bf16 planes ----------------
__global__ void convert_w_kernel(const float* __restrict__ W,
                                 uint16_t* __restrict__ wh, uint16_t* __restrict__ wl, int n)
{
    int i = blockIdx.x * 256 + threadIdx.x;
    if (i < n) {
        uint16_t h, l;
        split_hl(W[i], h, l);
        wh[i] = h;
        wl[i] = l;
    }
}

// ---------------- Block-diagonal per-head QKV -> packed q/k + V^T f16 ----------------
__global__ void __launch_bounds__(256) qkv_kernel(
    const float* __restrict__ ln,
    const float* __restrict__ Wq, const float* __restrict__ bq,
    const float* __restrict__ Wk, const float* __restrict__ bk,
    const float* __restrict__ Wv, const float* __restrict__ bv,
    uint32_t* __restrict__ qp, uint32_t* __restrict__ ksp,
    uint32_t* __restrict__ kwp, __half* __restrict__ vt)
{
    __shared__ float Xs[64 * 65];
    __shared__ float Ws[64 * 65];
    int hh = blockIdx.y;
    int t0 = blockIdx.x * 64;
    int t  = threadIdx.x;
    int tx = t & 15, ty = t >> 4;

#pragma unroll
    for (int it = 0; it < 4; it++) {
        int idx = it * 1024 + t * 4;
        int r = idx >> 6, c = idx & 63;
        float4 x4 = *(const float4*)(ln + (size_t)(t0 + r) * DMODEL + hh * HDIM + c);
        Xs[(c + 0) * 65 + r] = x4.x;
        Xs[(c + 1) * 65 + r] = x4.y;
        Xs[(c + 2) * 65 + r] = x4.z;
        Xs[(c + 3) * 65 + r] = x4.w;
    }

    const float* Wm[3] = { Wq + hh * 4096, Wk + hh * 4096, Wv + hh * 4096 };
    const float* bm[3] = { bq + hh * 64,  bk + hh * 64,  bv + hh * 64 };

    for (int m = 0; m < 3; m++) {
        __syncthreads();
#pragma unroll
        for (int it = 0; it < 4; it++) {
            int idx = it * 1024 + t * 4;
            int r = idx >> 6, c = idx & 63;
            float4 w4 = *(const float4*)(Wm[m] + r * 64 + c);
            Ws[(c + 0) * 65 + r] = w4.x;
            Ws[(c + 1) * 65 + r] = w4.y;
            Ws[(c + 2) * 65 + r] = w4.z;
            Ws[(c + 3) * 65 + r] = w4.w;
        }
        __syncthreads();

        float acc[4][4] = {};
#pragma unroll
        for (int d = 0; d < 64; d++) {
            float xa[4], wb[4];
#pragma unroll
            for (int i = 0; i < 4; i++) xa[i] = Xs[d * 65 + ty * 4 + i];
#pragma unroll
            for (int j = 0; j < 4; j++) wb[j] = Ws[d * 65 + tx + 16 * j];
#pragma unroll
            for (int i = 0; i < 4; i++)
#pragma unroll
                for (int j = 0; j < 4; j++) acc[i][j] += xa[i] * wb[j];
        }
#pragma unroll
        for (int i = 0; i < 4; i++) {
            int tok = t0 + ty * 4 + i;
#pragma unroll
            for (int j = 0; j < 4; j++) {
                int o = tx + 16 * j;
                float val = acc[i][j] + bm[m][o];
                size_t off = (size_t)tok * DMODEL + hh * HDIM + o;   // [tok][h*64+o]
                if (m == 0) {
                    qp[off] = pack_split(0.125f * val);
                } else if (m == 1) {
                    uint32_t s, w;
                    pack_split2(val, s, w);
                    ksp[off] = s;
                    kwp[off] = w;
                } else {
                    int bb = tok >> 10, pos = tok & 1023;
                    vt[((size_t)((bb * 12 + hh) * 64 + o)) * 1024 + pos] = __float2half(val);
                }
            }
        }
    }
}

// ---------------- HMMA flash attention + residual (unchanged from R5) ----------------
#define AT_BUF 40960

__global__ void __launch_bounds__(256, 1) attn_mma_kernel(
    const uint32_t* __restrict__ qp, const uint32_t* __restrict__ ksp,
    const uint32_t* __restrict__ kwp, const __half* __restrict__ vt,
    const float* __restrict__ x, float* __restrict__ out)
{
    extern __shared__ char dsm[];
    uint32_t sb = (uint32_t)__cvta_generic_to_shared(dsm);

    const int b = blockIdx.z, hh = blockIdx.y;
    const int q0 = blockIdx.x * 128;
    const int t = threadIdx.x, lane = t & 31, w = t >> 5;
    const int wq = w * 16;
    const int bh = b * 12 + hh;
    const int ho = hh * HDIM;
    const size_t tok0 = (size_t)b * 1024 + q0;

    const uint32_t Qb = sb;
    const uint32_t Bb = sb + 32768;

#pragma unroll
    for (int i = 0; i < 8; i++) {
        int idx = t + 256 * i;
        int r = idx >> 4, c = idx & 15;
        cp16(Qb + r * 256 + (uint32_t)((c ^ (r & 7)) << 4),
             qp + (tok0 + r) * DMODEL + ho + c * 4);
    }
    {
        int kg0 = b * 1024;
#pragma unroll
        for (int i = 0; i < 4; i++) {
            int idx = t + 256 * i;
            int r = idx >> 4, c = idx & 15;
            uint32_t so = (uint32_t)(r * 256 + ((c ^ (r & 7)) << 4));
            cp16(Bb + so,         ksp + (size_t)(kg0 + r) * DMODEL + ho + c * 4);
            cp16(Bb + 16384 + so, kwp + (size_t)(kg0 + r) * DMODEL + ho + c * 4);
        }
#pragma unroll
        for (int i = 0; i < 2; i++) {
            int idx = t + 256 * i;
            int r = idx >> 3, c = idx & 7;
            cp16(Bb + 32768 + (uint32_t)(r * 128 + ((c ^ (r & 7)) << 4)),
                 vt + ((size_t)(bh * 64 + r)) * 1024 + c * 8);
        }
    }
    cp_commit();

    float oacc[8][4] = {};
    float rs0 = 0.f, rs1 = 0.f;
    uint32_t af[8][4];

    for (int kt = 0; kt < 16; kt++) {
        if (kt + 1 < 16) {
            uint32_t nb = Bb + (uint32_t)((kt + 1) & 1) * AT_BUF;
            int kg = b * 1024 + (kt + 1) * 64;
#pragma unroll
            for (int i = 0; i < 4; i++) {
                int idx = t + 256 * i;
                int r = idx >> 4, c = idx & 15;
                uint32_t so = (uint32_t)(r * 256 + ((c ^ (r & 7)) << 4));
                cp16(nb + so,         ksp + (size_t)(kg + r) * DMODEL + ho + c * 4);
                cp16(nb + 16384 + so, kwp + (size_t)(kg + r) * DMODEL + ho + c * 4);
            }
#pragma unroll
            for (int i = 0; i < 2; i++) {
                int idx = t + 256 * i;
                int r = idx >> 3, c = idx & 7;
                cp16(nb + 32768 + (uint32_t)(r * 128 + ((c ^ (r & 7)) << 4)),
                     vt + ((size_t)(bh * 64 + r)) * 1024 + (kt + 1) * 64 + c * 8);
            }
            cp_commit();
            cp_wait1();
        } else {
            cp_wait0();
        }
        __syncthreads();

        uint32_t cb = Bb + (uint32_t)(kt & 1) * AT_BUF;

        if (kt == 0) {
#pragma unroll
            for (int ks = 0; ks < 8; ks++) {
                int r = wq + (lane & 15);
                int c = 2 * ks + (lane >> 4);
                ldsm4(af[ks], Qb + r * 256 + (uint32_t)((c ^ (r & 7)) << 4));
            }
        }

        float sacc[8][4] = {};
#pragma unroll
        for (int pass = 0; pass < 2; pass++) {
            uint32_t kb = cb + (uint32_t)pass * 16384;
#pragma unroll
            for (int kp = 0; kp < 4; kp++) {
                uint32_t bf[8][4];
#pragma unroll
                for (int j = 0; j < 8; j++) {
                    int r = j * 8 + (lane & 7);
                    int c = kp * 4 + ((lane >> 3) & 3);
                    ldsm4(bf[j], kb + r * 256 + (uint32_t)((c ^ (r & 7)) << 4));
                }
#pragma unroll
                for (int s = 0; s < 2; s++)
#pragma unroll
                    for (int j = 0; j < 8; j++)
                        mma_bf16(sacc[j], af[kp * 2 + s], &bf[j][s * 2]);
            }
        }

        uint32_t pa[4][4];
#pragma unroll
        for (int j = 0; j < 8; j++) {
            float e0 = __expf(sacc[j][0]);
            float e1 = __expf(sacc[j][1]);
            float e2 = __expf(sacc[j][2]);
            float e3 = __expf(sacc[j][3]);
            rs0 += e0 + e1;
            rs1 += e2 + e3;
            pa[j >> 1][(j & 1) * 2 + 0] = f16x2(e1, e0);
            pa[j >> 1][(j & 1) * 2 + 1] = f16x2(e3, e2);
        }

        uint32_t vb0 = cb + 32768;
#pragma unroll
        for (int kp = 0; kp < 2; kp++) {
            uint32_t vb[8][4];
#pragma unroll
            for (int j = 0; j < 8; j++) {
                int r = j * 8 + (lane & 7);
                int c = kp * 4 + ((lane >> 3) & 3);
                ldsm4(vb[j], vb0 + r * 128 + (uint32_t)((c ^ (r & 7)) << 4));
            }
#pragma unroll
            for (int s = 0; s < 2; s++)
#pragma unroll
                for (int j = 0; j < 8; j++)
                    mma_f16(oacc[j], pa[kp * 2 + s], &vb[j][s * 2]);
        }
        __syncthreads();
    }

    rs0 += __shfl_xor_sync(0xffffffffu, rs0, 1);
    rs0 += __shfl_xor_sync(0xffffffffu, rs0, 2);
    rs1 += __shfl_xor_sync(0xffffffffu, rs1, 1);
    rs1 += __shfl_xor_sync(0xffffffffu, rs1, 2);
    float inv0 = 1.0f / rs0, inv1 = 1.0f / rs1;

    size_t row0 = tok0 + wq + (lane >> 2);
    size_t row1 = row0 + 8;
#pragma unroll
    for (int j = 0; j < 8; j++) {
        int col = ho + j * 8 + 2 * (lane & 3);
        size_t o0 = row0 * DMODEL + col;
        size_t o1 = row1 * DMODEL + col;
        float2 x0 = *(const float2*)(x + o0);
        float2 x1v = *(const float2*)(x + o1);
        float2 r0 = { oacc[j][0] * inv0 + x0.x,  oacc[j][1] * inv0 + x0.y };
        float2 r1 = { oacc[j][2] * inv1 + x1v.x, oacc[j][3] * inv1 + x1v.y };
        *(float2*)(out + o0) = r0;
        *(float2*)(out + o1) = r1;
    }
}

// ---------------- HMMA 3-term split-bf16 GEMM ----------------
// C = A @ B^T + bias, A/B given as separate hi/lo bf16 planes.
// Terms: Ah*Bh + Ah*Bl + Al*Bh  (Al*Bl ~ 2^-18, dropped).
// CTA tile 128x128, K-chunk 64 elems, 8 warps (64x32), 2-stage cp.async.
// Tiles: 128 rows x 64 bf16 = 128B rows, 8 x 16B chunks, XOR swizzle.
#define GT_B   16384
#define GST_B  (4 * GT_B)   // 65536 per stage

__device__ __forceinline__ uint32_t sw(uint32_t b, int row, int ch) {
    return b + (uint32_t)(row * 128) + (uint32_t)((ch ^ (row & 7)) << 4);
}

__device__ __forceinline__ void load_tile4(uint32_t sb,
    const uint16_t* __restrict__ Ah, const uint16_t* __restrict__ Al,
    const uint16_t* __restrict__ Bh, const uint16_t* __restrict__ Bl,
    int m0, int n0, int K, int ic, int t)
{
#pragma unroll
    for (int i = 0; i < 4; i++) {
        int idx = t + 256 * i;
        int row = idx >> 3, ch = idx & 7;
        size_t ao = (size_t)(m0 + row) * K + ic * 64 + ch * 8;
        size_t bo = (size_t)(n0 + row) * K + ic * 64 + ch * 8;
        cp16(sw(sb,            row, ch), Ah + ao);
        cp16(sw(sb + GT_B,     row, ch), Al + ao);
        cp16(sw(sb + 2 * GT_B, row, ch), Bh + bo);
        cp16(sw(sb + 3 * GT_B, row, ch), Bl + bo);
    }
}

template<int MODE>
__global__ void __launch_bounds__(256, 1)
gemm_hmma_kernel(const uint16_t* __restrict__ Ah, const uint16_t* __restrict__ Al,
                 const uint16_t* __restrict__ Bh, const uint16_t* __restrict__ Bl,
                 const float* __restrict__ bias, const float* __restrict__ resid,
                 void* __restrict__ out_a, void* __restrict__ out_b, int N, int K)
{
    extern __shared__ char dsm[];
    uint32_t smem_u32 = (uint32_t)__cvta_generic_to_shared(dsm);
    uint32_t base = (smem_u32 + 127) & ~127u;

    const int t = threadIdx.x;
    const int lane = t & 31, wid = t >> 5;
    const int m0 = blockIdx.y * 128, n0 = blockIdx.x * 128;
    const int warp_m = (wid >> 2) * 64, warp_n = (wid & 3) * 32;

    float acc[4][4][4] = {};
    const int NC = K >> 6;

    load_tile4(base, Ah, Al, Bh, Bl, m0, n0, K, 0, t);
    cp_commit();

    for (int ic = 0; ic < NC; ic++) {
        uint32_t cb = base + (uint32_t)(ic & 1) * GST_B;
        if (ic + 1 < NC) {
            load_tile4(base + (uint32_t)((ic + 1) & 1) * GST_B,
                       Ah, Al, Bh, Bl, m0, n0, K, ic + 1, t);
            cp_commit();
            cp_wait1();
        } else {
            cp_wait0();
        }
        __syncthreads();

        uint32_t Ahb = cb, Alb = cb + GT_B, Bhb = cb + 2 * GT_B, Blb = cb + 3 * GT_B;
#pragma unroll
        for (int kp2 = 0; kp2 < 2; kp2++) {
            uint32_t ah[4][2][4], al[4][2][4];
#pragma unroll
            for (int mt = 0; mt < 4; mt++)
#pragma unroll
                for (int ks = 0; ks < 2; ks++) {
                    int row = warp_m + mt * 16 + (lane & 15);
                    int ch  = kp2 * 4 + ks * 2 + (lane >> 4);
                    ldsm4(ah[mt][ks], sw(Ahb, row, ch));
                    ldsm4(al[mt][ks], sw(Alb, row, ch));
                }
            uint32_t bh[4][4], bl[4][4];
#pragma unroll
            for (int nt = 0; nt < 4; nt++) {
                int row = warp_n + nt * 8 + (lane & 7);
                int ch  = kp2 * 4 + ((lane >> 3) & 3);
                ldsm4(bh[nt], sw(Bhb, row, ch));
                ldsm4(bl[nt], sw(Blb, row, ch));
            }
#pragma unroll
            for (int ks = 0; ks < 2; ks++)
#pragma unroll
                for (int mt = 0; mt < 4; mt++)
#pragma unroll
                    for (int nt = 0; nt < 4; nt++) {
                        mma_bf16(acc[mt][nt], ah[mt][ks], &bh[nt][ks * 2]);
                        mma_bf16(acc[mt][nt], ah[mt][ks], &bl[nt][ks * 2]);
                        mma_bf16(acc[mt][nt], al[mt][ks], &bh[nt][ks * 2]);
                    }
        }
        __syncthreads();
    }

    int rbase = m0 + warp_m + (lane >> 2);
    int cbase = n0 + warp_n + (lane & 3) * 2;
#pragma unroll
    for (int mt = 0; mt < 4; mt++)
#pragma unroll
        for (int nt = 0; nt < 4; nt++)
#pragma unroll
            for (int hh = 0; hh < 2; hh++) {
                int row = rbase + mt * 16 + hh * 8;
                int col = cbase + nt * 8;
                float v0 = acc[mt][nt][hh * 2 + 0] + bias[col];
                float v1 = acc[mt][nt][hh * 2 + 1] + bias[col + 1];
                size_t off = (size_t)row * N + col;
                if (MODE == 1) {
                    v0 = 0.5f * v0 * (1.0f + erff(v0 * 0.70710678118654752f));
                    v1 = 0.5f * v1 * (1.0f + erff(v1 * 0.70710678118654752f));
                    uint16_t h0, l0, h1, l1;
                    split_hl(v0, h0, l0);
                    split_hl(v1, h1, l1);
                    ((uint32_t*)out_a)[off >> 1] = (uint32_t)h0 | ((uint32_t)h1 << 16);
                    ((uint32_t*)out_b)[off >> 1] = (uint32_t)l0 | ((uint32_t)l1 << 16);
                } else {
                    const float2 rr = *(const float2*)(resid + off);
                    float2 ov = { v0 + rr.x, v1 + rr.y };
                    *(float2*)((float*)out_a + off) = ov;
                }
            }
}

// ---------------- launch ----------------
extern "C" void kernel_launch(void* const* d_in, const int* in_sizes, int n_in,
                              void* d_out, int out_size)
{
    const float* x    = (const float*)d_in[0];
    const float* ln1g = (const float*)d_in[1];
    const float* ln1b = (const float*)d_in[2];
    const float* Wq   = (const float*)d_in[3];
    const float* bq   = (const float*)d_in[4];
    const float* Wk   = (const float*)d_in[5];
    const float* bk   = (const float*)d_in[6];
    const float* Wv   = (const float*)d_in[7];
    const float* bv   = (const float*)d_in[8];
    const float* ln2g = (const float*)d_in[9];
    const float* ln2b = (const float*)d_in[10];
    const float* W1   = (const float*)d_in[11];
    const float* b1   = (const float*)d_in[12];
    const float* W2   = (const float*)d_in[13];
    const float* b2   = (const float*)d_in[14];
    float* out = (float*)d_out;

    float *ln, *x1;
    uint32_t *qp, *ksp, *kwp;
    uint16_t *lnh, *lnl, *acth, *actl, *w1h, *w1l, *w2h, *w2l;
    __half* vt;
    cudaGetSymbolAddress((void**)&ln,   g_ln);
    cudaGetSymbolAddress((void**)&lnh,  g_lnh);
    cudaGetSymbolAddress((void**)&lnl,  g_lnl);
    cudaGetSymbolAddress((void**)&qp,   g_qp);
    cudaGetSymbolAddress((void**)&ksp,  g_ks);
    cudaGetSymbolAddress((void**)&kwp,  g_kw);
    cudaGetSymbolAddress((void**)&vt,   g_vt);
    cudaGetSymbolAddress((void**)&x1,   g_x1);
    cudaGetSymbolAddress((void**)&acth, g_acth);
    cudaGetSymbolAddress((void**)&actl, g_actl);
    cudaGetSymbolAddress((void**)&w1h,  g_w1h);
    cudaGetSymbolAddress((void**)&w1l,  g_w1l);
    cudaGetSymbolAddress((void**)&w2h,  g_w2h);
    cudaGetSymbolAddress((void**)&w2l,  g_w2l);

    const int ATTN_SMEM = 32768 + 2 * AT_BUF;   // 114688
    cudaFuncSetAttribute((const void*)attn_mma_kernel,
                         cudaFuncAttributeMaxDynamicSharedMemorySize, ATTN_SMEM);
    const int GEMM_SMEM = 2 * GST_B + 256;      // 131328
    cudaFuncSetAttribute(gemm_hmma_kernel<1>,
                         cudaFuncAttributeMaxDynamicSharedMemorySize, GEMM_SMEM);
    cudaFuncSetAttribute(gemm_hmma_kernel<2>,
                         cudaFuncAttributeMaxDynamicSharedMemorySize, GEMM_SMEM);

    convert_w_kernel<<<(DMLP * DMODEL + 255) / 256, 256>>>(W1, w1h, w1l, DMLP * DMODEL);
    convert_w_kernel<<<(DMODEL * DMLP + 255) / 256, 256>>>(W2, w2h, w2l, DMODEL * DMLP);

    // 1) LN1
    ln_kernel<<<TOKENS, 256>>>(x, ln1g, ln1b, ln);
    // 2) QKV -> packed q/k + V^T f16
    qkv_kernel<<<dim3(TOKENS / 64, NHEAD), 256>>>(ln, Wq, bq, Wk, bk, Wv, bv, qp, ksp, kwp, vt);
    // 3) HMMA attention + residual -> x1
    attn_mma_kernel<<<dim3(SEQ / 128, NHEAD, BATCH), 256, ATTN_SMEM>>>(qp, ksp, kwp, vt, x, x1);
    // 4) LN2 -> hi/lo planes
    ln_split_kernel<<<TOKENS, 256>>>(x1, ln2g, ln2b, lnh, lnl);
    // 5) MLP up + GELU -> act hi/lo planes
    gemm_hmma_kernel<1><<<dim3(DMLP / 128, TOKENS / 128), 256, GEMM_SMEM>>>(
        lnh, lnl, w1h, w1l, b1, nullptr, (void*)acth, (void*)actl, DMLP, DMODEL);
    // 6) MLP down + bias + residual -> out
    gemm_hmma_kernel<2><<<dim3(DMODEL / 128, TOKENS / 128), 256, GEMM_SMEM>>>(
        acth, actl, w2h, w2l, b2, x1, (void*)out, nullptr, DMODEL, DMLP);
}

// round 7
// speedup vs baseline: 3.6334x; 1.0071x over previous
#include <cuda_runtime.h>
#include <cuda_bf16.h>
#include <cuda_fp16.h>
#include <math.h>
#include <stdint.h>

#define TOKENS 16384
#define DMODEL 768
#define NHEAD  12
#define HDIM   64
#define DMLP   3072
#define SEQ    1024
#define BATCH  16

// ---------------- scratch (device globals; no cudaMalloc allowed) ----------------
__device__ float    g_ln  [TOKENS * DMODEL];      // LN1 out fp32 (for qkv)
__device__ uint16_t g_lnh [TOKENS * DMODEL];      // LN2 out bf16 hi plane
__device__ uint16_t g_lnl [TOKENS * DMODEL];      // LN2 out bf16 lo plane
__device__ uint32_t g_qp  [TOKENS * DMODEL];      // q packed (hi,lo), pre-scaled by 0.125 [tok][h*64+o]
__device__ uint32_t g_ks  [TOKENS * DMODEL];      // k packed (hi,lo)
__device__ uint32_t g_kw  [TOKENS * DMODEL];      // k packed (lo,hi)
__device__ __half   g_vt  [TOKENS * DMODEL];      // V^T f16: [(b*12+h)*64+d][1024]
__device__ float    g_x1  [TOKENS * DMODEL];      // x + attn
__device__ uint16_t g_acth[TOKENS * DMLP];        // GELU out bf16 hi plane
__device__ uint16_t g_actl[TOKENS * DMLP];        // GELU out bf16 lo plane
__device__ uint16_t g_w1h [DMLP * DMODEL];
__device__ uint16_t g_w1l [DMLP * DMODEL];
__device__ uint16_t g_w2h [DMODEL * DMLP];
__device__ uint16_t g_w2l [DMODEL * DMLP];

// ---------------- PTX helpers (portable sm_80-class only) ----------------
__device__ __forceinline__ void cp16(uint32_t s, const void* g) {
    asm volatile("cp.async.cg.shared.global [%0], [%1], 16;" :: "r"(s), "l"(g));
}
__device__ __forceinline__ void cp_commit() { asm volatile("cp.async.commit_group;" ::: "memory"); }
__device__ __forceinline__ void cp_wait1()  { asm volatile("cp.async.wait_group 1;" ::: "memory"); }
__device__ __forceinline__ void cp_wait0()  { asm volatile("cp.async.wait_group 0;" ::: "memory"); }

__device__ __forceinline__ void ldsm4(uint32_t* r, uint32_t addr) {
    asm volatile("ldmatrix.sync.aligned.m8n8.x4.shared.b16 {%0,%1,%2,%3}, [%4];"
                 : "=r"(r[0]), "=r"(r[1]), "=r"(r[2]), "=r"(r[3]) : "r"(addr));
}
// NOTE: non-volatile — pure register dataflow; lets ptxas software-pipeline MMAs.
__device__ __forceinline__ void mma_bf16(float* d, const uint32_t* a, const uint32_t* b) {
    asm("mma.sync.aligned.m16n8k16.row.col.f32.bf16.bf16.f32 "
        "{%0,%1,%2,%3}, {%4,%5,%6,%7}, {%8,%9}, {%0,%1,%2,%3};"
        : "+f"(d[0]), "+f"(d[1]), "+f"(d[2]), "+f"(d[3])
        : "r"(a[0]), "r"(a[1]), "r"(a[2]), "r"(a[3]), "r"(b[0]), "r"(b[1]));
}
__device__ __forceinline__ void mma_f16(float* d, const uint32_t* a, const uint32_t* b) {
    asm("mma.sync.aligned.m16n8k16.row.col.f32.f16.f16.f32 "
        "{%0,%1,%2,%3}, {%4,%5,%6,%7}, {%8,%9}, {%0,%1,%2,%3};"
        : "+f"(d[0]), "+f"(d[1]), "+f"(d[2]), "+f"(d[3])
        : "r"(a[0]), "r"(a[1]), "r"(a[2]), "r"(a[3]), "r"(b[0]), "r"(b[1]));
}
__device__ __forceinline__ uint32_t f16x2(float hi, float lo) {
    uint32_t u;
    asm("cvt.rn.f16x2.f32 %0, %1, %2;" : "=r"(u) : "f"(hi), "f"(lo));
    return u;
}

// bf16 split helpers
__device__ __forceinline__ uint32_t pack_split(float x) {
    __nv_bfloat16 h = __float2bfloat16(x);
    float hf = __bfloat162float(h);
    __nv_bfloat16 l = __float2bfloat16(x - hf);
    uint32_t hu = (uint32_t)__bfloat16_as_ushort(h);
    uint32_t lu = (uint32_t)__bfloat16_as_ushort(l);
    return hu | (lu << 16);
}
__device__ __forceinline__ void pack_split2(float x, uint32_t& s, uint32_t& w) {
    __nv_bfloat16 h = __float2bfloat16(x);
    float hf = __bfloat162float(h);
    __nv_bfloat16 l = __float2bfloat16(x - hf);
    uint32_t hu = (uint32_t)__bfloat16_as_ushort(h);
    uint32_t lu = (uint32_t)__bfloat16_as_ushort(l);
    s = hu | (lu << 16);
    w = lu | (hu << 16);
}
__device__ __forceinline__ void split_hl(float x, uint16_t& h, uint16_t& l) {
    __nv_bfloat16 hb = __float2bfloat16(x);
    float hf = __bfloat162float(hb);
    __nv_bfloat16 lb = __float2bfloat16(x - hf);
    h = __bfloat16_as_ushort(hb);
    l = __bfloat16_as_ushort(lb);
}

// ---------------- LayerNorm (fp32 out) ----------------
__global__ void ln_kernel(const float* __restrict__ x, const float* __restrict__ g,
                          const float* __restrict__ b, float* __restrict__ out)
{
    int tok = blockIdx.x;
    int t = threadIdx.x;
    const float* xr = x + (size_t)tok * DMODEL;
    float v0 = xr[t], v1 = xr[t + 256], v2 = xr[t + 512];
    float s = v0 + v1 + v2;
    __shared__ float red[8];
#pragma unroll
    for (int o = 16; o > 0; o >>= 1) s += __shfl_xor_sync(0xffffffffu, s, o);
    if ((t & 31) == 0) red[t >> 5] = s;
    __syncthreads();
    float tot = 0.f;
#pragma unroll
    for (int i = 0; i < 8; i++) tot += red[i];
    float mu = tot * (1.0f / DMODEL);
    float d0 = v0 - mu, d1 = v1 - mu, d2 = v2 - mu;
    float sq = d0 * d0 + d1 * d1 + d2 * d2;
#pragma unroll
    for (int o = 16; o > 0; o >>= 1) sq += __shfl_xor_sync(0xffffffffu, sq, o);
    __syncthreads();
    if ((t & 31) == 0) red[t >> 5] = sq;
    __syncthreads();
    float vs = 0.f;
#pragma unroll
    for (int i = 0; i < 8; i++) vs += red[i];
    float rs = rsqrtf(vs * (1.0f / DMODEL) + 1e-5f);
    float* orow = out + (size_t)tok * DMODEL;
    orow[t]       = d0 * rs * g[t]       + b[t];
    orow[t + 256] = d1 * rs * g[t + 256] + b[t + 256];
    orow[t + 512] = d2 * rs * g[t + 512] + b[t + 512];
}

// ---------------- LayerNorm (split hi/lo bf16 planes out) ----------------
__global__ void ln_split_kernel(const float* __restrict__ x, const float* __restrict__ g,
                                const float* __restrict__ b,
                                uint16_t* __restrict__ oh, uint16_t* __restrict__ ol)
{
    int tok = blockIdx.x;
    int t = threadIdx.x;
    const float* xr = x + (size_t)tok * DMODEL;
    float v0 = xr[t], v1 = xr[t + 256], v2 = xr[t + 512];
    float s = v0 + v1 + v2;
    __shared__ float red[8];
#pragma unroll
    for (int o = 16; o > 0; o >>= 1) s += __shfl_xor_sync(0xffffffffu, s, o);
    if ((t & 31) == 0) red[t >> 5] = s;
    __syncthreads();
    float tot = 0.f;
#pragma unroll
    for (int i = 0; i < 8; i++) tot += red[i];
    float mu = tot * (1.0f / DMODEL);
    float d0 = v0 - mu, d1 = v1 - mu, d2 = v2 - mu;
    float sq = d0 * d0 + d1 * d1 + d2 * d2;
#pragma unroll
    for (int o = 16; o > 0; o >>= 1) sq += __shfl_xor_sync(0xffffffffu, sq, o);
    __syncthreads();
    if ((t & 31) == 0) red[t >> 5] = sq;
    __syncthreads();
    float vs = 0.f;
#pragma unroll
    for (int i = 0; i < 8; i++) vs += red[i];
    float rs = rsqrtf(vs * (1.0f / DMODEL) + 1e-5f);
    size_t base = (size_t)tok * DMODEL;
    float vals[3] = { d0 * rs * g[t] + b[t],
                      d1 * rs * g[t + 256] + b[t + 256],
                      d2 * rs * g[t + 512] + b[t + 512] };
#pragma unroll
    for (int i = 0; i < 3; i++) {
        uint16_t h, l;
        split_hl(vals[i], h, l);
        oh[base + t + 256 * i] = h;
        ol[base + t + 256 * i] = l;
    }
}

// ---------------- weight conversion: fp32 -> hi/lo bf16 planes ----------------
__global__ void convert_w_kernel(const float* __restrict__ W,
                                 uint16_t* __restrict__ wh, uint16_t* __restrict__ wl, int n)
{
    int i = blockIdx.x * 256 + threadIdx.x;
    if (i < n) {
        uint16_t h, l;
        split_hl(W[i], h, l);
        wh[i] = h;
        wl[i] = l;
    }
}

// ---------------- Block-diagonal per-head QKV -> packed q/k + V^T f16 ----------------
__global__ void __launch_bounds__(256) qkv_kernel(
    const float* __restrict__ ln,
    const float* __restrict__ Wq, const float* __restrict__ bq,
    const float* __restrict__ Wk, const float* __restrict__ bk,
    const float* __restrict__ Wv, const float* __restrict__ bv,
    uint32_t* __restrict__ qp, uint32_t* __restrict__ ksp,
    uint32_t* __restrict__ kwp, __half* __restrict__ vt)
{
    __shared__ float Xs[64 * 65];
    __shared__ float Ws[64 * 65];
    int hh = blockIdx.y;
    int t0 = blockIdx.x * 64;
    int t  = threadIdx.x;
    int tx = t & 15, ty = t >> 4;

#pragma unroll
    for (int it = 0; it < 4; it++) {
        int idx = it * 1024 + t * 4;
        int r = idx >> 6, c = idx & 63;
        float4 x4 = *(const float4*)(ln + (size_t)(t0 + r) * DMODEL + hh * HDIM + c);
        Xs[(c + 0) * 65 + r] = x4.x;
        Xs[(c + 1) * 65 + r] = x4.y;
        Xs[(c + 2) * 65 + r] = x4.z;
        Xs[(c + 3) * 65 + r] = x4.w;
    }

    const float* Wm[3] = { Wq + hh * 4096, Wk + hh * 4096, Wv + hh * 4096 };
    const float* bm[3] = { bq + hh * 64,  bk + hh * 64,  bv + hh * 64 };

    for (int m = 0; m < 3; m++) {
        __syncthreads();
#pragma unroll
        for (int it = 0; it < 4; it++) {
            int idx = it * 1024 + t * 4;
            int r = idx >> 6, c = idx & 63;
            float4 w4 = *(const float4*)(Wm[m] + r * 64 + c);
            Ws[(c + 0) * 65 + r] = w4.x;
            Ws[(c + 1) * 65 + r] = w4.y;
            Ws[(c + 2) * 65 + r] = w4.z;
            Ws[(c + 3) * 65 + r] = w4.w;
        }
        __syncthreads();

        float acc[4][4] = {};
#pragma unroll
        for (int d = 0; d < 64; d++) {
            float xa[4], wb[4];
#pragma unroll
            for (int i = 0; i < 4; i++) xa[i] = Xs[d * 65 + ty * 4 + i];
#pragma unroll
            for (int j = 0; j < 4; j++) wb[j] = Ws[d * 65 + tx + 16 * j];
#pragma unroll
            for (int i = 0; i < 4; i++)
#pragma unroll
                for (int j = 0; j < 4; j++) acc[i][j] += xa[i] * wb[j];
        }
#pragma unroll
        for (int i = 0; i < 4; i++) {
            int tok = t0 + ty * 4 + i;
#pragma unroll
            for (int j = 0; j < 4; j++) {
                int o = tx + 16 * j;
                float val = acc[i][j] + bm[m][o];
                size_t off = (size_t)tok * DMODEL + hh * HDIM + o;   // [tok][h*64+o]
                if (m == 0) {
                    qp[off] = pack_split(0.125f * val);
                } else if (m == 1) {
                    uint32_t s, w;
                    pack_split2(val, s, w);
                    ksp[off] = s;
                    kwp[off] = w;
                } else {
                    int bb = tok >> 10, pos = tok & 1023;
                    vt[((size_t)((bb * 12 + hh) * 64 + o)) * 1024 + pos] = __float2half(val);
                }
            }
        }
    }
}

// ---------------- HMMA flash attention + residual ----------------
#define AT_BUF 40960

__global__ void __launch_bounds__(256, 1) attn_mma_kernel(
    const uint32_t* __restrict__ qp, const uint32_t* __restrict__ ksp,
    const uint32_t* __restrict__ kwp, const __half* __restrict__ vt,
    const float* __restrict__ x, float* __restrict__ out)
{
    extern __shared__ char dsm[];
    uint32_t sb = (uint32_t)__cvta_generic_to_shared(dsm);

    const int b = blockIdx.z, hh = blockIdx.y;
    const int q0 = blockIdx.x * 128;
    const int t = threadIdx.x, lane = t & 31, w = t >> 5;
    const int wq = w * 16;
    const int bh = b * 12 + hh;
    const int ho = hh * HDIM;
    const size_t tok0 = (size_t)b * 1024 + q0;

    const uint32_t Qb = sb;
    const uint32_t Bb = sb + 32768;

#pragma unroll
    for (int i = 0; i < 8; i++) {
        int idx = t + 256 * i;
        int r = idx >> 4, c = idx & 15;
        cp16(Qb + r * 256 + (uint32_t)((c ^ (r & 7)) << 4),
             qp + (tok0 + r) * DMODEL + ho + c * 4);
    }
    {
        int kg0 = b * 1024;
#pragma unroll
        for (int i = 0; i < 4; i++) {
            int idx = t + 256 * i;
            int r = idx >> 4, c = idx & 15;
            uint32_t so = (uint32_t)(r * 256 + ((c ^ (r & 7)) << 4));
            cp16(Bb + so,         ksp + (size_t)(kg0 + r) * DMODEL + ho + c * 4);
            cp16(Bb + 16384 + so, kwp + (size_t)(kg0 + r) * DMODEL + ho + c * 4);
        }
#pragma unroll
        for (int i = 0; i < 2; i++) {
            int idx = t + 256 * i;
            int r = idx >> 3, c = idx & 7;
            cp16(Bb + 32768 + (uint32_t)(r * 128 + ((c ^ (r & 7)) << 4)),
                 vt + ((size_t)(bh * 64 + r)) * 1024 + c * 8);
        }
    }
    cp_commit();

    float oacc[8][4] = {};
    float rs0 = 0.f, rs1 = 0.f;
    uint32_t af[8][4];

    for (int kt = 0; kt < 16; kt++) {
        if (kt + 1 < 16) {
            uint32_t nb = Bb + (uint32_t)((kt + 1) & 1) * AT_BUF;
            int kg = b * 1024 + (kt + 1) * 64;
#pragma unroll
            for (int i = 0; i < 4; i++) {
                int idx = t + 256 * i;
                int r = idx >> 4, c = idx & 15;
                uint32_t so = (uint32_t)(r * 256 + ((c ^ (r & 7)) << 4));
                cp16(nb + so,         ksp + (size_t)(kg + r) * DMODEL + ho + c * 4);
                cp16(nb + 16384 + so, kwp + (size_t)(kg + r) * DMODEL + ho + c * 4);
            }
#pragma unroll
            for (int i = 0; i < 2; i++) {
                int idx = t + 256 * i;
                int r = idx >> 3, c = idx & 7;
                cp16(nb + 32768 + (uint32_t)(r * 128 + ((c ^ (r & 7)) << 4)),
                     vt + ((size_t)(bh * 64 + r)) * 1024 + (kt + 1) * 64 + c * 8);
            }
            cp_commit();
            cp_wait1();
        } else {
            cp_wait0();
        }
        __syncthreads();

        uint32_t cb = Bb + (uint32_t)(kt & 1) * AT_BUF;

        if (kt == 0) {
#pragma unroll
            for (int ks = 0; ks < 8; ks++) {
                int r = wq + (lane & 15);
                int c = 2 * ks + (lane >> 4);
                ldsm4(af[ks], Qb + r * 256 + (uint32_t)((c ^ (r & 7)) << 4));
            }
        }

        float sacc[8][4] = {};
#pragma unroll
        for (int pass = 0; pass < 2; pass++) {
            uint32_t kb = cb + (uint32_t)pass * 16384;
#pragma unroll
            for (int kp = 0; kp < 4; kp++) {
                uint32_t bf[8][4];
#pragma unroll
                for (int j = 0; j < 8; j++) {
                    int r = j * 8 + (lane & 7);
                    int c = kp * 4 + ((lane >> 3) & 3);
                    ldsm4(bf[j], kb + r * 256 + (uint32_t)((c ^ (r & 7)) << 4));
                }
#pragma unroll
                for (int s = 0; s < 2; s++)
#pragma unroll
                    for (int j = 0; j < 8; j++)
                        mma_bf16(sacc[j], af[kp * 2 + s], &bf[j][s * 2]);
            }
        }

        uint32_t pa[4][4];
#pragma unroll
        for (int j = 0; j < 8; j++) {
            float e0 = __expf(sacc[j][0]);
            float e1 = __expf(sacc[j][1]);
            float e2 = __expf(sacc[j][2]);
            float e3 = __expf(sacc[j][3]);
            rs0 += e0 + e1;
            rs1 += e2 + e3;
            pa[j >> 1][(j & 1) * 2 + 0] = f16x2(e1, e0);
            pa[j >> 1][(j & 1) * 2 + 1] = f16x2(e3, e2);
        }

        uint32_t vb0 = cb + 32768;
#pragma unroll
        for (int kp = 0; kp < 2; kp++) {
            uint32_t vb[8][4];
#pragma unroll
            for (int j = 0; j < 8; j++) {
                int r = j * 8 + (lane & 7);
                int c = kp * 4 + ((lane >> 3) & 3);
                ldsm4(vb[j], vb0 + r * 128 + (uint32_t)((c ^ (r & 7)) << 4));
            }
#pragma unroll
            for (int s = 0; s < 2; s++)
#pragma unroll
                for (int j = 0; j < 8; j++)
                    mma_f16(oacc[j], pa[kp * 2 + s], &vb[j][s * 2]);
        }
        __syncthreads();
    }

    rs0 += __shfl_xor_sync(0xffffffffu, rs0, 1);
    rs0 += __shfl_xor_sync(0xffffffffu, rs0, 2);
    rs1 += __shfl_xor_sync(0xffffffffu, rs1, 1);
    rs1 += __shfl_xor_sync(0xffffffffu, rs1, 2);
    float inv0 = 1.0f / rs0, inv1 = 1.0f / rs1;

    size_t row0 = tok0 + wq + (lane >> 2);
    size_t row1 = row0 + 8;
#pragma unroll
    for (int j = 0; j < 8; j++) {
        int col = ho + j * 8 + 2 * (lane & 3);
        size_t o0 = row0 * DMODEL + col;
        size_t o1 = row1 * DMODEL + col;
        float2 x0 = *(const float2*)(x + o0);
        float2 x1v = *(const float2*)(x + o1);
        float2 r0 = { oacc[j][0] * inv0 + x0.x,  oacc[j][1] * inv0 + x0.y };
        float2 r1 = { oacc[j][2] * inv1 + x1v.x, oacc[j][3] * inv1 + x1v.y };
        *(float2*)(out + o0) = r0;
        *(float2*)(out + o1) = r1;
    }
}

// ---------------- HMMA 3-term split-bf16 GEMM (term-major MMA ordering) ----------------
#define GT_B   16384
#define GST_B  (4 * GT_B)   // 65536 per stage

__device__ __forceinline__ uint32_t sw(uint32_t b, int row, int ch) {
    return b + (uint32_t)(row * 128) + (uint32_t)((ch ^ (row & 7)) << 4);
}

__device__ __forceinline__ void load_tile4(uint32_t sb,
    const uint16_t* __restrict__ Ah, const uint16_t* __restrict__ Al,
    const uint16_t* __restrict__ Bh, const uint16_t* __restrict__ Bl,
    int m0, int n0, int K, int ic, int t)
{
#pragma unroll
    for (int i = 0; i < 4; i++) {
        int idx = t + 256 * i;
        int row = idx >> 3, ch = idx & 7;
        size_t ao = (size_t)(m0 + row) * K + ic * 64 + ch * 8;
        size_t bo = (size_t)(n0 + row) * K + ic * 64 + ch * 8;
        cp16(sw(sb,            row, ch), Ah + ao);
        cp16(sw(sb + GT_B,     row, ch), Al + ao);
        cp16(sw(sb + 2 * GT_B, row, ch), Bh + bo);
        cp16(sw(sb + 3 * GT_B, row, ch), Bl + bo);
    }
}

template<int MODE>
__global__ void __launch_bounds__(256, 1)
gemm_hmma_kernel(const uint16_t* __restrict__ Ah, const uint16_t* __restrict__ Al,
                 const uint16_t* __restrict__ Bh, const uint16_t* __restrict__ Bl,
                 const float* __restrict__ bias, const float* __restrict__ resid,
                 void* __restrict__ out_a, void* __restrict__ out_b, int N, int K)
{
    extern __shared__ char dsm[];
    uint32_t smem_u32 = (uint32_t)__cvta_generic_to_shared(dsm);
    uint32_t base = (smem_u32 + 127) & ~127u;

    const int t = threadIdx.x;
    const int lane = t & 31, wid = t >> 5;
    const int m0 = blockIdx.y * 128, n0 = blockIdx.x * 128;
    const int warp_m = (wid >> 2) * 64, warp_n = (wid & 3) * 32;

    float acc[4][4][4] = {};
    const int NC = K >> 6;

    load_tile4(base, Ah, Al, Bh, Bl, m0, n0, K, 0, t);
    cp_commit();

    for (int ic = 0; ic < NC; ic++) {
        uint32_t cb = base + (uint32_t)(ic & 1) * GST_B;
        if (ic + 1 < NC) {
            load_tile4(base + (uint32_t)((ic + 1) & 1) * GST_B,
                       Ah, Al, Bh, Bl, m0, n0, K, ic + 1, t);
            cp_commit();
            cp_wait1();
        } else {
            cp_wait0();
        }
        __syncthreads();

        uint32_t Ahb = cb, Alb = cb + GT_B, Bhb = cb + 2 * GT_B, Blb = cb + 3 * GT_B;
#pragma unroll
        for (int kp2 = 0; kp2 < 2; kp2++) {
            uint32_t ah[4][2][4], al[4][2][4];
#pragma unroll
            for (int mt = 0; mt < 4; mt++)
#pragma unroll
                for (int ks = 0; ks < 2; ks++) {
                    int row = warp_m + mt * 16 + (lane & 15);
                    int ch  = kp2 * 4 + ks * 2 + (lane >> 4);
                    ldsm4(ah[mt][ks], sw(Ahb, row, ch));
                    ldsm4(al[mt][ks], sw(Alb, row, ch));
                }
            uint32_t bh[4][4], bl[4][4];
#pragma unroll
            for (int nt = 0; nt < 4; nt++) {
                int row = warp_n + nt * 8 + (lane & 7);
                int ch  = kp2 * 4 + ((lane >> 3) & 3);
                ldsm4(bh[nt], sw(Bhb, row, ch));
                ldsm4(bl[nt], sw(Blb, row, ch));
            }
            // term-major: 16 independent accumulators between reuses of any acc
#pragma unroll
            for (int ks = 0; ks < 2; ks++) {
#pragma unroll
                for (int mt = 0; mt < 4; mt++)
#pragma unroll
                    for (int nt = 0; nt < 4; nt++)
                        mma_bf16(acc[mt][nt], ah[mt][ks], &bh[nt][ks * 2]);
#pragma unroll
                for (int mt = 0; mt < 4; mt++)
#pragma unroll
                    for (int nt = 0; nt < 4; nt++)
                        mma_bf16(acc[mt][nt], ah[mt][ks], &bl[nt][ks * 2]);
#pragma unroll
                for (int mt = 0; mt < 4; mt++)
#pragma unroll
                    for (int nt = 0; nt < 4; nt++)
                        mma_bf16(acc[mt][nt], al[mt][ks], &bh[nt][ks * 2]);
            }
        }
        __syncthreads();
    }

    int rbase = m0 + warp_m + (lane >> 2);
    int cbase = n0 + warp_n + (lane & 3) * 2;
#pragma unroll
    for (int mt = 0; mt < 4; mt++)
#pragma unroll
        for (int nt = 0; nt < 4; nt++)
#pragma unroll
            for (int hh = 0; hh < 2; hh++) {
                int row = rbase + mt * 16 + hh * 8;
                int col = cbase + nt * 8;
                float v0 = acc[mt][nt][hh * 2 + 0] + bias[col];
                float v1 = acc[mt][nt][hh * 2 + 1] + bias[col + 1];
                size_t off = (size_t)row * N + col;
                if (MODE == 1) {
                    v0 = 0.5f * v0 * (1.0f + erff(v0 * 0.70710678118654752f));
                    v1 = 0.5f * v1 * (1.0f + erff(v1 * 0.70710678118654752f));
                    uint16_t h0, l0, h1, l1;
                    split_hl(v0, h0, l0);
                    split_hl(v1, h1, l1);
                    ((uint32_t*)out_a)[off >> 1] = (uint32_t)h0 | ((uint32_t)h1 << 16);
                    ((uint32_t*)out_b)[off >> 1] = (uint32_t)l0 | ((uint32_t)l1 << 16);
                } else {
                    const float2 rr = *(const float2*)(resid + off);
                    float2 ov = { v0 + rr.x, v1 + rr.y };
                    *(float2*)((float*)out_a + off) = ov;
                }
            }
}

// ---------------- launch ----------------
extern "C" void kernel_launch(void* const* d_in, const int* in_sizes, int n_in,
                              void* d_out, int out_size)
{
    const float* x    = (const float*)d_in[0];
    const float* ln1g = (const float*)d_in[1];
    const float* ln1b = (const float*)d_in[2];
    const float* Wq   = (const float*)d_in[3];
    const float* bq   = (const float*)d_in[4];
    const float* Wk   = (const float*)d_in[5];
    const float* bk   = (const float*)d_in[6];
    const float* Wv   = (const float*)d_in[7];
    const float* bv   = (const float*)d_in[8];
    const float* ln2g = (const float*)d_in[9];
    const float* ln2b = (const float*)d_in[10];
    const float* W1   = (const float*)d_in[11];
    const float* b1   = (const float*)d_in[12];
    const float* W2   = (const float*)d_in[13];
    const float* b2   = (const float*)d_in[14];
    float* out = (float*)d_out;

    float *ln, *x1;
    uint32_t *qp, *ksp, *kwp;
    uint16_t *lnh, *lnl, *acth, *actl, *w1h, *w1l, *w2h, *w2l;
    __half* vt;
    cudaGetSymbolAddress((void**)&ln,   g_ln);
    cudaGetSymbolAddress((void**)&lnh,  g_lnh);
    cudaGetSymbolAddress((void**)&lnl,  g_lnl);
    cudaGetSymbolAddress((void**)&qp,   g_qp);
    cudaGetSymbolAddress((void**)&ksp,  g_ks);
    cudaGetSymbolAddress((void**)&kwp,  g_kw);
    cudaGetSymbolAddress((void**)&vt,   g_vt);
    cudaGetSymbolAddress((void**)&x1,   g_x1);
    cudaGetSymbolAddress((void**)&acth, g_acth);
    cudaGetSymbolAddress((void**)&actl, g_actl);
    cudaGetSymbolAddress((void**)&w1h,  g_w1h);
    cudaGetSymbolAddress((void**)&w1l,  g_w1l);
    cudaGetSymbolAddress((void**)&w2h,  g_w2h);
    cudaGetSymbolAddress((void**)&w2l,  g_w2l);

    const int ATTN_SMEM = 32768 + 2 * AT_BUF;   // 114688
    cudaFuncSetAttribute((const void*)attn_mma_kernel,
                         cudaFuncAttributeMaxDynamicSharedMemorySize, ATTN_SMEM);
    const int GEMM_SMEM = 2 * GST_B + 256;      // 131328
    cudaFuncSetAttribute(gemm_hmma_kernel<1>,
                         cudaFuncAttributeMaxDynamicSharedMemorySize, GEMM_SMEM);
    cudaFuncSetAttribute(gemm_hmma_kernel<2>,
                         cudaFuncAttributeMaxDynamicSharedMemorySize, GEMM_SMEM);

    convert_w_kernel<<<(DMLP * DMODEL + 255) / 256, 256>>>(W1, w1h, w1l, DMLP * DMODEL);
    convert_w_kernel<<<(DMODEL * DMLP + 255) / 256, 256>>>(W2, w2h, w2l, DMODEL * DMLP);

    // 1) LN1
    ln_kernel<<<TOKENS, 256>>>(x, ln1g, ln1b, ln);
    // 2) QKV -> packed q/k + V^T f16
    qkv_kernel<<<dim3(TOKENS / 64, NHEAD), 256>>>(ln, Wq, bq, Wk, bk, Wv, bv, qp, ksp, kwp, vt);
    // 3) HMMA attention + residual -> x1
    attn_mma_kernel<<<dim3(SEQ / 128, NHEAD, BATCH), 256, ATTN_SMEM>>>(qp, ksp, kwp, vt, x, x1);
    // 4) LN2 -> hi/lo planes
    ln_split_kernel<<<TOKENS, 256>>>(x1, ln2g, ln2b, lnh, lnl);
    // 5) MLP up + GELU -> act hi/lo planes
    gemm_hmma_kernel<1><<<dim3(DMLP / 128, TOKENS / 128), 256, GEMM_SMEM>>>(
        lnh, lnl, w1h, w1l, b1, nullptr, (void*)acth, (void*)actl, DMLP, DMODEL);
    // 6) MLP down + bias + residual -> out
    gemm_hmma_kernel<2><<<dim3(DMODEL / 128, TOKENS / 128), 256, GEMM_SMEM>>>(
        acth, actl, w2h, w2l, b2, x1, (void*)out, nullptr, DMODEL, DMLP);
}

// round 8
// speedup vs baseline: 3.7006x; 1.0185x over previous
#include <cuda_runtime.h>
#include <cuda_bf16.h>
#include <cuda_fp16.h>
#include <math.h>
#include <stdint.h>

#define TOKENS 16384
#define DMODEL 768
#define NHEAD  12
#define HDIM   64
#define DMLP   3072
#define SEQ    1024
#define BATCH  16

// ---------------- scratch (device globals; no cudaMalloc allowed) ----------------
__device__ float    g_ln  [TOKENS * DMODEL];      // LN1 out fp32 (for qkv)
__device__ uint16_t g_lnh [TOKENS * DMODEL];      // LN2 out bf16 hi plane
__device__ uint16_t g_lnl [TOKENS * DMODEL];      // LN2 out bf16 lo plane
__device__ uint32_t g_qp  [TOKENS * DMODEL];      // q packed (hi,lo), pre-scaled by 0.125 [tok][h*64+o]
__device__ uint32_t g_ks  [TOKENS * DMODEL];      // k packed (hi,lo)
__device__ uint32_t g_kw  [TOKENS * DMODEL];      // k packed (lo,hi)
__device__ __half   g_vt  [TOKENS * DMODEL];      // V^T f16: [(b*12+h)*64+d][1024]
__device__ float    g_x1  [TOKENS * DMODEL];      // x + attn
__device__ uint16_t g_acth[TOKENS * DMLP];        // GELU out bf16 hi plane
__device__ uint16_t g_actl[TOKENS * DMLP];        // GELU out bf16 lo plane
__device__ uint16_t g_w1h [DMLP * DMODEL];
__device__ uint16_t g_w1l [DMLP * DMODEL];
__device__ uint16_t g_w2h [DMODEL * DMLP];
__device__ uint16_t g_w2l [DMODEL * DMLP];

// ---------------- PTX helpers (portable sm_80-class only) ----------------
__device__ __forceinline__ void cp16(uint32_t s, const void* g) {
    asm volatile("cp.async.cg.shared.global [%0], [%1], 16;" :: "r"(s), "l"(g));
}
__device__ __forceinline__ void cp_commit() { asm volatile("cp.async.commit_group;" ::: "memory"); }
__device__ __forceinline__ void cp_wait1()  { asm volatile("cp.async.wait_group 1;" ::: "memory"); }
__device__ __forceinline__ void cp_wait0()  { asm volatile("cp.async.wait_group 0;" ::: "memory"); }

__device__ __forceinline__ void ldsm4(uint32_t* r, uint32_t addr) {
    asm volatile("ldmatrix.sync.aligned.m8n8.x4.shared.b16 {%0,%1,%2,%3}, [%4];"
                 : "=r"(r[0]), "=r"(r[1]), "=r"(r[2]), "=r"(r[3]) : "r"(addr));
}
__device__ __forceinline__ void mma_bf16(float* d, const uint32_t* a, const uint32_t* b) {
    asm("mma.sync.aligned.m16n8k16.row.col.f32.bf16.bf16.f32 "
        "{%0,%1,%2,%3}, {%4,%5,%6,%7}, {%8,%9}, {%0,%1,%2,%3};"
        : "+f"(d[0]), "+f"(d[1]), "+f"(d[2]), "+f"(d[3])
        : "r"(a[0]), "r"(a[1]), "r"(a[2]), "r"(a[3]), "r"(b[0]), "r"(b[1]));
}
__device__ __forceinline__ void mma_f16(float* d, const uint32_t* a, const uint32_t* b) {
    asm("mma.sync.aligned.m16n8k16.row.col.f32.f16.f16.f32 "
        "{%0,%1,%2,%3}, {%4,%5,%6,%7}, {%8,%9}, {%0,%1,%2,%3};"
        : "+f"(d[0]), "+f"(d[1]), "+f"(d[2]), "+f"(d[3])
        : "r"(a[0]), "r"(a[1]), "r"(a[2]), "r"(a[3]), "r"(b[0]), "r"(b[1]));
}
__device__ __forceinline__ uint32_t f16x2(float hi, float lo) {
    uint32_t u;
    asm("cvt.rn.f16x2.f32 %0, %1, %2;" : "=r"(u) : "f"(hi), "f"(lo));
    return u;
}

// bf16 split helpers
__device__ __forceinline__ uint32_t pack_split(float x) {
    __nv_bfloat16 h = __float2bfloat16(x);
    float hf = __bfloat162float(h);
    __nv_bfloat16 l = __float2bfloat16(x - hf);
    uint32_t hu = (uint32_t)__bfloat16_as_ushort(h);
    uint32_t lu = (uint32_t)__bfloat16_as_ushort(l);
    return hu | (lu << 16);
}
__device__ __forceinline__ void pack_split2(float x, uint32_t& s, uint32_t& w) {
    __nv_bfloat16 h = __float2bfloat16(x);
    float hf = __bfloat162float(h);
    __nv_bfloat16 l = __float2bfloat16(x - hf);
    uint32_t hu = (uint32_t)__bfloat16_as_ushort(h);
    uint32_t lu = (uint32_t)__bfloat16_as_ushort(l);
    s = hu | (lu << 16);
    w = lu | (hu << 16);
}
__device__ __forceinline__ void split_hl(float x, uint16_t& h, uint16_t& l) {
    __nv_bfloat16 hb = __float2bfloat16(x);
    float hf = __bfloat162float(hb);
    __nv_bfloat16 lb = __float2bfloat16(x - hf);
    h = __bfloat16_as_ushort(hb);
    l = __bfloat16_as_ushort(lb);
}

// ---------------- LayerNorm (fp32 out) ----------------
__global__ void ln_kernel(const float* __restrict__ x, const float* __restrict__ g,
                          const float* __restrict__ b, float* __restrict__ out)
{
    int tok = blockIdx.x;
    int t = threadIdx.x;
    const float* xr = x + (size_t)tok * DMODEL;
    float v0 = xr[t], v1 = xr[t + 256], v2 = xr[t + 512];
    float s = v0 + v1 + v2;
    __shared__ float red[8];
#pragma unroll
    for (int o = 16; o > 0; o >>= 1) s += __shfl_xor_sync(0xffffffffu, s, o);
    if ((t & 31) == 0) red[t >> 5] = s;
    __syncthreads();
    float tot = 0.f;
#pragma unroll
    for (int i = 0; i < 8; i++) tot += red[i];
    float mu = tot * (1.0f / DMODEL);
    float d0 = v0 - mu, d1 = v1 - mu, d2 = v2 - mu;
    float sq = d0 * d0 + d1 * d1 + d2 * d2;
#pragma unroll
    for (int o = 16; o > 0; o >>= 1) sq += __shfl_xor_sync(0xffffffffu, sq, o);
    __syncthreads();
    if ((t & 31) == 0) red[t >> 5] = sq;
    __syncthreads();
    float vs = 0.f;
#pragma unroll
    for (int i = 0; i < 8; i++) vs += red[i];
    float rs = rsqrtf(vs * (1.0f / DMODEL) + 1e-5f);
    float* orow = out + (size_t)tok * DMODEL;
    orow[t]       = d0 * rs * g[t]       + b[t];
    orow[t + 256] = d1 * rs * g[t + 256] + b[t + 256];
    orow[t + 512] = d2 * rs * g[t + 512] + b[t + 512];
}

// ---------------- LayerNorm (split hi/lo bf16 planes out) ----------------
__global__ void ln_split_kernel(const float* __restrict__ x, const float* __restrict__ g,
                                const float* __restrict__ b,
                                uint16_t* __restrict__ oh, uint16_t* __restrict__ ol)
{
    int tok = blockIdx.x;
    int t = threadIdx.x;
    const float* xr = x + (size_t)tok * DMODEL;
    float v0 = xr[t], v1 = xr[t + 256], v2 = xr[t + 512];
    float s = v0 + v1 + v2;
    __shared__ float red[8];
#pragma unroll
    for (int o = 16; o > 0; o >>= 1) s += __shfl_xor_sync(0xffffffffu, s, o);
    if ((t & 31) == 0) red[t >> 5] = s;
    __syncthreads();
    float tot = 0.f;
#pragma unroll
    for (int i = 0; i < 8; i++) tot += red[i];
    float mu = tot * (1.0f / DMODEL);
    float d0 = v0 - mu, d1 = v1 - mu, d2 = v2 - mu;
    float sq = d0 * d0 + d1 * d1 + d2 * d2;
#pragma unroll
    for (int o = 16; o > 0; o >>= 1) sq += __shfl_xor_sync(0xffffffffu, sq, o);
    __syncthreads();
    if ((t & 31) == 0) red[t >> 5] = sq;
    __syncthreads();
    float vs = 0.f;
#pragma unroll
    for (int i = 0; i < 8; i++) vs += red[i];
    float rs = rsqrtf(vs * (1.0f / DMODEL) + 1e-5f);
    size_t base = (size_t)tok * DMODEL;
    float vals[3] = { d0 * rs * g[t] + b[t],
                      d1 * rs * g[t + 256] + b[t + 256],
                      d2 * rs * g[t + 512] + b[t + 512] };
#pragma unroll
    for (int i = 0; i < 3; i++) {
        uint16_t h, l;
        split_hl(vals[i], h, l);
        oh[base + t + 256 * i] = h;
        ol[base + t + 256 * i] = l;
    }
}

// ---------------- weight conversion: fp32 -> hi/lo bf16 planes ----------------
__global__ void convert_w_kernel(const float* __restrict__ W,
                                 uint16_t* __restrict__ wh, uint16_t* __restrict__ wl, int n)
{
    int i = blockIdx.x * 256 + threadIdx.x;
    if (i < n) {
        uint16_t h, l;
        split_hl(W[i], h, l);
        wh[i] = h;
        wl[i] = l;
    }
}

// ---------------- Block-diagonal per-head QKV -> packed q/k + V^T f16 ----------------
__global__ void __launch_bounds__(256) qkv_kernel(
    const float* __restrict__ ln,
    const float* __restrict__ Wq, const float* __restrict__ bq,
    const float* __restrict__ Wk, const float* __restrict__ bk,
    const float* __restrict__ Wv, const float* __restrict__ bv,
    uint32_t* __restrict__ qp, uint32_t* __restrict__ ksp,
    uint32_t* __restrict__ kwp, __half* __restrict__ vt)
{
    __shared__ float Xs[64 * 65];
    __shared__ float Ws[64 * 65];
    int hh = blockIdx.y;
    int t0 = blockIdx.x * 64;
    int t  = threadIdx.x;
    int tx = t & 15, ty = t >> 4;

#pragma unroll
    for (int it = 0; it < 4; it++) {
        int idx = it * 1024 + t * 4;
        int r = idx >> 6, c = idx & 63;
        float4 x4 = *(const float4*)(ln + (size_t)(t0 + r) * DMODEL + hh * HDIM + c);
        Xs[(c + 0) * 65 + r] = x4.x;
        Xs[(c + 1) * 65 + r] = x4.y;
        Xs[(c + 2) * 65 + r] = x4.z;
        Xs[(c + 3) * 65 + r] = x4.w;
    }

    const float* Wm[3] = { Wq + hh * 4096, Wk + hh * 4096, Wv + hh * 4096 };
    const float* bm[3] = { bq + hh * 64,  bk + hh * 64,  bv + hh * 64 };

    for (int m = 0; m < 3; m++) {
        __syncthreads();
#pragma unroll
        for (int it = 0; it < 4; it++) {
            int idx = it * 1024 + t * 4;
            int r = idx >> 6, c = idx & 63;
            float4 w4 = *(const float4*)(Wm[m] + r * 64 + c);
            Ws[(c + 0) * 65 + r] = w4.x;
            Ws[(c + 1) * 65 + r] = w4.y;
            Ws[(c + 2) * 65 + r] = w4.z;
            Ws[(c + 3) * 65 + r] = w4.w;
        }
        __syncthreads();

        float acc[4][4] = {};
#pragma unroll
        for (int d = 0; d < 64; d++) {
            float xa[4], wb[4];
#pragma unroll
            for (int i = 0; i < 4; i++) xa[i] = Xs[d * 65 + ty * 4 + i];
#pragma unroll
            for (int j = 0; j < 4; j++) wb[j] = Ws[d * 65 + tx + 16 * j];
#pragma unroll
            for (int i = 0; i < 4; i++)
#pragma unroll
                for (int j = 0; j < 4; j++) acc[i][j] += xa[i] * wb[j];
        }
#pragma unroll
        for (int i = 0; i < 4; i++) {
            int tok = t0 + ty * 4 + i;
#pragma unroll
            for (int j = 0; j < 4; j++) {
                int o = tx + 16 * j;
                float val = acc[i][j] + bm[m][o];
                size_t off = (size_t)tok * DMODEL + hh * HDIM + o;
                if (m == 0) {
                    qp[off] = pack_split(0.125f * val);
                } else if (m == 1) {
                    uint32_t s, w;
                    pack_split2(val, s, w);
                    ksp[off] = s;
                    kwp[off] = w;
                } else {
                    int bb = tok >> 10, pos = tok & 1023;
                    vt[((size_t)((bb * 12 + hh) * 64 + o)) * 1024 + pos] = __float2half(val);
                }
            }
        }
    }
}

// ---------------- HMMA flash attention + residual (unchanged) ----------------
#define AT_BUF 40960

__global__ void __launch_bounds__(256, 1) attn_mma_kernel(
    const uint32_t* __restrict__ qp, const uint32_t* __restrict__ ksp,
    const uint32_t* __restrict__ kwp, const __half* __restrict__ vt,
    const float* __restrict__ x, float* __restrict__ out)
{
    extern __shared__ char dsm[];
    uint32_t sb = (uint32_t)__cvta_generic_to_shared(dsm);

    const int b = blockIdx.z, hh = blockIdx.y;
    const int q0 = blockIdx.x * 128;
    const int t = threadIdx.x, lane = t & 31, w = t >> 5;
    const int wq = w * 16;
    const int bh = b * 12 + hh;
    const int ho = hh * HDIM;
    const size_t tok0 = (size_t)b * 1024 + q0;

    const uint32_t Qb = sb;
    const uint32_t Bb = sb + 32768;

#pragma unroll
    for (int i = 0; i < 8; i++) {
        int idx = t + 256 * i;
        int r = idx >> 4, c = idx & 15;
        cp16(Qb + r * 256 + (uint32_t)((c ^ (r & 7)) << 4),
             qp + (tok0 + r) * DMODEL + ho + c * 4);
    }
    {
        int kg0 = b * 1024;
#pragma unroll
        for (int i = 0; i < 4; i++) {
            int idx = t + 256 * i;
            int r = idx >> 4, c = idx & 15;
            uint32_t so = (uint32_t)(r * 256 + ((c ^ (r & 7)) << 4));
            cp16(Bb + so,         ksp + (size_t)(kg0 + r) * DMODEL + ho + c * 4);
            cp16(Bb + 16384 + so, kwp + (size_t)(kg0 + r) * DMODEL + ho + c * 4);
        }
#pragma unroll
        for (int i = 0; i < 2; i++) {
            int idx = t + 256 * i;
            int r = idx >> 3, c = idx & 7;
            cp16(Bb + 32768 + (uint32_t)(r * 128 + ((c ^ (r & 7)) << 4)),
                 vt + ((size_t)(bh * 64 + r)) * 1024 + c * 8);
        }
    }
    cp_commit();

    float oacc[8][4] = {};
    float rs0 = 0.f, rs1 = 0.f;
    uint32_t af[8][4];

    for (int kt = 0; kt < 16; kt++) {
        if (kt + 1 < 16) {
            uint32_t nb = Bb + (uint32_t)((kt + 1) & 1) * AT_BUF;
            int kg = b * 1024 + (kt + 1) * 64;
#pragma unroll
            for (int i = 0; i < 4; i++) {
                int idx = t + 256 * i;
                int r = idx >> 4, c = idx & 15;
                uint32_t so = (uint32_t)(r * 256 + ((c ^ (r & 7)) << 4));
                cp16(nb + so,         ksp + (size_t)(kg + r) * DMODEL + ho + c * 4);
                cp16(nb + 16384 + so, kwp + (size_t)(kg + r) * DMODEL + ho + c * 4);
            }
#pragma unroll
            for (int i = 0; i < 2; i++) {
                int idx = t + 256 * i;
                int r = idx >> 3, c = idx & 7;
                cp16(nb + 32768 + (uint32_t)(r * 128 + ((c ^ (r & 7)) << 4)),
                     vt + ((size_t)(bh * 64 + r)) * 1024 + (kt + 1) * 64 + c * 8);
            }
            cp_commit();
            cp_wait1();
        } else {
            cp_wait0();
        }
        __syncthreads();

        uint32_t cb = Bb + (uint32_t)(kt & 1) * AT_BUF;

        if (kt == 0) {
#pragma unroll
            for (int ks = 0; ks < 8; ks++) {
                int r = wq + (lane & 15);
                int c = 2 * ks + (lane >> 4);
                ldsm4(af[ks], Qb + r * 256 + (uint32_t)((c ^ (r & 7)) << 4));
            }
        }

        float sacc[8][4] = {};
#pragma unroll
        for (int pass = 0; pass < 2; pass++) {
            uint32_t kb = cb + (uint32_t)pass * 16384;
#pragma unroll
            for (int kp = 0; kp < 4; kp++) {
                uint32_t bf[8][4];
#pragma unroll
                for (int j = 0; j < 8; j++) {
                    int r = j * 8 + (lane & 7);
                    int c = kp * 4 + ((lane >> 3) & 3);
                    ldsm4(bf[j], kb + r * 256 + (uint32_t)((c ^ (r & 7)) << 4));
                }
#pragma unroll
                for (int s = 0; s < 2; s++)
#pragma unroll
                    for (int j = 0; j < 8; j++)
                        mma_bf16(sacc[j], af[kp * 2 + s], &bf[j][s * 2]);
            }
        }

        uint32_t pa[4][4];
#pragma unroll
        for (int j = 0; j < 8; j++) {
            float e0 = __expf(sacc[j][0]);
            float e1 = __expf(sacc[j][1]);
            float e2 = __expf(sacc[j][2]);
            float e3 = __expf(sacc[j][3]);
            rs0 += e0 + e1;
            rs1 += e2 + e3;
            pa[j >> 1][(j & 1) * 2 + 0] = f16x2(e1, e0);
            pa[j >> 1][(j & 1) * 2 + 1] = f16x2(e3, e2);
        }

        uint32_t vb0 = cb + 32768;
#pragma unroll
        for (int kp = 0; kp < 2; kp++) {
            uint32_t vb[8][4];
#pragma unroll
            for (int j = 0; j < 8; j++) {
                int r = j * 8 + (lane & 7);
                int c = kp * 4 + ((lane >> 3) & 3);
                ldsm4(vb[j], vb0 + r * 128 + (uint32_t)((c ^ (r & 7)) << 4));
            }
#pragma unroll
            for (int s = 0; s < 2; s++)
#pragma unroll
                for (int j = 0; j < 8; j++)
                    mma_f16(oacc[j], pa[kp * 2 + s], &vb[j][s * 2]);
        }
        __syncthreads();
    }

    rs0 += __shfl_xor_sync(0xffffffffu, rs0, 1);
    rs0 += __shfl_xor_sync(0xffffffffu, rs0, 2);
    rs1 += __shfl_xor_sync(0xffffffffu, rs1, 1);
    rs1 += __shfl_xor_sync(0xffffffffu, rs1, 2);
    float inv0 = 1.0f / rs0, inv1 = 1.0f / rs1;

    size_t row0 = tok0 + wq + (lane >> 2);
    size_t row1 = row0 + 8;
#pragma unroll
    for (int j = 0; j < 8; j++) {
        int col = ho + j * 8 + 2 * (lane & 3);
        size_t o0 = row0 * DMODEL + col;
        size_t o1 = row1 * DMODEL + col;
        float2 x0 = *(const float2*)(x + o0);
        float2 x1v = *(const float2*)(x + o1);
        float2 r0 = { oacc[j][0] * inv0 + x0.x,  oacc[j][1] * inv0 + x0.y };
        float2 r1 = { oacc[j][2] * inv1 + x1v.x, oacc[j][3] * inv1 + x1v.y };
        *(float2*)(out + o0) = r0;
        *(float2*)(out + o1) = r1;
    }
}

// ---------------- HMMA 3-term split-bf16 GEMM: 256x128 CTA tile, 64x64 warp tile ----------------
// 8 warps in 4m x 2n grid. A re-read x2, B x4 (was x4/x2 on smaller warp tiles):
// smem reads drop ~35% per unit of work. acc[4][8][4] = 128 regs.
#define GA_B   32768                 // A plane tile: 256 rows x 128B
#define GB_B   16384                 // B plane tile: 128 rows x 128B
#define GST_B  (2 * GA_B + 2 * GB_B) // 98304 per stage

__device__ __forceinline__ uint32_t sw(uint32_t b, int row, int ch) {
    return b + (uint32_t)(row * 128) + (uint32_t)((ch ^ (row & 7)) << 4);
}

__device__ __forceinline__ void load_tile4(uint32_t sb,
    const uint16_t* __restrict__ Ah, const uint16_t* __restrict__ Al,
    const uint16_t* __restrict__ Bh, const uint16_t* __restrict__ Bl,
    int m0, int n0, int K, int ic, int t)
{
#pragma unroll
    for (int i = 0; i < 8; i++) {          // A planes: 256 rows x 8 chunks
        int idx = t + 256 * i;
        int row = idx >> 3, ch = idx & 7;
        size_t ao = (size_t)(m0 + row) * K + ic * 64 + ch * 8;
        cp16(sw(sb,        row, ch), Ah + ao);
        cp16(sw(sb + GA_B, row, ch), Al + ao);
    }
#pragma unroll
    for (int i = 0; i < 4; i++) {          // B planes: 128 rows x 8 chunks
        int idx = t + 256 * i;
        int row = idx >> 3, ch = idx & 7;
        size_t bo = (size_t)(n0 + row) * K + ic * 64 + ch * 8;
        cp16(sw(sb + 2 * GA_B,        row, ch), Bh + bo);
        cp16(sw(sb + 2 * GA_B + GB_B, row, ch), Bl + bo);
    }
}

template<int MODE>
__global__ void __launch_bounds__(256, 1)
gemm_hmma_kernel(const uint16_t* __restrict__ Ah, const uint16_t* __restrict__ Al,
                 const uint16_t* __restrict__ Bh, const uint16_t* __restrict__ Bl,
                 const float* __restrict__ bias, const float* __restrict__ resid,
                 void* __restrict__ out_a, void* __restrict__ out_b, int N, int K)
{
    extern __shared__ char dsm[];
    uint32_t smem_u32 = (uint32_t)__cvta_generic_to_shared(dsm);
    uint32_t base = (smem_u32 + 127) & ~127u;

    const int t = threadIdx.x;
    const int lane = t & 31, wid = t >> 5;
    const int m0 = blockIdx.y * 256, n0 = blockIdx.x * 128;
    const int warp_m = (wid >> 1) * 64, warp_n = (wid & 1) * 64;

    float acc[4][8][4] = {};
    const int NC = K >> 6;

    load_tile4(base, Ah, Al, Bh, Bl, m0, n0, K, 0, t);
    cp_commit();

    for (int ic = 0; ic < NC; ic++) {
        uint32_t cb = base + (uint32_t)(ic & 1) * GST_B;
        if (ic + 1 < NC) {
            load_tile4(base + (uint32_t)((ic + 1) & 1) * GST_B,
                       Ah, Al, Bh, Bl, m0, n0, K, ic + 1, t);
            cp_commit();
            cp_wait1();
        } else {
            cp_wait0();
        }
        __syncthreads();

        uint32_t Ahb = cb, Alb = cb + GA_B, Bhb = cb + 2 * GA_B, Blb = cb + 2 * GA_B + GB_B;
#pragma unroll
        for (int kp2 = 0; kp2 < 2; kp2++) {
            uint32_t ah[4][2][4], al[4][2][4];
#pragma unroll
            for (int mt = 0; mt < 4; mt++)
#pragma unroll
                for (int ks = 0; ks < 2; ks++) {
                    int row = warp_m + mt * 16 + (lane & 15);
                    int ch  = kp2 * 4 + ks * 2 + (lane >> 4);
                    ldsm4(ah[mt][ks], sw(Ahb, row, ch));
                    ldsm4(al[mt][ks], sw(Alb, row, ch));
                }
            // B in nt-pairs: 16 frag regs live at a time; 8 independent accs per term-group
#pragma unroll
            for (int np = 0; np < 4; np++) {
                uint32_t bh[2][4], bl[2][4];
#pragma unroll
                for (int j = 0; j < 2; j++) {
                    int row = warp_n + (np * 2 + j) * 8 + (lane & 7);
                    int ch  = kp2 * 4 + ((lane >> 3) & 3);
                    ldsm4(bh[j], sw(Bhb, row, ch));
                    ldsm4(bl[j], sw(Blb, row, ch));
                }
#pragma unroll
                for (int ks = 0; ks < 2; ks++) {
#pragma unroll
                    for (int mt = 0; mt < 4; mt++)
#pragma unroll
                        for (int j = 0; j < 2; j++)
                            mma_bf16(acc[mt][np * 2 + j], ah[mt][ks], &bh[j][ks * 2]);
#pragma unroll
                    for (int mt = 0; mt < 4; mt++)
#pragma unroll
                        for (int j = 0; j < 2; j++)
                            mma_bf16(acc[mt][np * 2 + j], ah[mt][ks], &bl[j][ks * 2]);
#pragma unroll
                    for (int mt = 0; mt < 4; mt++)
#pragma unroll
                        for (int j = 0; j < 2; j++)
                            mma_bf16(acc[mt][np * 2 + j], al[mt][ks], &bh[j][ks * 2]);
                }
            }
        }
        __syncthreads();
    }

    int rbase = m0 + warp_m + (lane >> 2);
    int cbase = n0 + warp_n + (lane & 3) * 2;
#pragma unroll
    for (int mt = 0; mt < 4; mt++)
#pragma unroll
        for (int nt = 0; nt < 8; nt++)
#pragma unroll
            for (int hh = 0; hh < 2; hh++) {
                int row = rbase + mt * 16 + hh * 8;
                int col = cbase + nt * 8;
                float v0 = acc[mt][nt][hh * 2 + 0] + bias[col];
                float v1 = acc[mt][nt][hh * 2 + 1] + bias[col + 1];
                size_t off = (size_t)row * N + col;
                if (MODE == 1) {
                    v0 = 0.5f * v0 * (1.0f + erff(v0 * 0.70710678118654752f));
                    v1 = 0.5f * v1 * (1.0f + erff(v1 * 0.70710678118654752f));
                    uint16_t h0, l0, h1, l1;
                    split_hl(v0, h0, l0);
                    split_hl(v1, h1, l1);
                    ((uint32_t*)out_a)[off >> 1] = (uint32_t)h0 | ((uint32_t)h1 << 16);
                    ((uint32_t*)out_b)[off >> 1] = (uint32_t)l0 | ((uint32_t)l1 << 16);
                } else {
                    const float2 rr = *(const float2*)(resid + off);
                    float2 ov = { v0 + rr.x, v1 + rr.y };
                    *(float2*)((float*)out_a + off) = ov;
                }
            }
}

// ---------------- launch ----------------
extern "C" void kernel_launch(void* const* d_in, const int* in_sizes, int n_in,
                              void* d_out, int out_size)
{
    const float* x    = (const float*)d_in[0];
    const float* ln1g = (const float*)d_in[1];
    const float* ln1b = (const float*)d_in[2];
    const float* Wq   = (const float*)d_in[3];
    const float* bq   = (const float*)d_in[4];
    const float* Wk   = (const float*)d_in[5];
    const float* bk   = (const float*)d_in[6];
    const float* Wv   = (const float*)d_in[7];
    const float* bv   = (const float*)d_in[8];
    const float* ln2g = (const float*)d_in[9];
    const float* ln2b = (const float*)d_in[10];
    const float* W1   = (const float*)d_in[11];
    const float* b1   = (const float*)d_in[12];
    const float* W2   = (const float*)d_in[13];
    const float* b2   = (const float*)d_in[14];
    float* out = (float*)d_out;

    float *ln, *x1;
    uint32_t *qp, *ksp, *kwp;
    uint16_t *lnh, *lnl, *acth, *actl, *w1h, *w1l, *w2h, *w2l;
    __half* vt;
    cudaGetSymbolAddress((void**)&ln,   g_ln);
    cudaGetSymbolAddress((void**)&lnh,  g_lnh);
    cudaGetSymbolAddress((void**)&lnl,  g_lnl);
    cudaGetSymbolAddress((void**)&qp,   g_qp);
    cudaGetSymbolAddress((void**)&ksp,  g_ks);
    cudaGetSymbolAddress((void**)&kwp,  g_kw);
    cudaGetSymbolAddress((void**)&vt,   g_vt);
    cudaGetSymbolAddress((void**)&x1,   g_x1);
    cudaGetSymbolAddress((void**)&acth, g_acth);
    cudaGetSymbolAddress((void**)&actl, g_actl);
    cudaGetSymbolAddress((void**)&w1h,  g_w1h);
    cudaGetSymbolAddress((void**)&w1l,  g_w1l);
    cudaGetSymbolAddress((void**)&w2h,  g_w2h);
    cudaGetSymbolAddress((void**)&w2l,  g_w2l);

    const int ATTN_SMEM = 32768 + 2 * AT_BUF;   // 114688
    cudaFuncSetAttribute((const void*)attn_mma_kernel,
                         cudaFuncAttributeMaxDynamicSharedMemorySize, ATTN_SMEM);
    const int GEMM_SMEM = 2 * GST_B + 256;      // 196864
    cudaFuncSetAttribute(gemm_hmma_kernel<1>,
                         cudaFuncAttributeMaxDynamicSharedMemorySize, GEMM_SMEM);
    cudaFuncSetAttribute(gemm_hmma_kernel<2>,
                         cudaFuncAttributeMaxDynamicSharedMemorySize, GEMM_SMEM);

    convert_w_kernel<<<(DMLP * DMODEL + 255) / 256, 256>>>(W1, w1h, w1l, DMLP * DMODEL);
    convert_w_kernel<<<(DMODEL * DMLP + 255) / 256, 256>>>(W2, w2h, w2l, DMODEL * DMLP);

    // 1) LN1
    ln_kernel<<<TOKENS, 256>>>(x, ln1g, ln1b, ln);
    // 2) QKV -> packed q/k + V^T f16
    qkv_kernel<<<dim3(TOKENS / 64, NHEAD), 256>>>(ln, Wq, bq, Wk, bk, Wv, bv, qp, ksp, kwp, vt);
    // 3) HMMA attention + residual -> x1
    attn_mma_kernel<<<dim3(SEQ / 128, NHEAD, BATCH), 256, ATTN_SMEM>>>(qp, ksp, kwp, vt, x, x1);
    // 4) LN2 -> hi/lo planes
    ln_split_kernel<<<TOKENS, 256>>>(x1, ln2g, ln2b, lnh, lnl);
    // 5) MLP up + GELU -> act hi/lo planes
    gemm_hmma_kernel<1><<<dim3(DMLP / 128, TOKENS / 256), 256, GEMM_SMEM>>>(
        lnh, lnl, w1h, w1l, b1, nullptr, (void*)acth, (void*)actl, DMLP, DMODEL);
    // 6) MLP down + bias + residual -> out
    gemm_hmma_kernel<2><<<dim3(DMODEL / 128, TOKENS / 256), 256, GEMM_SMEM>>>(
        acth, actl, w2h, w2l, b2, x1, (void*)out, nullptr, DMODEL, DMLP);
}

// round 9
// speedup vs baseline: 5.1299x; 1.3862x over previous
#include <cuda_runtime.h>
#include <cuda_bf16.h>
#include <cuda_fp16.h>
#include <math.h>
#include <stdint.h>

#define TOKENS 16384
#define DMODEL 768
#define NHEAD  12
#define HDIM   64
#define DMLP   3072
#define SEQ    1024
#define BATCH  16

// ---------------- scratch (device globals; no cudaMalloc allowed) ----------------
__device__ float  g_ln  [TOKENS * DMODEL];   // LN1 out fp32 (for qkv)
__device__ __half g_lnh [TOKENS * DMODEL];   // LN2 out f16 hi plane
__device__ __half g_lnl [TOKENS * DMODEL];   // LN2 out f16 lo plane
__device__ __half g_qf  [TOKENS * DMODEL];   // q f16, pre-scaled by 0.125 [tok][h*64+d]
__device__ __half g_kf  [TOKENS * DMODEL];   // k f16                      [tok][h*64+d]
__device__ __half g_vt  [TOKENS * DMODEL];   // V^T f16: [(b*12+h)*64+d][1024]
__device__ float  g_x1  [TOKENS * DMODEL];   // x + attn
__device__ __half g_acth[TOKENS * DMLP];     // GELU out f16 hi plane
__device__ __half g_actl[TOKENS * DMLP];     // GELU out f16 lo plane
__device__ __half g_w1h [DMLP * DMODEL];     // W1 f16
__device__ __half g_w2h [DMODEL * DMLP];     // W2 f16

// ---------------- PTX helpers (portable sm_80-class only) ----------------
__device__ __forceinline__ void cp16(uint32_t s, const void* g) {
    asm volatile("cp.async.cg.shared.global [%0], [%1], 16;" :: "r"(s), "l"(g));
}
__device__ __forceinline__ void cp_commit() { asm volatile("cp.async.commit_group;" ::: "memory"); }
__device__ __forceinline__ void cp_wait1()  { asm volatile("cp.async.wait_group 1;" ::: "memory"); }
__device__ __forceinline__ void cp_wait0()  { asm volatile("cp.async.wait_group 0;" ::: "memory"); }

__device__ __forceinline__ void ldsm4(uint32_t* r, uint32_t addr) {
    asm volatile("ldmatrix.sync.aligned.m8n8.x4.shared.b16 {%0,%1,%2,%3}, [%4];"
                 : "=r"(r[0]), "=r"(r[1]), "=r"(r[2]), "=r"(r[3]) : "r"(addr));
}
__device__ __forceinline__ void mma_f16(float* d, const uint32_t* a, const uint32_t* b) {
    asm("mma.sync.aligned.m16n8k16.row.col.f32.f16.f16.f32 "
        "{%0,%1,%2,%3}, {%4,%5,%6,%7}, {%8,%9}, {%0,%1,%2,%3};"
        : "+f"(d[0]), "+f"(d[1]), "+f"(d[2]), "+f"(d[3])
        : "r"(a[0]), "r"(a[1]), "r"(a[2]), "r"(a[3]), "r"(b[0]), "r"(b[1]));
}
__device__ __forceinline__ uint32_t f16x2(float hi, float lo) {
    uint32_t u;
    asm("cvt.rn.f16x2.f32 %0, %1, %2;" : "=r"(u) : "f"(hi), "f"(lo));
    return u;
}

// f16 split helpers
__device__ __forceinline__ void split_hl16(float x, __half& h, __half& l) {
    h = __float2half(x);
    l = __float2half(x - __half2float(h));
}

// ---------------- LayerNorm (fp32 out) ----------------
__global__ void ln_kernel(const float* __restrict__ x, const float* __restrict__ g,
                          const float* __restrict__ b, float* __restrict__ out)
{
    int tok = blockIdx.x;
    int t = threadIdx.x;
    const float* xr = x + (size_t)tok * DMODEL;
    float v0 = xr[t], v1 = xr[t + 256], v2 = xr[t + 512];
    float s = v0 + v1 + v2;
    __shared__ float red[8];
#pragma unroll
    for (int o = 16; o > 0; o >>= 1) s += __shfl_xor_sync(0xffffffffu, s, o);
    if ((t & 31) == 0) red[t >> 5] = s;
    __syncthreads();
    float tot = 0.f;
#pragma unroll
    for (int i = 0; i < 8; i++) tot += red[i];
    float mu = tot * (1.0f / DMODEL);
    float d0 = v0 - mu, d1 = v1 - mu, d2 = v2 - mu;
    float sq = d0 * d0 + d1 * d1 + d2 * d2;
#pragma unroll
    for (int o = 16; o > 0; o >>= 1) sq += __shfl_xor_sync(0xffffffffu, sq, o);
    __syncthreads();
    if ((t & 31) == 0) red[t >> 5] = sq;
    __syncthreads();
    float vs = 0.f;
#pragma unroll
    for (int i = 0; i < 8; i++) vs += red[i];
    float rs = rsqrtf(vs * (1.0f / DMODEL) + 1e-5f);
    float* orow = out + (size_t)tok * DMODEL;
    orow[t]       = d0 * rs * g[t]       + b[t];
    orow[t + 256] = d1 * rs * g[t + 256] + b[t + 256];
    orow[t + 512] = d2 * rs * g[t + 512] + b[t + 512];
}

// ---------------- LayerNorm (split hi/lo f16 planes out) ----------------
__global__ void ln_split_kernel(const float* __restrict__ x, const float* __restrict__ g,
                                const float* __restrict__ b,
                                __half* __restrict__ oh, __half* __restrict__ ol)
{
    int tok = blockIdx.x;
    int t = threadIdx.x;
    const float* xr = x + (size_t)tok * DMODEL;
    float v0 = xr[t], v1 = xr[t + 256], v2 = xr[t + 512];
    float s = v0 + v1 + v2;
    __shared__ float red[8];
#pragma unroll
    for (int o = 16; o > 0; o >>= 1) s += __shfl_xor_sync(0xffffffffu, s, o);
    if ((t & 31) == 0) red[t >> 5] = s;
    __syncthreads();
    float tot = 0.f;
#pragma unroll
    for (int i = 0; i < 8; i++) tot += red[i];
    float mu = tot * (1.0f / DMODEL);
    float d0 = v0 - mu, d1 = v1 - mu, d2 = v2 - mu;
    float sq = d0 * d0 + d1 * d1 + d2 * d2;
#pragma unroll
    for (int o = 16; o > 0; o >>= 1) sq += __shfl_xor_sync(0xffffffffu, sq, o);
    __syncthreads();
    if ((t & 31) == 0) red[t >> 5] = sq;
    __syncthreads();
    float vs = 0.f;
#pragma unroll
    for (int i = 0; i < 8; i++) vs += red[i];
    float rs = rsqrtf(vs * (1.0f / DMODEL) + 1e-5f);
    size_t base = (size_t)tok * DMODEL;
    float vals[3] = { d0 * rs * g[t] + b[t],
                      d1 * rs * g[t + 256] + b[t + 256],
                      d2 * rs * g[t + 512] + b[t + 512] };
#pragma unroll
    for (int i = 0; i < 3; i++) {
        __half h, l;
        split_hl16(vals[i], h, l);
        oh[base + t + 256 * i] = h;
        ol[base + t + 256 * i] = l;
    }
}

// ---------------- weight conversion: fp32 -> f16 ----------------
__global__ void convert_w_kernel(const float* __restrict__ W, __half* __restrict__ wh, int n)
{
    int i = blockIdx.x * 256 + threadIdx.x;
    if (i < n) wh[i] = __float2half(W[i]);
}

// ---------------- Block-diagonal per-head QKV -> q/k f16 + V^T f16 ----------------
__global__ void __launch_bounds__(256) qkv_kernel(
    const float* __restrict__ ln,
    const float* __restrict__ Wq, const float* __restrict__ bq,
    const float* __restrict__ Wk, const float* __restrict__ bk,
    const float* __restrict__ Wv, const float* __restrict__ bv,
    __half* __restrict__ qf, __half* __restrict__ kf, __half* __restrict__ vt)
{
    __shared__ float Xs[64 * 65];
    __shared__ float Ws[64 * 65];
    int hh = blockIdx.y;
    int t0 = blockIdx.x * 64;
    int t  = threadIdx.x;
    int tx = t & 15, ty = t >> 4;

#pragma unroll
    for (int it = 0; it < 4; it++) {
        int idx = it * 1024 + t * 4;
        int r = idx >> 6, c = idx & 63;
        float4 x4 = *(const float4*)(ln + (size_t)(t0 + r) * DMODEL + hh * HDIM + c);
        Xs[(c + 0) * 65 + r] = x4.x;
        Xs[(c + 1) * 65 + r] = x4.y;
        Xs[(c + 2) * 65 + r] = x4.z;
        Xs[(c + 3) * 65 + r] = x4.w;
    }

    const float* Wm[3] = { Wq + hh * 4096, Wk + hh * 4096, Wv + hh * 4096 };
    const float* bm[3] = { bq + hh * 64,  bk + hh * 64,  bv + hh * 64 };

    for (int m = 0; m < 3; m++) {
        __syncthreads();
#pragma unroll
        for (int it = 0; it < 4; it++) {
            int idx = it * 1024 + t * 4;
            int r = idx >> 6, c = idx & 63;
            float4 w4 = *(const float4*)(Wm[m] + r * 64 + c);
            Ws[(c + 0) * 65 + r] = w4.x;
            Ws[(c + 1) * 65 + r] = w4.y;
            Ws[(c + 2) * 65 + r] = w4.z;
            Ws[(c + 3) * 65 + r] = w4.w;
        }
        __syncthreads();

        float acc[4][4] = {};
#pragma unroll
        for (int d = 0; d < 64; d++) {
            float xa[4], wb[4];
#pragma unroll
            for (int i = 0; i < 4; i++) xa[i] = Xs[d * 65 + ty * 4 + i];
#pragma unroll
            for (int j = 0; j < 4; j++) wb[j] = Ws[d * 65 + tx + 16 * j];
#pragma unroll
            for (int i = 0; i < 4; i++)
#pragma unroll
                for (int j = 0; j < 4; j++) acc[i][j] += xa[i] * wb[j];
        }
#pragma unroll
        for (int i = 0; i < 4; i++) {
            int tok = t0 + ty * 4 + i;
#pragma unroll
            for (int j = 0; j < 4; j++) {
                int o = tx + 16 * j;
                float val = acc[i][j] + bm[m][o];
                size_t off = (size_t)tok * DMODEL + hh * HDIM + o;
                if (m == 0) {
                    qf[off] = __float2half(0.125f * val);
                } else if (m == 1) {
                    kf[off] = __float2half(val);
                } else {
                    int bb = tok >> 10, pos = tok & 1023;
                    vt[((size_t)((bb * 12 + hh) * 64 + o)) * 1024 + pos] = __float2half(val);
                }
            }
        }
    }
}

// ---------------- shared swizzle: 128B rows, 8 x 16B chunks ----------------
__device__ __forceinline__ uint32_t sw(uint32_t b, int row, int ch) {
    return b + (uint32_t)(row * 128) + (uint32_t)((ch ^ (row & 7)) << 4);
}

// ---------------- HMMA flash attention (full f16) + residual ----------------
// CTA: (b,h) x 128 queries; stream 16 key-tiles of 64. Q,K,V all f16.
// Smem: Q 16KB + 2 x (K 8KB + Vt 8KB) = 48KB.
#define AT_BUF 16384

__global__ void __launch_bounds__(256, 1) attn_mma_kernel(
    const __half* __restrict__ qf, const __half* __restrict__ kf,
    const __half* __restrict__ vt,
    const float* __restrict__ x, float* __restrict__ out)
{
    extern __shared__ char dsm[];
    uint32_t sb = (uint32_t)__cvta_generic_to_shared(dsm);

    const int b = blockIdx.z, hh = blockIdx.y;
    const int q0 = blockIdx.x * 128;
    const int t = threadIdx.x, lane = t & 31, w = t >> 5;
    const int wq = w * 16;
    const int bh = b * 12 + hh;
    const int ho = hh * HDIM;
    const size_t tok0 = (size_t)b * 1024 + q0;

    const uint32_t Qb = sb;
    const uint32_t Bb = sb + 16384;

    // Q tile: 128 rows x 64 f16 (128B rows)
#pragma unroll
    for (int i = 0; i < 4; i++) {
        int idx = t + 256 * i;
        int r = idx >> 3, c = idx & 7;
        cp16(sw(Qb, r, c), qf + (tok0 + r) * DMODEL + ho + c * 8);
    }
    // key-tile 0: K 64x64 f16 + V^T 64x64 f16
    {
        int kg0 = b * 1024;
#pragma unroll
        for (int i = 0; i < 2; i++) {
            int idx = t + 256 * i;
            int r = idx >> 3, c = idx & 7;
            cp16(sw(Bb, r, c),        kf + (size_t)(kg0 + r) * DMODEL + ho + c * 8);
            cp16(sw(Bb + 8192, r, c), vt + ((size_t)(bh * 64 + r)) * 1024 + c * 8);
        }
    }
    cp_commit();

    float oacc[8][4] = {};
    float rs0 = 0.f, rs1 = 0.f;
    uint32_t af[4][4];

    for (int kt = 0; kt < 16; kt++) {
        if (kt + 1 < 16) {
            uint32_t nb = Bb + (uint32_t)((kt + 1) & 1) * AT_BUF;
            int kg = b * 1024 + (kt + 1) * 64;
#pragma unroll
            for (int i = 0; i < 2; i++) {
                int idx = t + 256 * i;
                int r = idx >> 3, c = idx & 7;
                cp16(sw(nb, r, c),        kf + (size_t)(kg + r) * DMODEL + ho + c * 8);
                cp16(sw(nb + 8192, r, c), vt + ((size_t)(bh * 64 + r)) * 1024 + (kt + 1) * 64 + c * 8);
            }
            cp_commit();
            cp_wait1();
        } else {
            cp_wait0();
        }
        __syncthreads();

        uint32_t cb = Bb + (uint32_t)(kt & 1) * AT_BUF;

        if (kt == 0) {
            // hoisted Q A-fragments (4 k16-steps)
#pragma unroll
            for (int ks = 0; ks < 4; ks++) {
                int r = wq + (lane & 15);
                int c = ks * 2 + (lane >> 4);
                ldsm4(af[ks], sw(Qb, r, c));
            }
        }

        // ---- scores: single-pass f16 ----
        float sacc[8][4] = {};
#pragma unroll
        for (int kp = 0; kp < 2; kp++) {
            uint32_t bf[8][4];
#pragma unroll
            for (int j = 0; j < 8; j++) {
                int r = j * 8 + (lane & 7);
                int c = kp * 4 + ((lane >> 3) & 3);
                ldsm4(bf[j], sw(cb, r, c));
            }
#pragma unroll
            for (int s = 0; s < 2; s++)
#pragma unroll
                for (int j = 0; j < 8; j++)
                    mma_f16(sacc[j], af[kp * 2 + s], &bf[j][s * 2]);
        }

        // ---- exp (no max) + pack P to f16 A-fragments ----
        uint32_t pa[4][4];
#pragma unroll
        for (int j = 0; j < 8; j++) {
            float e0 = __expf(sacc[j][0]);
            float e1 = __expf(sacc[j][1]);
            float e2 = __expf(sacc[j][2]);
            float e3 = __expf(sacc[j][3]);
            rs0 += e0 + e1;
            rs1 += e2 + e3;
            pa[j >> 1][(j & 1) * 2 + 0] = f16x2(e1, e0);
            pa[j >> 1][(j & 1) * 2 + 1] = f16x2(e3, e2);
        }

        // ---- O += P @ V (f16) ----
        uint32_t vb0 = cb + 8192;
#pragma unroll
        for (int kp = 0; kp < 2; kp++) {
            uint32_t vb[8][4];
#pragma unroll
            for (int j = 0; j < 8; j++) {
                int r = j * 8 + (lane & 7);
                int c = kp * 4 + ((lane >> 3) & 3);
                ldsm4(vb[j], sw(vb0, r, c));
            }
#pragma unroll
            for (int s = 0; s < 2; s++)
#pragma unroll
                for (int j = 0; j < 8; j++)
                    mma_f16(oacc[j], pa[kp * 2 + s], &vb[j][s * 2]);
        }
        __syncthreads();
    }

    rs0 += __shfl_xor_sync(0xffffffffu, rs0, 1);
    rs0 += __shfl_xor_sync(0xffffffffu, rs0, 2);
    rs1 += __shfl_xor_sync(0xffffffffu, rs1, 1);
    rs1 += __shfl_xor_sync(0xffffffffu, rs1, 2);
    float inv0 = 1.0f / rs0, inv1 = 1.0f / rs1;

    size_t row0 = tok0 + wq + (lane >> 2);
    size_t row1 = row0 + 8;
#pragma unroll
    for (int j = 0; j < 8; j++) {
        int col = ho + j * 8 + 2 * (lane & 3);
        size_t o0 = row0 * DMODEL + col;
        size_t o1 = row1 * DMODEL + col;
        float2 x0 = *(const float2*)(x + o0);
        float2 x1v = *(const float2*)(x + o1);
        float2 r0 = { oacc[j][0] * inv0 + x0.x,  oacc[j][1] * inv0 + x0.y };
        float2 r1 = { oacc[j][2] * inv1 + x1v.x, oacc[j][3] * inv1 + x1v.y };
        *(float2*)(out + o0) = r0;
        *(float2*)(out + o1) = r1;
    }
}

// ---------------- HMMA 2-term f16 GEMM: 256x128 CTA tile, 64x64 warp tile ----------------
// C = (Ah + Al) @ Bh^T + bias; A split f16 hi/lo (repr ~2^-21), B single f16 (err ~1.4e-4).
// 8 warps in 4m x 2n grid; K-chunk 64; 2-stage cp.async (160KB smem).
#define GA_B   32768                 // A plane tile: 256 rows x 128B
#define GB_B   16384                 // B plane tile: 128 rows x 128B
#define GST_B  (2 * GA_B + GB_B)     // 81920 per stage

__device__ __forceinline__ void load_tile3(uint32_t sb,
    const __half* __restrict__ Ah, const __half* __restrict__ Al,
    const __half* __restrict__ Bh,
    int m0, int n0, int K, int ic, int t)
{
#pragma unroll
    for (int i = 0; i < 8; i++) {          // A planes: 256 rows x 8 chunks
        int idx = t + 256 * i;
        int row = idx >> 3, ch = idx & 7;
        size_t ao = (size_t)(m0 + row) * K + ic * 64 + ch * 8;
        cp16(sw(sb,        row, ch), Ah + ao);
        cp16(sw(sb + GA_B, row, ch), Al + ao);
    }
#pragma unroll
    for (int i = 0; i < 4; i++) {          // B plane: 128 rows x 8 chunks
        int idx = t + 256 * i;
        int row = idx >> 3, ch = idx & 7;
        cp16(sw(sb + 2 * GA_B, row, ch), Bh + (size_t)(n0 + row) * K + ic * 64 + ch * 8);
    }
}

template<int MODE>
__global__ void __launch_bounds__(256, 1)
gemm_hmma_kernel(const __half* __restrict__ Ah, const __half* __restrict__ Al,
                 const __half* __restrict__ Bh,
                 const float* __restrict__ bias, const float* __restrict__ resid,
                 void* __restrict__ out_a, void* __restrict__ out_b, int N, int K)
{
    extern __shared__ char dsm[];
    uint32_t smem_u32 = (uint32_t)__cvta_generic_to_shared(dsm);
    uint32_t base = (smem_u32 + 127) & ~127u;

    const int t = threadIdx.x;
    const int lane = t & 31, wid = t >> 5;
    const int m0 = blockIdx.y * 256, n0 = blockIdx.x * 128;
    const int warp_m = (wid >> 1) * 64, warp_n = (wid & 1) * 64;

    float acc[4][8][4] = {};
    const int NC = K >> 6;

    load_tile3(base, Ah, Al, Bh, m0, n0, K, 0, t);
    cp_commit();

    for (int ic = 0; ic < NC; ic++) {
        uint32_t cb = base + (uint32_t)(ic & 1) * GST_B;
        if (ic + 1 < NC) {
            load_tile3(base + (uint32_t)((ic + 1) & 1) * GST_B,
                       Ah, Al, Bh, m0, n0, K, ic + 1, t);
            cp_commit();
            cp_wait1();
        } else {
            cp_wait0();
        }
        __syncthreads();

        uint32_t Ahb = cb, Alb = cb + GA_B, Bhb = cb + 2 * GA_B;
#pragma unroll
        for (int kp2 = 0; kp2 < 2; kp2++) {
            uint32_t ah[4][2][4], al[4][2][4];
#pragma unroll
            for (int mt = 0; mt < 4; mt++)
#pragma unroll
                for (int ks = 0; ks < 2; ks++) {
                    int row = warp_m + mt * 16 + (lane & 15);
                    int ch  = kp2 * 4 + ks * 2 + (lane >> 4);
                    ldsm4(ah[mt][ks], sw(Ahb, row, ch));
                    ldsm4(al[mt][ks], sw(Alb, row, ch));
                }
#pragma unroll
            for (int np = 0; np < 4; np++) {
                uint32_t bh[2][4];
#pragma unroll
                for (int j = 0; j < 2; j++) {
                    int row = warp_n + (np * 2 + j) * 8 + (lane & 7);
                    int ch  = kp2 * 4 + ((lane >> 3) & 3);
                    ldsm4(bh[j], sw(Bhb, row, ch));
                }
#pragma unroll
                for (int ks = 0; ks < 2; ks++) {
#pragma unroll
                    for (int mt = 0; mt < 4; mt++)
#pragma unroll
                        for (int j = 0; j < 2; j++)
                            mma_f16(acc[mt][np * 2 + j], ah[mt][ks], &bh[j][ks * 2]);
#pragma unroll
                    for (int mt = 0; mt < 4; mt++)
#pragma unroll
                        for (int j = 0; j < 2; j++)
                            mma_f16(acc[mt][np * 2 + j], al[mt][ks], &bh[j][ks * 2]);
                }
            }
        }
        __syncthreads();
    }

    int rbase = m0 + warp_m + (lane >> 2);
    int cbase = n0 + warp_n + (lane & 3) * 2;
#pragma unroll
    for (int mt = 0; mt < 4; mt++)
#pragma unroll
        for (int nt = 0; nt < 8; nt++)
#pragma unroll
            for (int hh = 0; hh < 2; hh++) {
                int row = rbase + mt * 16 + hh * 8;
                int col = cbase + nt * 8;
                float v0 = acc[mt][nt][hh * 2 + 0] + bias[col];
                float v1 = acc[mt][nt][hh * 2 + 1] + bias[col + 1];
                size_t off = (size_t)row * N + col;
                if (MODE == 1) {
                    v0 = 0.5f * v0 * (1.0f + erff(v0 * 0.70710678118654752f));
                    v1 = 0.5f * v1 * (1.0f + erff(v1 * 0.70710678118654752f));
                    __half h0, l0, h1, l1;
                    split_hl16(v0, h0, l0);
                    split_hl16(v1, h1, l1);
                    ((uint32_t*)out_a)[off >> 1] =
                        (uint32_t)__half_as_ushort(h0) | ((uint32_t)__half_as_ushort(h1) << 16);
                    ((uint32_t*)out_b)[off >> 1] =
                        (uint32_t)__half_as_ushort(l0) | ((uint32_t)__half_as_ushort(l1) << 16);
                } else {
                    const float2 rr = *(const float2*)(resid + off);
                    float2 ov = { v0 + rr.x, v1 + rr.y };
                    *(float2*)((float*)out_a + off) = ov;
                }
            }
}

// ---------------- launch ----------------
extern "C" void kernel_launch(void* const* d_in, const int* in_sizes, int n_in,
                              void* d_out, int out_size)
{
    const float* x    = (const float*)d_in[0];
    const float* ln1g = (const float*)d_in[1];
    const float* ln1b = (const float*)d_in[2];
    const float* Wq   = (const float*)d_in[3];
    const float* bq   = (const float*)d_in[4];
    const float* Wk   = (const float*)d_in[5];
    const float* bk   = (const float*)d_in[6];
    const float* Wv   = (const float*)d_in[7];
    const float* bv   = (const float*)d_in[8];
    const float* ln2g = (const float*)d_in[9];
    const float* ln2b = (const float*)d_in[10];
    const float* W1   = (const float*)d_in[11];
    const float* b1   = (const float*)d_in[12];
    const float* W2   = (const float*)d_in[13];
    const float* b2   = (const float*)d_in[14];
    float* out = (float*)d_out;

    float *ln, *x1;
    __half *lnh, *lnl, *qf, *kf, *vt, *acth, *actl, *w1h, *w2h;
    cudaGetSymbolAddress((void**)&ln,   g_ln);
    cudaGetSymbolAddress((void**)&lnh,  g_lnh);
    cudaGetSymbolAddress((void**)&lnl,  g_lnl);
    cudaGetSymbolAddress((void**)&qf,   g_qf);
    cudaGetSymbolAddress((void**)&kf,   g_kf);
    cudaGetSymbolAddress((void**)&vt,   g_vt);
    cudaGetSymbolAddress((void**)&x1,   g_x1);
    cudaGetSymbolAddress((void**)&acth, g_acth);
    cudaGetSymbolAddress((void**)&actl, g_actl);
    cudaGetSymbolAddress((void**)&w1h,  g_w1h);
    cudaGetSymbolAddress((void**)&w2h,  g_w2h);

    const int ATTN_SMEM = 16384 + 2 * AT_BUF;   // 49152
    cudaFuncSetAttribute((const void*)attn_mma_kernel,
                         cudaFuncAttributeMaxDynamicSharedMemorySize, ATTN_SMEM);
    const int GEMM_SMEM = 2 * GST_B + 256;      // 164096
    cudaFuncSetAttribute(gemm_hmma_kernel<1>,
                         cudaFuncAttributeMaxDynamicSharedMemorySize, GEMM_SMEM);
    cudaFuncSetAttribute(gemm_hmma_kernel<2>,
                         cudaFuncAttributeMaxDynamicSharedMemorySize, GEMM_SMEM);

    convert_w_kernel<<<(DMLP * DMODEL + 255) / 256, 256>>>(W1, w1h, DMLP * DMODEL);
    convert_w_kernel<<<(DMODEL * DMLP + 255) / 256, 256>>>(W2, w2h, DMODEL * DMLP);

    // 1) LN1
    ln_kernel<<<TOKENS, 256>>>(x, ln1g, ln1b, ln);
    // 2) QKV -> q/k f16 + V^T f16
    qkv_kernel<<<dim3(TOKENS / 64, NHEAD), 256>>>(ln, Wq, bq, Wk, bk, Wv, bv, qf, kf, vt);
    // 3) HMMA f16 attention + residual -> x1
    attn_mma_kernel<<<dim3(SEQ / 128, NHEAD, BATCH), 256, ATTN_SMEM>>>(qf, kf, vt, x, x1);
    // 4) LN2 -> f16 hi/lo planes
    ln_split_kernel<<<TOKENS, 256>>>(x1, ln2g, ln2b, lnh, lnl);
    // 5) MLP up + GELU -> act f16 hi/lo planes
    gemm_hmma_kernel<1><<<dim3(DMLP / 128, TOKENS / 256), 256, GEMM_SMEM>>>(
        lnh, lnl, w1h, b1, nullptr, (void*)acth, (void*)actl, DMLP, DMODEL);
    // 6) MLP down + bias + residual -> out
    gemm_hmma_kernel<2><<<dim3(DMODEL / 128, TOKENS / 256), 256, GEMM_SMEM>>>(
        acth, actl, w2h, b2, x1, (void*)out, nullptr, DMODEL, DMLP);
}

// round 10
// speedup vs baseline: 7.2146x; 1.4064x over previous
#include <cuda_runtime.h>
#include <cuda_bf16.h>
#include <cuda_fp16.h>
#include <math.h>
#include <stdint.h>

#define TOKENS 16384
#define DMODEL 768
#define NHEAD  12
#define HDIM   64
#define DMLP   3072
#define SEQ    1024
#define BATCH  16

// ---------------- scratch (device globals; no cudaMalloc allowed) ----------------
__device__ float  g_ln  [TOKENS * DMODEL];   // LN1 out fp32 (for qkv)
__device__ __half g_lnh [TOKENS * DMODEL];   // LN2 out f16
__device__ __half g_qf  [TOKENS * DMODEL];   // q f16, pre-scaled by 0.125 [tok][h*64+d]
__device__ __half g_kf  [TOKENS * DMODEL];   // k f16
__device__ __half g_vt  [TOKENS * DMODEL];   // V^T f16: [(b*12+h)*64+d][1024]
__device__ float  g_x1  [TOKENS * DMODEL];   // x + attn
__device__ __half g_acth[TOKENS * DMLP];     // GELU out f16
__device__ __half g_w1h [DMLP * DMODEL];     // W1 f16
__device__ __half g_w2h [DMODEL * DMLP];     // W2 f16

// ---------------- PTX helpers (portable sm_80-class only) ----------------
__device__ __forceinline__ void cp16(uint32_t s, const void* g) {
    asm volatile("cp.async.cg.shared.global [%0], [%1], 16;" :: "r"(s), "l"(g));
}
__device__ __forceinline__ void cp_commit() { asm volatile("cp.async.commit_group;" ::: "memory"); }
__device__ __forceinline__ void cp_wait1()  { asm volatile("cp.async.wait_group 1;" ::: "memory"); }
__device__ __forceinline__ void cp_wait0()  { asm volatile("cp.async.wait_group 0;" ::: "memory"); }

__device__ __forceinline__ void ldsm4(uint32_t* r, uint32_t addr) {
    asm volatile("ldmatrix.sync.aligned.m8n8.x4.shared.b16 {%0,%1,%2,%3}, [%4];"
                 : "=r"(r[0]), "=r"(r[1]), "=r"(r[2]), "=r"(r[3]) : "r"(addr));
}
__device__ __forceinline__ void mma_f16(float* d, const uint32_t* a, const uint32_t* b) {
    asm("mma.sync.aligned.m16n8k16.row.col.f32.f16.f16.f32 "
        "{%0,%1,%2,%3}, {%4,%5,%6,%7}, {%8,%9}, {%0,%1,%2,%3};"
        : "+f"(d[0]), "+f"(d[1]), "+f"(d[2]), "+f"(d[3])
        : "r"(a[0]), "r"(a[1]), "r"(a[2]), "r"(a[3]), "r"(b[0]), "r"(b[1]));
}
__device__ __forceinline__ uint32_t f16x2(float hi, float lo) {
    uint32_t u;
    asm("cvt.rn.f16x2.f32 %0, %1, %2;" : "=r"(u) : "f"(hi), "f"(lo));
    return u;
}

// ---------------- LayerNorm (fp32 out) ----------------
__global__ void ln_kernel(const float* __restrict__ x, const float* __restrict__ g,
                          const float* __restrict__ b, float* __restrict__ out)
{
    int tok = blockIdx.x;
    int t = threadIdx.x;
    const float* xr = x + (size_t)tok * DMODEL;
    float v0 = xr[t], v1 = xr[t + 256], v2 = xr[t + 512];
    float s = v0 + v1 + v2;
    __shared__ float red[8];
#pragma unroll
    for (int o = 16; o > 0; o >>= 1) s += __shfl_xor_sync(0xffffffffu, s, o);
    if ((t & 31) == 0) red[t >> 5] = s;
    __syncthreads();
    float tot = 0.f;
#pragma unroll
    for (int i = 0; i < 8; i++) tot += red[i];
    float mu = tot * (1.0f / DMODEL);
    float d0 = v0 - mu, d1 = v1 - mu, d2 = v2 - mu;
    float sq = d0 * d0 + d1 * d1 + d2 * d2;
#pragma unroll
    for (int o = 16; o > 0; o >>= 1) sq += __shfl_xor_sync(0xffffffffu, sq, o);
    __syncthreads();
    if ((t & 31) == 0) red[t >> 5] = sq;
    __syncthreads();
    float vs = 0.f;
#pragma unroll
    for (int i = 0; i < 8; i++) vs += red[i];
    float rs = rsqrtf(vs * (1.0f / DMODEL) + 1e-5f);
    float* orow = out + (size_t)tok * DMODEL;
    orow[t]       = d0 * rs * g[t]       + b[t];
    orow[t + 256] = d1 * rs * g[t + 256] + b[t + 256];
    orow[t + 512] = d2 * rs * g[t + 512] + b[t + 512];
}

// ---------------- LayerNorm (f16 out) ----------------
__global__ void ln_f16_kernel(const float* __restrict__ x, const float* __restrict__ g,
                              const float* __restrict__ b, __half* __restrict__ oh)
{
    int tok = blockIdx.x;
    int t = threadIdx.x;
    const float* xr = x + (size_t)tok * DMODEL;
    float v0 = xr[t], v1 = xr[t + 256], v2 = xr[t + 512];
    float s = v0 + v1 + v2;
    __shared__ float red[8];
#pragma unroll
    for (int o = 16; o > 0; o >>= 1) s += __shfl_xor_sync(0xffffffffu, s, o);
    if ((t & 31) == 0) red[t >> 5] = s;
    __syncthreads();
    float tot = 0.f;
#pragma unroll
    for (int i = 0; i < 8; i++) tot += red[i];
    float mu = tot * (1.0f / DMODEL);
    float d0 = v0 - mu, d1 = v1 - mu, d2 = v2 - mu;
    float sq = d0 * d0 + d1 * d1 + d2 * d2;
#pragma unroll
    for (int o = 16; o > 0; o >>= 1) sq += __shfl_xor_sync(0xffffffffu, sq, o);
    __syncthreads();
    if ((t & 31) == 0) red[t >> 5] = sq;
    __syncthreads();
    float vs = 0.f;
#pragma unroll
    for (int i = 0; i < 8; i++) vs += red[i];
    float rs = rsqrtf(vs * (1.0f / DMODEL) + 1e-5f);
    size_t base = (size_t)tok * DMODEL;
    oh[base + t]       = __float2half(d0 * rs * g[t]       + b[t]);
    oh[base + t + 256] = __float2half(d1 * rs * g[t + 256] + b[t + 256]);
    oh[base + t + 512] = __float2half(d2 * rs * g[t + 512] + b[t + 512]);
}

// ---------------- weight conversion: fp32 -> f16 ----------------
__global__ void convert_w_kernel(const float* __restrict__ W, __half* __restrict__ wh, int n)
{
    int i = blockIdx.x * 256 + threadIdx.x;
    if (i < n) wh[i] = __float2half(W[i]);
}

// ---------------- Block-diagonal per-head QKV -> q/k f16 + V^T f16 ----------------
__global__ void __launch_bounds__(256) qkv_kernel(
    const float* __restrict__ ln,
    const float* __restrict__ Wq, const float* __restrict__ bq,
    const float* __restrict__ Wk, const float* __restrict__ bk,
    const float* __restrict__ Wv, const float* __restrict__ bv,
    __half* __restrict__ qf, __half* __restrict__ kf, __half* __restrict__ vt)
{
    __shared__ float Xs[64 * 65];
    __shared__ float Ws[64 * 65];
    int hh = blockIdx.y;
    int t0 = blockIdx.x * 64;
    int t  = threadIdx.x;
    int tx = t & 15, ty = t >> 4;

#pragma unroll
    for (int it = 0; it < 4; it++) {
        int idx = it * 1024 + t * 4;
        int r = idx >> 6, c = idx & 63;
        float4 x4 = *(const float4*)(ln + (size_t)(t0 + r) * DMODEL + hh * HDIM + c);
        Xs[(c + 0) * 65 + r] = x4.x;
        Xs[(c + 1) * 65 + r] = x4.y;
        Xs[(c + 2) * 65 + r] = x4.z;
        Xs[(c + 3) * 65 + r] = x4.w;
    }

    const float* Wm[3] = { Wq + hh * 4096, Wk + hh * 4096, Wv + hh * 4096 };
    const float* bm[3] = { bq + hh * 64,  bk + hh * 64,  bv + hh * 64 };

    for (int m = 0; m < 3; m++) {
        __syncthreads();
#pragma unroll
        for (int it = 0; it < 4; it++) {
            int idx = it * 1024 + t * 4;
            int r = idx >> 6, c = idx & 63;
            float4 w4 = *(const float4*)(Wm[m] + r * 64 + c);
            Ws[(c + 0) * 65 + r] = w4.x;
            Ws[(c + 1) * 65 + r] = w4.y;
            Ws[(c + 2) * 65 + r] = w4.z;
            Ws[(c + 3) * 65 + r] = w4.w;
        }
        __syncthreads();

        float acc[4][4] = {};
#pragma unroll
        for (int d = 0; d < 64; d++) {
            float xa[4], wb[4];
#pragma unroll
            for (int i = 0; i < 4; i++) xa[i] = Xs[d * 65 + ty * 4 + i];
#pragma unroll
            for (int j = 0; j < 4; j++) wb[j] = Ws[d * 65 + tx + 16 * j];
#pragma unroll
            for (int i = 0; i < 4; i++)
#pragma unroll
                for (int j = 0; j < 4; j++) acc[i][j] += xa[i] * wb[j];
        }
#pragma unroll
        for (int i = 0; i < 4; i++) {
            int tok = t0 + ty * 4 + i;
#pragma unroll
            for (int j = 0; j < 4; j++) {
                int o = tx + 16 * j;
                float val = acc[i][j] + bm[m][o];
                size_t off = (size_t)tok * DMODEL + hh * HDIM + o;
                if (m == 0) {
                    qf[off] = __float2half(0.125f * val);
                } else if (m == 1) {
                    kf[off] = __float2half(val);
                } else {
                    int bb = tok >> 10, pos = tok & 1023;
                    vt[((size_t)((bb * 12 + hh) * 64 + o)) * 1024 + pos] = __float2half(val);
                }
            }
        }
    }
}

// ---------------- shared swizzle: 128B rows, 8 x 16B chunks ----------------
__device__ __forceinline__ uint32_t sw(uint32_t b, int row, int ch) {
    return b + (uint32_t)(row * 128) + (uint32_t)((ch ^ (row & 7)) << 4);
}

// ---------------- HMMA flash attention (full f16) + residual ----------------
#define AT_BUF 16384

__global__ void __launch_bounds__(256, 1) attn_mma_kernel(
    const __half* __restrict__ qf, const __half* __restrict__ kf,
    const __half* __restrict__ vt,
    const float* __restrict__ x, float* __restrict__ out)
{
    extern __shared__ char dsm[];
    uint32_t sb = (uint32_t)__cvta_generic_to_shared(dsm);

    const int b = blockIdx.z, hh = blockIdx.y;
    const int q0 = blockIdx.x * 128;
    const int t = threadIdx.x, lane = t & 31, w = t >> 5;
    const int wq = w * 16;
    const int bh = b * 12 + hh;
    const int ho = hh * HDIM;
    const size_t tok0 = (size_t)b * 1024 + q0;

    const uint32_t Qb = sb;
    const uint32_t Bb = sb + 16384;

#pragma unroll
    for (int i = 0; i < 4; i++) {
        int idx = t + 256 * i;
        int r = idx >> 3, c = idx & 7;
        cp16(sw(Qb, r, c), qf + (tok0 + r) * DMODEL + ho + c * 8);
    }
    {
        int kg0 = b * 1024;
#pragma unroll
        for (int i = 0; i < 2; i++) {
            int idx = t + 256 * i;
            int r = idx >> 3, c = idx & 7;
            cp16(sw(Bb, r, c),        kf + (size_t)(kg0 + r) * DMODEL + ho + c * 8);
            cp16(sw(Bb + 8192, r, c), vt + ((size_t)(bh * 64 + r)) * 1024 + c * 8);
        }
    }
    cp_commit();

    float oacc[8][4] = {};
    float rs0 = 0.f, rs1 = 0.f;
    uint32_t af[4][4];

    for (int kt = 0; kt < 16; kt++) {
        if (kt + 1 < 16) {
            uint32_t nb = Bb + (uint32_t)((kt + 1) & 1) * AT_BUF;
            int kg = b * 1024 + (kt + 1) * 64;
#pragma unroll
            for (int i = 0; i < 2; i++) {
                int idx = t + 256 * i;
                int r = idx >> 3, c = idx & 7;
                cp16(sw(nb, r, c),        kf + (size_t)(kg + r) * DMODEL + ho + c * 8);
                cp16(sw(nb + 8192, r, c), vt + ((size_t)(bh * 64 + r)) * 1024 + (kt + 1) * 64 + c * 8);
            }
            cp_commit();
            cp_wait1();
        } else {
            cp_wait0();
        }
        __syncthreads();

        uint32_t cb = Bb + (uint32_t)(kt & 1) * AT_BUF;

        if (kt == 0) {
#pragma unroll
            for (int ks = 0; ks < 4; ks++) {
                int r = wq + (lane & 15);
                int c = ks * 2 + (lane >> 4);
                ldsm4(af[ks], sw(Qb, r, c));
            }
        }

        float sacc[8][4] = {};
#pragma unroll
        for (int kp = 0; kp < 2; kp++) {
            uint32_t bf[8][4];
#pragma unroll
            for (int j = 0; j < 8; j++) {
                int r = j * 8 + (lane & 7);
                int c = kp * 4 + ((lane >> 3) & 3);
                ldsm4(bf[j], sw(cb, r, c));
            }
#pragma unroll
            for (int s = 0; s < 2; s++)
#pragma unroll
                for (int j = 0; j < 8; j++)
                    mma_f16(sacc[j], af[kp * 2 + s], &bf[j][s * 2]);
        }

        uint32_t pa[4][4];
#pragma unroll
        for (int j = 0; j < 8; j++) {
            float e0 = __expf(sacc[j][0]);
            float e1 = __expf(sacc[j][1]);
            float e2 = __expf(sacc[j][2]);
            float e3 = __expf(sacc[j][3]);
            rs0 += e0 + e1;
            rs1 += e2 + e3;
            pa[j >> 1][(j & 1) * 2 + 0] = f16x2(e1, e0);
            pa[j >> 1][(j & 1) * 2 + 1] = f16x2(e3, e2);
        }

        uint32_t vb0 = cb + 8192;
#pragma unroll
        for (int kp = 0; kp < 2; kp++) {
            uint32_t vb[8][4];
#pragma unroll
            for (int j = 0; j < 8; j++) {
                int r = j * 8 + (lane & 7);
                int c = kp * 4 + ((lane >> 3) & 3);
                ldsm4(vb[j], sw(vb0, r, c));
            }
#pragma unroll
            for (int s = 0; s < 2; s++)
#pragma unroll
                for (int j = 0; j < 8; j++)
                    mma_f16(oacc[j], pa[kp * 2 + s], &vb[j][s * 2]);
        }
        __syncthreads();
    }

    rs0 += __shfl_xor_sync(0xffffffffu, rs0, 1);
    rs0 += __shfl_xor_sync(0xffffffffu, rs0, 2);
    rs1 += __shfl_xor_sync(0xffffffffu, rs1, 1);
    rs1 += __shfl_xor_sync(0xffffffffu, rs1, 2);
    float inv0 = 1.0f / rs0, inv1 = 1.0f / rs1;

    size_t row0 = tok0 + wq + (lane >> 2);
    size_t row1 = row0 + 8;
#pragma unroll
    for (int j = 0; j < 8; j++) {
        int col = ho + j * 8 + 2 * (lane & 3);
        size_t o0 = row0 * DMODEL + col;
        size_t o1 = row1 * DMODEL + col;
        float2 x0 = *(const float2*)(x + o0);
        float2 x1v = *(const float2*)(x + o1);
        float2 r0 = { oacc[j][0] * inv0 + x0.x,  oacc[j][1] * inv0 + x0.y };
        float2 r1 = { oacc[j][2] * inv1 + x1v.x, oacc[j][3] * inv1 + x1v.y };
        *(float2*)(out + o0) = r0;
        *(float2*)(out + o1) = r1;
    }
}

// ---------------- HMMA plain-f16 GEMM: 256x128 CTA tile, 64x64 warp tile ----------------
// C = A @ B^T + bias; A,B f16. 8 warps in 4m x 2n grid; K-chunk 64; 2-stage cp.async.
#define GA_B   32768                 // A tile: 256 rows x 128B
#define GB_B   16384                 // B tile: 128 rows x 128B
#define GST_B  (GA_B + GB_B)         // 49152 per stage

__device__ __forceinline__ void load_tile2(uint32_t sb,
    const __half* __restrict__ Ah, const __half* __restrict__ Bh,
    int m0, int n0, int K, int ic, int t)
{
#pragma unroll
    for (int i = 0; i < 8; i++) {          // A: 256 rows x 8 chunks
        int idx = t + 256 * i;
        int row = idx >> 3, ch = idx & 7;
        cp16(sw(sb, row, ch), Ah + (size_t)(m0 + row) * K + ic * 64 + ch * 8);
    }
#pragma unroll
    for (int i = 0; i < 4; i++) {          // B: 128 rows x 8 chunks
        int idx = t + 256 * i;
        int row = idx >> 3, ch = idx & 7;
        cp16(sw(sb + GA_B, row, ch), Bh + (size_t)(n0 + row) * K + ic * 64 + ch * 8);
    }
}

template<int MODE>
__global__ void __launch_bounds__(256, 1)
gemm_hmma_kernel(const __half* __restrict__ Ah, const __half* __restrict__ Bh,
                 const float* __restrict__ bias, const float* __restrict__ resid,
                 void* __restrict__ outp, int N, int K)
{
    extern __shared__ char dsm[];
    uint32_t smem_u32 = (uint32_t)__cvta_generic_to_shared(dsm);
    uint32_t base = (smem_u32 + 127) & ~127u;

    const int t = threadIdx.x;
    const int lane = t & 31, wid = t >> 5;
    const int m0 = blockIdx.y * 256, n0 = blockIdx.x * 128;
    const int warp_m = (wid >> 1) * 64, warp_n = (wid & 1) * 64;

    float acc[4][8][4] = {};
    const int NC = K >> 6;

    load_tile2(base, Ah, Bh, m0, n0, K, 0, t);
    cp_commit();

    for (int ic = 0; ic < NC; ic++) {
        uint32_t cb = base + (uint32_t)(ic & 1) * GST_B;
        if (ic + 1 < NC) {
            load_tile2(base + (uint32_t)((ic + 1) & 1) * GST_B, Ah, Bh, m0, n0, K, ic + 1, t);
            cp_commit();
            cp_wait1();
        } else {
            cp_wait0();
        }
        __syncthreads();

        uint32_t Ahb = cb, Bhb = cb + GA_B;
#pragma unroll
        for (int kp2 = 0; kp2 < 2; kp2++) {
            uint32_t ah[4][2][4];
#pragma unroll
            for (int mt = 0; mt < 4; mt++)
#pragma unroll
                for (int ks = 0; ks < 2; ks++) {
                    int row = warp_m + mt * 16 + (lane & 15);
                    int ch  = kp2 * 4 + ks * 2 + (lane >> 4);
                    ldsm4(ah[mt][ks], sw(Ahb, row, ch));
                }
#pragma unroll
            for (int np = 0; np < 4; np++) {
                uint32_t bh[2][4];
#pragma unroll
                for (int j = 0; j < 2; j++) {
                    int row = warp_n + (np * 2 + j) * 8 + (lane & 7);
                    int ch  = kp2 * 4 + ((lane >> 3) & 3);
                    ldsm4(bh[j], sw(Bhb, row, ch));
                }
#pragma unroll
                for (int ks = 0; ks < 2; ks++)
#pragma unroll
                    for (int mt = 0; mt < 4; mt++)
#pragma unroll
                        for (int j = 0; j < 2; j++)
                            mma_f16(acc[mt][np * 2 + j], ah[mt][ks], &bh[j][ks * 2]);
            }
        }
        __syncthreads();
    }

    int rbase = m0 + warp_m + (lane >> 2);
    int cbase = n0 + warp_n + (lane & 3) * 2;
#pragma unroll
    for (int mt = 0; mt < 4; mt++)
#pragma unroll
        for (int nt = 0; nt < 8; nt++)
#pragma unroll
            for (int hh = 0; hh < 2; hh++) {
                int row = rbase + mt * 16 + hh * 8;
                int col = cbase + nt * 8;
                float v0 = acc[mt][nt][hh * 2 + 0] + bias[col];
                float v1 = acc[mt][nt][hh * 2 + 1] + bias[col + 1];
                size_t off = (size_t)row * N + col;
                if (MODE == 1) {
                    v0 = 0.5f * v0 * (1.0f + erff(v0 * 0.70710678118654752f));
                    v1 = 0.5f * v1 * (1.0f + erff(v1 * 0.70710678118654752f));
                    ((uint32_t*)outp)[off >> 1] = f16x2(v1, v0);
                } else {
                    const float2 rr = *(const float2*)(resid + off);
                    float2 ov = { v0 + rr.x, v1 + rr.y };
                    *(float2*)((float*)outp + off) = ov;
                }
            }
}

// ---------------- launch ----------------
extern "C" void kernel_launch(void* const* d_in, const int* in_sizes, int n_in,
                              void* d_out, int out_size)
{
    const float* x    = (const float*)d_in[0];
    const float* ln1g = (const float*)d_in[1];
    const float* ln1b = (const float*)d_in[2];
    const float* Wq   = (const float*)d_in[3];
    const float* bq   = (const float*)d_in[4];
    const float* Wk   = (const float*)d_in[5];
    const float* bk   = (const float*)d_in[6];
    const float* Wv   = (const float*)d_in[7];
    const float* bv   = (const float*)d_in[8];
    const float* ln2g = (const float*)d_in[9];
    const float* ln2b = (const float*)d_in[10];
    const float* W1   = (const float*)d_in[11];
    const float* b1   = (const float*)d_in[12];
    const float* W2   = (const float*)d_in[13];
    const float* b2   = (const float*)d_in[14];
    float* out = (float*)d_out;

    float *ln, *x1;
    __half *lnh, *qf, *kf, *vt, *acth, *w1h, *w2h;
    cudaGetSymbolAddress((void**)&ln,   g_ln);
    cudaGetSymbolAddress((void**)&lnh,  g_lnh);
    cudaGetSymbolAddress((void**)&qf,   g_qf);
    cudaGetSymbolAddress((void**)&kf,   g_kf);
    cudaGetSymbolAddress((void**)&vt,   g_vt);
    cudaGetSymbolAddress((void**)&x1,   g_x1);
    cudaGetSymbolAddress((void**)&acth, g_acth);
    cudaGetSymbolAddress((void**)&w1h,  g_w1h);
    cudaGetSymbolAddress((void**)&w2h,  g_w2h);

    const int ATTN_SMEM = 16384 + 2 * AT_BUF;   // 49152
    cudaFuncSetAttribute((const void*)attn_mma_kernel,
                         cudaFuncAttributeMaxDynamicSharedMemorySize, ATTN_SMEM);
    const int GEMM_SMEM = 2 * GST_B + 256;      // 98560
    cudaFuncSetAttribute(gemm_hmma_kernel<1>,
                         cudaFuncAttributeMaxDynamicSharedMemorySize, GEMM_SMEM);
    cudaFuncSetAttribute(gemm_hmma_kernel<2>,
                         cudaFuncAttributeMaxDynamicSharedMemorySize, GEMM_SMEM);

    convert_w_kernel<<<(DMLP * DMODEL + 255) / 256, 256>>>(W1, w1h, DMLP * DMODEL);
    convert_w_kernel<<<(DMODEL * DMLP + 255) / 256, 256>>>(W2, w2h, DMODEL * DMLP);

    // 1) LN1
    ln_kernel<<<TOKENS, 256>>>(x, ln1g, ln1b, ln);
    // 2) QKV -> q/k f16 + V^T f16
    qkv_kernel<<<dim3(TOKENS / 64, NHEAD), 256>>>(ln, Wq, bq, Wk, bk, Wv, bv, qf, kf, vt);
    // 3) HMMA f16 attention + residual -> x1
    attn_mma_kernel<<<dim3(SEQ / 128, NHEAD, BATCH), 256, ATTN_SMEM>>>(qf, kf, vt, x, x1);
    // 4) LN2 -> f16
    ln_f16_kernel<<<TOKENS, 256>>>(x1, ln2g, ln2b, lnh);
    // 5) MLP up + GELU -> act f16
    gemm_hmma_kernel<1><<<dim3(DMLP / 128, TOKENS / 256), 256, GEMM_SMEM>>>(
        lnh, w1h, b1, nullptr, (void*)acth, DMLP, DMODEL);
    // 6) MLP down + bias + residual -> out
    gemm_hmma_kernel<2><<<dim3(DMODEL / 128, TOKENS / 256), 256, GEMM_SMEM>>>(
        acth, w2h, b2, x1, (void*)out, DMODEL, DMLP);
}

// round 11
// speedup vs baseline: 8.4350x; 1.1692x over previous
#include <cuda_runtime.h>
#include <cuda_bf16.h>
#include <cuda_fp16.h>
#include <math.h>
#include <stdint.h>

#define TOKENS 16384
#define DMODEL 768
#define NHEAD  12
#define HDIM   64
#define DMLP   3072
#define SEQ    1024
#define BATCH  16

// ---------------- scratch (device globals; no cudaMalloc allowed) ----------------
__device__ __half g_lnx [TOKENS * DMODEL];   // LN1 out f16 (qkv input)
__device__ __half g_lnh [TOKENS * DMODEL];   // LN2 out f16
__device__ __half g_qf  [TOKENS * DMODEL];   // q f16, pre-scaled by 0.125 [tok][h*64+d]
__device__ __half g_kf  [TOKENS * DMODEL];   // k f16
__device__ __half g_vt  [TOKENS * DMODEL];   // V^T f16: [(b*12+h)*64+d][1024]
__device__ float  g_x1  [TOKENS * DMODEL];   // x + attn
__device__ __half g_acth[TOKENS * DMLP];     // GELU out f16
__device__ __half g_w1h [DMLP * DMODEL];     // W1 f16
__device__ __half g_w2h [DMODEL * DMLP];     // W2 f16
__device__ __half g_wqkv[3 * NHEAD * HDIM * HDIM];  // Wq|Wk|Wv f16, [m][h][o][d]

// ---------------- PTX helpers (portable sm_80-class only) ----------------
__device__ __forceinline__ void cp16(uint32_t s, const void* g) {
    asm volatile("cp.async.cg.shared.global [%0], [%1], 16;" :: "r"(s), "l"(g));
}
__device__ __forceinline__ void cp_commit() { asm volatile("cp.async.commit_group;" ::: "memory"); }
__device__ __forceinline__ void cp_wait1()  { asm volatile("cp.async.wait_group 1;" ::: "memory"); }
__device__ __forceinline__ void cp_wait0()  { asm volatile("cp.async.wait_group 0;" ::: "memory"); }

__device__ __forceinline__ void ldsm4(uint32_t* r, uint32_t addr) {
    asm volatile("ldmatrix.sync.aligned.m8n8.x4.shared.b16 {%0,%1,%2,%3}, [%4];"
                 : "=r"(r[0]), "=r"(r[1]), "=r"(r[2]), "=r"(r[3]) : "r"(addr));
}
__device__ __forceinline__ void mma_f16(float* d, const uint32_t* a, const uint32_t* b) {
    asm("mma.sync.aligned.m16n8k16.row.col.f32.f16.f16.f32 "
        "{%0,%1,%2,%3}, {%4,%5,%6,%7}, {%8,%9}, {%0,%1,%2,%3};"
        : "+f"(d[0]), "+f"(d[1]), "+f"(d[2]), "+f"(d[3])
        : "r"(a[0]), "r"(a[1]), "r"(a[2]), "r"(a[3]), "r"(b[0]), "r"(b[1]));
}
__device__ __forceinline__ uint32_t f16x2(float hi, float lo) {
    uint32_t u;
    asm("cvt.rn.f16x2.f32 %0, %1, %2;" : "=r"(u) : "f"(hi), "f"(lo));
    return u;
}

// ---------------- LayerNorm (f16 out) ----------------
__global__ void ln_f16_kernel(const float* __restrict__ x, const float* __restrict__ g,
                              const float* __restrict__ b, __half* __restrict__ oh)
{
    int tok = blockIdx.x;
    int t = threadIdx.x;
    const float* xr = x + (size_t)tok * DMODEL;
    float v0 = xr[t], v1 = xr[t + 256], v2 = xr[t + 512];
    float s = v0 + v1 + v2;
    __shared__ float red[8];
#pragma unroll
    for (int o = 16; o > 0; o >>= 1) s += __shfl_xor_sync(0xffffffffu, s, o);
    if ((t & 31) == 0) red[t >> 5] = s;
    __syncthreads();
    float tot = 0.f;
#pragma unroll
    for (int i = 0; i < 8; i++) tot += red[i];
    float mu = tot * (1.0f / DMODEL);
    float d0 = v0 - mu, d1 = v1 - mu, d2 = v2 - mu;
    float sq = d0 * d0 + d1 * d1 + d2 * d2;
#pragma unroll
    for (int o = 16; o > 0; o >>= 1) sq += __shfl_xor_sync(0xffffffffu, sq, o);
    __syncthreads();
    if ((t & 31) == 0) red[t >> 5] = sq;
    __syncthreads();
    float vs = 0.f;
#pragma unroll
    for (int i = 0; i < 8; i++) vs += red[i];
    float rs = rsqrtf(vs * (1.0f / DMODEL) + 1e-5f);
    size_t base = (size_t)tok * DMODEL;
    oh[base + t]       = __float2half(d0 * rs * g[t]       + b[t]);
    oh[base + t + 256] = __float2half(d1 * rs * g[t + 256] + b[t + 256]);
    oh[base + t + 512] = __float2half(d2 * rs * g[t + 512] + b[t + 512]);
}

// ---------------- weight conversions ----------------
__global__ void convert_w_kernel(const float* __restrict__ W, __half* __restrict__ wh, int n)
{
    int i = blockIdx.x * 256 + threadIdx.x;
    if (i < n) wh[i] = __float2half(W[i]);
}
__global__ void convert_wqkv_kernel(const float* __restrict__ Wq, const float* __restrict__ Wk,
                                    const float* __restrict__ Wv, __half* __restrict__ o)
{
    int i = blockIdx.x * 256 + threadIdx.x;
    const int n = NHEAD * HDIM * HDIM;   // 49152
    if (i < n) {
        o[i]         = __float2half(Wq[i]);
        o[n + i]     = __float2half(Wk[i]);
        o[2 * n + i] = __float2half(Wv[i]);
    }
}

// ---------------- shared swizzle: 128B rows, 8 x 16B chunks ----------------
__device__ __forceinline__ uint32_t sw(uint32_t b, int row, int ch) {
    return b + (uint32_t)(row * 128) + (uint32_t)((ch ^ (row & 7)) << 4);
}

// ---------------- HMMA QKV: per-CTA 128 tokens x one head ----------------
// X[128,64]f16 (A-frags) @ W[m][64,64]f16 (B-frags, K-major) + bias.
// q,k written coalesced f16x2; V staged to smem and written transposed coalesced.
// Dynamic smem: X 16K + 3x W 8K + Vstage 64x272B = 57856 B.
#define QX_OFF  0
#define QW_OFF  16384
#define QV_OFF  (16384 + 3 * 8192)
#define QKV_SMEM (QV_OFF + 64 * 272)

__global__ void __launch_bounds__(256, 1) qkv_mma_kernel(
    const __half* __restrict__ lnx, const __half* __restrict__ wqkv,
    const float* __restrict__ bq, const float* __restrict__ bk, const float* __restrict__ bv,
    __half* __restrict__ qf, __half* __restrict__ kf, __half* __restrict__ vt)
{
    extern __shared__ char dsm[];
    uint32_t sb = (uint32_t)__cvta_generic_to_shared(dsm);
    const int hh = blockIdx.y;
    const int t0 = blockIdx.x * 128;
    const int t = threadIdx.x, lane = t & 31, w = t >> 5;
    const int ho = hh * HDIM;
    const int bh = (t0 >> 10) * 12 + hh;

    // X tile: 128 rows x 64 f16 (128B rows)
#pragma unroll
    for (int i = 0; i < 4; i++) {
        int idx = t + 256 * i;
        int r = idx >> 3, c = idx & 7;
        cp16(sw(sb + QX_OFF, r, c), lnx + (size_t)(t0 + r) * DMODEL + ho + c * 8);
    }
    // W tiles: 3 x 64 rows x 64 f16
#pragma unroll
    for (int m = 0; m < 3; m++)
#pragma unroll
        for (int i = 0; i < 2; i++) {
            int idx = t + 256 * i;
            int r = idx >> 3, c = idx & 7;
            cp16(sw(sb + QW_OFF + m * 8192, r, c),
                 wqkv + (size_t)(m * NHEAD + hh) * 4096 + r * 64 + c * 8);
        }
    cp_commit();
    cp_wait0();
    __syncthreads();

    // A fragments: 16 token rows per warp, 4 k16-steps
    uint32_t af[4][4];
#pragma unroll
    for (int ks = 0; ks < 4; ks++) {
        int r = w * 16 + (lane & 15);
        int c = ks * 2 + (lane >> 4);
        ldsm4(af[ks], sw(sb + QX_OFF, r, c));
    }

    const float* biases[3] = { bq + ho, bk + ho, bv + ho };

#pragma unroll
    for (int m = 0; m < 3; m++) {
        float acc[8][4] = {};
        uint32_t wb0 = sb + QW_OFF + m * 8192;
#pragma unroll
        for (int kp = 0; kp < 2; kp++) {
            uint32_t bf[8][4];
#pragma unroll
            for (int j = 0; j < 8; j++) {
                int r = j * 8 + (lane & 7);
                int c = kp * 4 + ((lane >> 3) & 3);
                ldsm4(bf[j], sw(wb0, r, c));
            }
#pragma unroll
            for (int s = 0; s < 2; s++)
#pragma unroll
                for (int j = 0; j < 8; j++)
                    mma_f16(acc[j], af[kp * 2 + s], &bf[j][s * 2]);
        }
        const float* bias = biases[m];
        int r0 = w * 16 + (lane >> 2);
        int cb = 2 * (lane & 3);
        if (m < 2) {
            __half* dst = (m == 0) ? qf : kf;
            float scale = (m == 0) ? 0.125f : 1.0f;
#pragma unroll
            for (int j = 0; j < 8; j++)
#pragma unroll
                for (int h2 = 0; h2 < 2; h2++) {
                    int col = cb + j * 8;
                    int row = t0 + r0 + h2 * 8;
                    float v0 = (acc[j][h2 * 2 + 0] + bias[col])     * scale;
                    float v1 = (acc[j][h2 * 2 + 1] + bias[col + 1]) * scale;
                    *(uint32_t*)(dst + (size_t)row * DMODEL + ho + col) = f16x2(v1, v0);
                }
        } else {
            // stage V transposed into smem: Vs[o][tok_local], row stride 272B
#pragma unroll
            for (int j = 0; j < 8; j++)
#pragma unroll
                for (int h2 = 0; h2 < 2; h2++) {
                    int col = cb + j * 8;
                    int rl  = r0 + h2 * 8;       // local token 0..127 (within warp's 16)
                    float v0 = acc[j][h2 * 2 + 0] + bias[col];
                    float v1 = acc[j][h2 * 2 + 1] + bias[col + 1];
                    *(__half*)(dsm + QV_OFF + col * 272 + rl * 2)       = __float2half(v0);
                    *(__half*)(dsm + QV_OFF + (col + 1) * 272 + rl * 2) = __float2half(v1);
                }
        }
    }
    __syncthreads();
    // coalesced V^T write: 64 rows x 128 f16 (256B each) -> vt[(bh*64+o)*1024 + pos]
    int pos0 = t0 & 1023;
#pragma unroll
    for (int i = 0; i < 4; i++) {
        int idx = t + 256 * i;
        int o = idx >> 4, q16 = idx & 15;
        uint4 val = *(const uint4*)(dsm + QV_OFF + o * 272 + q16 * 16);
        *(uint4*)(vt + ((size_t)(bh * 64 + o)) * 1024 + pos0 + q16 * 8) = val;
    }
}

// ---------------- HMMA flash attention (full f16) + residual ----------------
#define AT_BUF 16384

__global__ void __launch_bounds__(256, 1) attn_mma_kernel(
    const __half* __restrict__ qf, const __half* __restrict__ kf,
    const __half* __restrict__ vt,
    const float* __restrict__ x, float* __restrict__ out)
{
    extern __shared__ char dsm[];
    uint32_t sb = (uint32_t)__cvta_generic_to_shared(dsm);

    const int b = blockIdx.z, hh = blockIdx.y;
    const int q0 = blockIdx.x * 128;
    const int t = threadIdx.x, lane = t & 31, w = t >> 5;
    const int wq = w * 16;
    const int bh = b * 12 + hh;
    const int ho = hh * HDIM;
    const size_t tok0 = (size_t)b * 1024 + q0;

    const uint32_t Qb = sb;
    const uint32_t Bb = sb + 16384;

#pragma unroll
    for (int i = 0; i < 4; i++) {
        int idx = t + 256 * i;
        int r = idx >> 3, c = idx & 7;
        cp16(sw(Qb, r, c), qf + (tok0 + r) * DMODEL + ho + c * 8);
    }
    {
        int kg0 = b * 1024;
#pragma unroll
        for (int i = 0; i < 2; i++) {
            int idx = t + 256 * i;
            int r = idx >> 3, c = idx & 7;
            cp16(sw(Bb, r, c),        kf + (size_t)(kg0 + r) * DMODEL + ho + c * 8);
            cp16(sw(Bb + 8192, r, c), vt + ((size_t)(bh * 64 + r)) * 1024 + c * 8);
        }
    }
    cp_commit();

    float oacc[8][4] = {};
    float rs0 = 0.f, rs1 = 0.f;
    uint32_t af[4][4];

    for (int kt = 0; kt < 16; kt++) {
        if (kt + 1 < 16) {
            uint32_t nb = Bb + (uint32_t)((kt + 1) & 1) * AT_BUF;
            int kg = b * 1024 + (kt + 1) * 64;
#pragma unroll
            for (int i = 0; i < 2; i++) {
                int idx = t + 256 * i;
                int r = idx >> 3, c = idx & 7;
                cp16(sw(nb, r, c),        kf + (size_t)(kg + r) * DMODEL + ho + c * 8);
                cp16(sw(nb + 8192, r, c), vt + ((size_t)(bh * 64 + r)) * 1024 + (kt + 1) * 64 + c * 8);
            }
            cp_commit();
            cp_wait1();
        } else {
            cp_wait0();
        }
        __syncthreads();

        uint32_t cb = Bb + (uint32_t)(kt & 1) * AT_BUF;

        if (kt == 0) {
#pragma unroll
            for (int ks = 0; ks < 4; ks++) {
                int r = wq + (lane & 15);
                int c = ks * 2 + (lane >> 4);
                ldsm4(af[ks], sw(Qb, r, c));
            }
        }

        float sacc[8][4] = {};
#pragma unroll
        for (int kp = 0; kp < 2; kp++) {
            uint32_t bf[8][4];
#pragma unroll
            for (int j = 0; j < 8; j++) {
                int r = j * 8 + (lane & 7);
                int c = kp * 4 + ((lane >> 3) & 3);
                ldsm4(bf[j], sw(cb, r, c));
            }
#pragma unroll
            for (int s = 0; s < 2; s++)
#pragma unroll
                for (int j = 0; j < 8; j++)
                    mma_f16(sacc[j], af[kp * 2 + s], &bf[j][s * 2]);
        }

        uint32_t pa[4][4];
#pragma unroll
        for (int j = 0; j < 8; j++) {
            float e0 = __expf(sacc[j][0]);
            float e1 = __expf(sacc[j][1]);
            float e2 = __expf(sacc[j][2]);
            float e3 = __expf(sacc[j][3]);
            rs0 += e0 + e1;
            rs1 += e2 + e3;
            pa[j >> 1][(j & 1) * 2 + 0] = f16x2(e1, e0);
            pa[j >> 1][(j & 1) * 2 + 1] = f16x2(e3, e2);
        }

        uint32_t vb0 = cb + 8192;
#pragma unroll
        for (int kp = 0; kp < 2; kp++) {
            uint32_t vb[8][4];
#pragma unroll
            for (int j = 0; j < 8; j++) {
                int r = j * 8 + (lane & 7);
                int c = kp * 4 + ((lane >> 3) & 3);
                ldsm4(vb[j], sw(vb0, r, c));
            }
#pragma unroll
            for (int s = 0; s < 2; s++)
#pragma unroll
                for (int j = 0; j < 8; j++)
                    mma_f16(oacc[j], pa[kp * 2 + s], &vb[j][s * 2]);
        }
        __syncthreads();
    }

    rs0 += __shfl_xor_sync(0xffffffffu, rs0, 1);
    rs0 += __shfl_xor_sync(0xffffffffu, rs0, 2);
    rs1 += __shfl_xor_sync(0xffffffffu, rs1, 1);
    rs1 += __shfl_xor_sync(0xffffffffu, rs1, 2);
    float inv0 = 1.0f / rs0, inv1 = 1.0f / rs1;

    size_t row0 = tok0 + wq + (lane >> 2);
    size_t row1 = row0 + 8;
#pragma unroll
    for (int j = 0; j < 8; j++) {
        int col = ho + j * 8 + 2 * (lane & 3);
        size_t o0 = row0 * DMODEL + col;
        size_t o1 = row1 * DMODEL + col;
        float2 x0 = *(const float2*)(x + o0);
        float2 x1v = *(const float2*)(x + o1);
        float2 r0 = { oacc[j][0] * inv0 + x0.x,  oacc[j][1] * inv0 + x0.y };
        float2 r1 = { oacc[j][2] * inv1 + x1v.x, oacc[j][3] * inv1 + x1v.y };
        *(float2*)(out + o0) = r0;
        *(float2*)(out + o1) = r1;
    }
}

// ---------------- HMMA plain-f16 GEMM: 256x128 CTA tile, 64x64 warp tile ----------------
#define GA_B   32768
#define GB_B   16384
#define GST_B  (GA_B + GB_B)

__device__ __forceinline__ void load_tile2(uint32_t sb,
    const __half* __restrict__ Ah, const __half* __restrict__ Bh,
    int m0, int n0, int K, int ic, int t)
{
#pragma unroll
    for (int i = 0; i < 8; i++) {
        int idx = t + 256 * i;
        int row = idx >> 3, ch = idx & 7;
        cp16(sw(sb, row, ch), Ah + (size_t)(m0 + row) * K + ic * 64 + ch * 8);
    }
#pragma unroll
    for (int i = 0; i < 4; i++) {
        int idx = t + 256 * i;
        int row = idx >> 3, ch = idx & 7;
        cp16(sw(sb + GA_B, row, ch), Bh + (size_t)(n0 + row) * K + ic * 64 + ch * 8);
    }
}

template<int MODE>
__global__ void __launch_bounds__(256, 1)
gemm_hmma_kernel(const __half* __restrict__ Ah, const __half* __restrict__ Bh,
                 const float* __restrict__ bias, const float* __restrict__ resid,
                 void* __restrict__ outp, int N, int K)
{
    extern __shared__ char dsm[];
    uint32_t smem_u32 = (uint32_t)__cvta_generic_to_shared(dsm);
    uint32_t base = (smem_u32 + 127) & ~127u;

    const int t = threadIdx.x;
    const int lane = t & 31, wid = t >> 5;
    const int m0 = blockIdx.y * 256, n0 = blockIdx.x * 128;
    const int warp_m = (wid >> 1) * 64, warp_n = (wid & 1) * 64;

    float acc[4][8][4] = {};
    const int NC = K >> 6;

    load_tile2(base, Ah, Bh, m0, n0, K, 0, t);
    cp_commit();

    for (int ic = 0; ic < NC; ic++) {
        uint32_t cb = base + (uint32_t)(ic & 1) * GST_B;
        if (ic + 1 < NC) {
            load_tile2(base + (uint32_t)((ic + 1) & 1) * GST_B, Ah, Bh, m0, n0, K, ic + 1, t);
            cp_commit();
            cp_wait1();
        } else {
            cp_wait0();
        }
        __syncthreads();

        uint32_t Ahb = cb, Bhb = cb + GA_B;
#pragma unroll
        for (int kp2 = 0; kp2 < 2; kp2++) {
            uint32_t ah[4][2][4];
#pragma unroll
            for (int mt = 0; mt < 4; mt++)
#pragma unroll
                for (int ks = 0; ks < 2; ks++) {
                    int row = warp_m + mt * 16 + (lane & 15);
                    int ch  = kp2 * 4 + ks * 2 + (lane >> 4);
                    ldsm4(ah[mt][ks], sw(Ahb, row, ch));
                }
#pragma unroll
            for (int np = 0; np < 4; np++) {
                uint32_t bh[2][4];
#pragma unroll
                for (int j = 0; j < 2; j++) {
                    int row = warp_n + (np * 2 + j) * 8 + (lane & 7);
                    int ch  = kp2 * 4 + ((lane >> 3) & 3);
                    ldsm4(bh[j], sw(Bhb, row, ch));
                }
#pragma unroll
                for (int ks = 0; ks < 2; ks++)
#pragma unroll
                    for (int mt = 0; mt < 4; mt++)
#pragma unroll
                        for (int j = 0; j < 2; j++)
                            mma_f16(acc[mt][np * 2 + j], ah[mt][ks], &bh[j][ks * 2]);
            }
        }
        __syncthreads();
    }

    int rbase = m0 + warp_m + (lane >> 2);
    int cbase = n0 + warp_n + (lane & 3) * 2;
#pragma unroll
    for (int mt = 0; mt < 4; mt++)
#pragma unroll
        for (int nt = 0; nt < 8; nt++)
#pragma unroll
            for (int hh = 0; hh < 2; hh++) {
                int row = rbase + mt * 16 + hh * 8;
                int col = cbase + nt * 8;
                float v0 = acc[mt][nt][hh * 2 + 0] + bias[col];
                float v1 = acc[mt][nt][hh * 2 + 1] + bias[col + 1];
                size_t off = (size_t)row * N + col;
                if (MODE == 1) {
                    v0 = 0.5f * v0 * (1.0f + erff(v0 * 0.70710678118654752f));
                    v1 = 0.5f * v1 * (1.0f + erff(v1 * 0.70710678118654752f));
                    ((uint32_t*)outp)[off >> 1] = f16x2(v1, v0);
                } else {
                    const float2 rr = *(const float2*)(resid + off);
                    float2 ov = { v0 + rr.x, v1 + rr.y };
                    *(float2*)((float*)outp + off) = ov;
                }
            }
}

// ---------------- launch ----------------
extern "C" void kernel_launch(void* const* d_in, const int* in_sizes, int n_in,
                              void* d_out, int out_size)
{
    const float* x    = (const float*)d_in[0];
    const float* ln1g = (const float*)d_in[1];
    const float* ln1b = (const float*)d_in[2];
    const float* Wq   = (const float*)d_in[3];
    const float* bq   = (const float*)d_in[4];
    const float* Wk   = (const float*)d_in[5];
    const float* bk   = (const float*)d_in[6];
    const float* Wv   = (const float*)d_in[7];
    const float* bv   = (const float*)d_in[8];
    const float* ln2g = (const float*)d_in[9];
    const float* ln2b = (const float*)d_in[10];
    const float* W1   = (const float*)d_in[11];
    const float* b1   = (const float*)d_in[12];
    const float* W2   = (const float*)d_in[13];
    const float* b2   = (const float*)d_in[14];
    float* out = (float*)d_out;

    float* x1;
    __half *lnx, *lnh, *qf, *kf, *vt, *acth, *w1h, *w2h, *wqkv;
    cudaGetSymbolAddress((void**)&lnx,  g_lnx);
    cudaGetSymbolAddress((void**)&lnh,  g_lnh);
    cudaGetSymbolAddress((void**)&qf,   g_qf);
    cudaGetSymbolAddress((void**)&kf,   g_kf);
    cudaGetSymbolAddress((void**)&vt,   g_vt);
    cudaGetSymbolAddress((void**)&x1,   g_x1);
    cudaGetSymbolAddress((void**)&acth, g_acth);
    cudaGetSymbolAddress((void**)&w1h,  g_w1h);
    cudaGetSymbolAddress((void**)&w2h,  g_w2h);
    cudaGetSymbolAddress((void**)&wqkv, g_wqkv);

    const int ATTN_SMEM = 16384 + 2 * AT_BUF;   // 49152
    cudaFuncSetAttribute((const void*)attn_mma_kernel,
                         cudaFuncAttributeMaxDynamicSharedMemorySize, ATTN_SMEM);
    const int GEMM_SMEM = 2 * GST_B + 256;      // 98560
    cudaFuncSetAttribute(gemm_hmma_kernel<1>,
                         cudaFuncAttributeMaxDynamicSharedMemorySize, GEMM_SMEM);
    cudaFuncSetAttribute(gemm_hmma_kernel<2>,
                         cudaFuncAttributeMaxDynamicSharedMemorySize, GEMM_SMEM);
    cudaFuncSetAttribute((const void*)qkv_mma_kernel,
                         cudaFuncAttributeMaxDynamicSharedMemorySize, QKV_SMEM);

    convert_w_kernel<<<(DMLP * DMODEL + 255) / 256, 256>>>(W1, w1h, DMLP * DMODEL);
    convert_w_kernel<<<(DMODEL * DMLP + 255) / 256, 256>>>(W2, w2h, DMODEL * DMLP);
    convert_wqkv_kernel<<<(NHEAD * HDIM * HDIM + 255) / 256, 256>>>(Wq, Wk, Wv, wqkv);

    // 1) LN1 -> f16
    ln_f16_kernel<<<TOKENS, 256>>>(x, ln1g, ln1b, lnx);
    // 2) HMMA QKV -> q/k f16 + V^T f16
    qkv_mma_kernel<<<dim3(TOKENS / 128, NHEAD), 256, QKV_SMEM>>>(
        lnx, wqkv, bq, bk, bv, qf, kf, vt);
    // 3) HMMA f16 attention + residual -> x1
    attn_mma_kernel<<<dim3(SEQ / 128, NHEAD, BATCH), 256, ATTN_SMEM>>>(qf, kf, vt, x, x1);
    // 4) LN2 -> f16
    ln_f16_kernel<<<TOKENS, 256>>>(x1, ln2g, ln2b, lnh);
    // 5) MLP up + GELU -> act f16
    gemm_hmma_kernel<1><<<dim3(DMLP / 128, TOKENS / 256), 256, GEMM_SMEM>>>(
        lnh, w1h, b1, nullptr, (void*)acth, DMLP, DMODEL);
    // 6) MLP down + bias + residual -> out
    gemm_hmma_kernel<2><<<dim3(DMODEL / 128, TOKENS / 256), 256, GEMM_SMEM>>>(
        acth, w2h, b2, x1, (void*)out, DMODEL, DMLP);
}